// round 2
// baseline (speedup 1.0000x reference)
#include <cuda_runtime.h>
#include <math.h>

#define NB 4
#define NS 2048
#define NE 256
#define NH 4
#define ND 64

// Scratch (allocation-free): Q,K,V,attn_out in [B,H,S,D] layout. 8MB each.
__device__ float g_Q[NB*NH*NS*ND];
__device__ float g_K[NB*NH*NS*ND];
__device__ float g_V[NB*NH*NS*ND];
__device__ float g_AO[NB*NH*NS*ND];

// ---------------------------------------------------------------------------
// Kernel 1: fused QKV projection.  C = X(8192x256) @ W(256x256) + b, scattered
// to [B,H,S,D]. grid = (M/64, N/64, 3), 256 threads, 4x4 micro-tile.
// ---------------------------------------------------------------------------
__global__ __launch_bounds__(256) void qkv_proj(
    const float* __restrict__ X,
    const float* __restrict__ Wq, const float* __restrict__ bq,
    const float* __restrict__ Wk, const float* __restrict__ bk,
    const float* __restrict__ Wv, const float* __restrict__ bv)
{
    __shared__ float As[32][65];   // [k][m]
    __shared__ float Bs[32][65];   // [k][n]

    const float* W; const float* bias; float* out;
    if (blockIdx.z == 0)      { W = Wq; bias = bq; out = g_Q; }
    else if (blockIdx.z == 1) { W = Wk; bias = bk; out = g_K; }
    else                      { W = Wv; bias = bv; out = g_V; }

    const int tid = threadIdx.x;
    const int ty = tid >> 4, tx = tid & 15;
    const int m0 = blockIdx.x * 64;
    const int n0 = blockIdx.y * 64;

    float acc[4][4];
    #pragma unroll
    for (int i = 0; i < 4; i++)
        #pragma unroll
        for (int j = 0; j < 4; j++) acc[i][j] = 0.f;

    for (int k0 = 0; k0 < NE; k0 += 32) {
        #pragma unroll
        for (int i = 0; i < 8; i++) {          // A tile 64x32
            int idx = tid + i * 256;
            int m = idx >> 5, kk = idx & 31;
            As[kk][m] = X[(m0 + m) * NE + k0 + kk];
        }
        #pragma unroll
        for (int i = 0; i < 8; i++) {          // B tile 32x64
            int idx = tid + i * 256;
            int kk = idx >> 6, n = idx & 63;
            Bs[kk][n] = W[(k0 + kk) * NE + n0 + n];
        }
        __syncthreads();
        #pragma unroll 8
        for (int kk = 0; kk < 32; kk++) {
            float a[4], bb[4];
            #pragma unroll
            for (int i = 0; i < 4; i++) a[i] = As[kk][ty + 16 * i];
            #pragma unroll
            for (int j = 0; j < 4; j++) bb[j] = Bs[kk][tx + 16 * j];
            #pragma unroll
            for (int i = 0; i < 4; i++)
                #pragma unroll
                for (int j = 0; j < 4; j++)
                    acc[i][j] += a[i] * bb[j];
        }
        __syncthreads();
    }

    const int h = n0 >> 6;                     // BN=64 aligned to head size
    #pragma unroll
    for (int i = 0; i < 4; i++) {
        int m = m0 + ty + 16 * i;
        int b = m >> 11, s = m & (NS - 1);
        float* orow = out + (((size_t)b * NH + h) * NS + s) * ND;
        #pragma unroll
        for (int j = 0; j < 4; j++) {
            int n = n0 + tx + 16 * j;
            orow[n & 63] = acc[i][j] + bias[n];
        }
    }
}

// ---------------------------------------------------------------------------
// Kernel 2: flash attention with per-query temperature.
// grid = (S/64, H, B), 256 threads. Thread owns rows q=ty+16i, cols tx+16j.
// All smem reads are broadcast or 16-consecutive-bank -> conflict free.
// ---------------------------------------------------------------------------
__global__ __launch_bounds__(256) void attn_kernel(
    const int* __restrict__ mask,
    const float* __restrict__ explore,
    const float* __restrict__ exploit)
{
    extern __shared__ float sm[];
    float (*Qs)[65] = (float(*)[65])(sm);
    float (*Ks)[65] = (float(*)[65])(sm + 64 * 65);
    float (*Vs)[65] = (float(*)[65])(sm + 2 * 64 * 65);
    float (*Ss)[65] = (float(*)[65])(sm + 3 * 64 * 65);
    __shared__ float rowscale[64];
    __shared__ float kpen[64];

    const int tid = threadIdx.x;
    const int ty = tid >> 4, tx = tid & 15;
    const int q0 = blockIdx.x * 64;
    const int h = blockIdx.y, b = blockIdx.z;

    const size_t base = ((size_t)b * NH + h) * NS * ND;
    const float* Qp = g_Q + base;
    const float* Kp = g_K + base;
    const float* Vp = g_V + base;
    float*       Op = g_AO + base;

    if (tid < 64) {
        int s = q0 + tid;
        float t = 1.0f + 0.5f * explore[b * NS + s] - 0.5f * exploit[b * NS + s];
        t = fminf(fmaxf(t, 0.5f), 2.0f);
        if (mask[b * NS + s] != 0) t = 1.0f;
        rowscale[tid] = 0.125f / t;     // 1/(sqrt(64)*temp)
    }
    __syncthreads();

    #pragma unroll
    for (int i = 0; i < 16; i++) {      // Q tile, pre-scaled per row
        int idx = tid + i * 256;
        int r = idx >> 6, d = idx & 63;
        Qs[r][d] = Qp[(q0 + r) * ND + d] * rowscale[r];
    }

    float m_run[4], l_run[4], o[4][4];
    #pragma unroll
    for (int i = 0; i < 4; i++) {
        m_run[i] = -1e30f; l_run[i] = 0.f;
        #pragma unroll
        for (int j = 0; j < 4; j++) o[i][j] = 0.f;
    }

    for (int kt = 0; kt < NS / 64; kt++) {
        const int kk0 = kt * 64;
        #pragma unroll
        for (int i = 0; i < 16; i++) {
            int idx = tid + i * 256;
            int r = idx >> 6, d = idx & 63;
            Ks[r][d] = Kp[(kk0 + r) * ND + d];
            Vs[r][d] = Vp[(kk0 + r) * ND + d];
        }
        if (tid < 64) kpen[tid] = (mask[b * NS + kk0 + tid] != 0) ? -1e30f : 0.f;
        __syncthreads();

        // --- scores: S = Qs * Ks^T (Q already scaled) ---
        float sc[4][4];
        #pragma unroll
        for (int i = 0; i < 4; i++)
            #pragma unroll
            for (int j = 0; j < 4; j++) sc[i][j] = 0.f;

        #pragma unroll 8
        for (int d = 0; d < 64; d++) {
            float a[4], bb[4];
            #pragma unroll
            for (int i = 0; i < 4; i++) a[i] = Qs[ty + 16 * i][d];
            #pragma unroll
            for (int j = 0; j < 4; j++) bb[j] = Ks[tx + 16 * j][d];
            #pragma unroll
            for (int i = 0; i < 4; i++)
                #pragma unroll
                for (int j = 0; j < 4; j++)
                    sc[i][j] += a[i] * bb[j];
        }
        #pragma unroll
        for (int j = 0; j < 4; j++) {
            float pen = kpen[tx + 16 * j];
            #pragma unroll
            for (int i = 0; i < 4; i++) sc[i][j] += pen;
        }

        // --- online softmax per row (4 rows/thread, reduce over 16 tx lanes) ---
        #pragma unroll
        for (int i = 0; i < 4; i++) {
            float rm = fmaxf(fmaxf(sc[i][0], sc[i][1]), fmaxf(sc[i][2], sc[i][3]));
            rm = fmaxf(rm, __shfl_xor_sync(0xffffffffu, rm, 1));
            rm = fmaxf(rm, __shfl_xor_sync(0xffffffffu, rm, 2));
            rm = fmaxf(rm, __shfl_xor_sync(0xffffffffu, rm, 4));
            rm = fmaxf(rm, __shfl_xor_sync(0xffffffffu, rm, 8));
            float mn = fmaxf(m_run[i], rm);
            float c = __expf(m_run[i] - mn);
            float rs = 0.f;
            #pragma unroll
            for (int j = 0; j < 4; j++) {
                sc[i][j] = __expf(sc[i][j] - mn);
                rs += sc[i][j];
            }
            rs += __shfl_xor_sync(0xffffffffu, rs, 1);
            rs += __shfl_xor_sync(0xffffffffu, rs, 2);
            rs += __shfl_xor_sync(0xffffffffu, rs, 4);
            rs += __shfl_xor_sync(0xffffffffu, rs, 8);
            l_run[i] = l_run[i] * c + rs;
            m_run[i] = mn;
            #pragma unroll
            for (int j = 0; j < 4; j++) o[i][j] *= c;
            #pragma unroll
            for (int j = 0; j < 4; j++) Ss[ty + 16 * i][tx + 16 * j] = sc[i][j];
        }
        __syncthreads();

        // --- PV accumulate: o += P * V ---
        #pragma unroll 8
        for (int k = 0; k < 64; k++) {
            float pv[4], vv[4];
            #pragma unroll
            for (int i = 0; i < 4; i++) pv[i] = Ss[ty + 16 * i][k];
            #pragma unroll
            for (int j = 0; j < 4; j++) vv[j] = Vs[k][tx + 16 * j];
            #pragma unroll
            for (int i = 0; i < 4; i++)
                #pragma unroll
                for (int j = 0; j < 4; j++)
                    o[i][j] += pv[i] * vv[j];
        }
        __syncthreads();
    }

    #pragma unroll
    for (int i = 0; i < 4; i++) {
        float inv = (l_run[i] > 0.f) ? 1.f / l_run[i] : 0.f;
        #pragma unroll
        for (int j = 0; j < 4; j++)
            Op[(q0 + ty + 16 * i) * ND + tx + 16 * j] = o[i][j] * inv;
    }
}

// ---------------------------------------------------------------------------
// Kernel 3: output projection + query-mask zeroing.
// out[b,s,:] = mask[b,s] ? 0 : attn[b,s,:] @ Wo + bo
// ---------------------------------------------------------------------------
__global__ __launch_bounds__(256) void out_proj(
    const float* __restrict__ Wo, const float* __restrict__ bo,
    const int* __restrict__ mask,
    float* __restrict__ out)
{
    __shared__ float As[32][65];
    __shared__ float Bs[32][65];

    const int tid = threadIdx.x;
    const int ty = tid >> 4, tx = tid & 15;
    const int m0 = blockIdx.x * 64;
    const int n0 = blockIdx.y * 64;

    float acc[4][4];
    #pragma unroll
    for (int i = 0; i < 4; i++)
        #pragma unroll
        for (int j = 0; j < 4; j++) acc[i][j] = 0.f;

    for (int k0 = 0; k0 < NE; k0 += 32) {
        const int hh = k0 >> 6;     // head for this 32-chunk (BK=32 within head)
        #pragma unroll
        for (int i = 0; i < 8; i++) {
            int idx = tid + i * 256;
            int m = idx >> 5, kk = idx & 31;
            int mm = m0 + m;
            int bb_ = mm >> 11, s = mm & (NS - 1);
            As[kk][m] = g_AO[(((size_t)bb_ * NH + hh) * NS + s) * ND + ((k0 + kk) & 63)];
        }
        #pragma unroll
        for (int i = 0; i < 8; i++) {
            int idx = tid + i * 256;
            int kk = idx >> 6, n = idx & 63;
            Bs[kk][n] = Wo[(k0 + kk) * NE + n0 + n];
        }
        __syncthreads();
        #pragma unroll 8
        for (int kk = 0; kk < 32; kk++) {
            float a[4], bb[4];
            #pragma unroll
            for (int i = 0; i < 4; i++) a[i] = As[kk][ty + 16 * i];
            #pragma unroll
            for (int j = 0; j < 4; j++) bb[j] = Bs[kk][tx + 16 * j];
            #pragma unroll
            for (int i = 0; i < 4; i++)
                #pragma unroll
                for (int j = 0; j < 4; j++)
                    acc[i][j] += a[i] * bb[j];
        }
        __syncthreads();
    }

    #pragma unroll
    for (int i = 0; i < 4; i++) {
        int m = m0 + ty + 16 * i;
        int b = m >> 11, s = m & (NS - 1);
        bool mq = mask[b * NS + s] != 0;
        #pragma unroll
        for (int j = 0; j < 4; j++) {
            int n = n0 + tx + 16 * j;
            out[(size_t)m * NE + n] = mq ? 0.f : (acc[i][j] + bo[n]);
        }
    }
}

// ---------------------------------------------------------------------------
extern "C" void kernel_launch(void* const* d_in, const int* in_sizes, int n_in,
                              void* d_out, int out_size)
{
    const float* his     = (const float*)d_in[0];
    const int*   mask    = (const int*)d_in[1];
    const float* explore = (const float*)d_in[2];
    const float* exploit = (const float*)d_in[3];
    const float* Wq = (const float*)d_in[4];
    const float* bq = (const float*)d_in[5];
    const float* Wk = (const float*)d_in[6];
    const float* bk = (const float*)d_in[7];
    const float* Wv = (const float*)d_in[8];
    const float* bv = (const float*)d_in[9];
    const float* Wo = (const float*)d_in[10];
    const float* bo = (const float*)d_in[11];
    float* out = (float*)d_out;

    const int attn_smem = 4 * 64 * 65 * (int)sizeof(float);   // 66560 B
    cudaFuncSetAttribute(attn_kernel,
                         cudaFuncAttributeMaxDynamicSharedMemorySize, attn_smem);

    qkv_proj<<<dim3(128, 4, 3), 256>>>(his, Wq, bq, Wk, bk, Wv, bv);
    attn_kernel<<<dim3(NS / 64, NH, NB), 256, attn_smem>>>(mask, explore, exploit);
    out_proj<<<dim3(128, 4), 256>>>(Wo, bo, mask, out);
}

// round 4
// speedup vs baseline: 2.4268x; 2.4268x over previous
#include <cuda_runtime.h>
#include <cuda_bf16.h>
#include <cstdint>
#include <math.h>

#define NB 4
#define NS 2048
#define NE 256
#define NH 4
#define ND 64

// Scratch (allocation-free). g_V is stored TRANSPOSED: [b,h,d,s].
__device__ float g_Q[NB*NH*NS*ND];
__device__ float g_K[NB*NH*NS*ND];
__device__ float g_V[NB*NH*NS*ND];
__device__ float g_AO[NB*NH*NS*ND];

__device__ __forceinline__ uint32_t pack_bf16x2(float a, float b) {
    __nv_bfloat162 t = __floats2bfloat162_rn(a, b);   // a -> low half
    return *(uint32_t*)&t;
}
__device__ __forceinline__ void split_hi_lo(float x, float& hi, float& lo) {
    __nv_bfloat16 h = __float2bfloat16_rn(x);
    hi = __bfloat162float(h);
    lo = x - hi;
}

// mma.sync m16n8k16 row.col f32.bf16.bf16.f32  (sm_80+ PTX, no arch suffix)
__device__ __forceinline__ void mma16816(float c[4], const uint32_t a[4],
                                         uint32_t b0, uint32_t b1) {
    asm volatile(
        "mma.sync.aligned.m16n8k16.row.col.f32.bf16.bf16.f32 "
        "{%0,%1,%2,%3}, {%4,%5,%6,%7}, {%8,%9}, {%0,%1,%2,%3};"
        : "+f"(c[0]), "+f"(c[1]), "+f"(c[2]), "+f"(c[3])
        : "r"(a[0]), "r"(a[1]), "r"(a[2]), "r"(a[3]), "r"(b0), "r"(b1));
}

// ---------------------------------------------------------------------------
// Kernel 1: fused QKV projection (fp32 SIMT). V written transposed [b,h,d,s].
// ---------------------------------------------------------------------------
__global__ __launch_bounds__(256) void qkv_proj(
    const float* __restrict__ X,
    const float* __restrict__ Wq, const float* __restrict__ bq,
    const float* __restrict__ Wk, const float* __restrict__ bk,
    const float* __restrict__ Wv, const float* __restrict__ bv)
{
    __shared__ float As[32][65];
    __shared__ float Bs[32][65];

    const float* W; const float* bias; float* out;
    bool transposeV = false;
    if (blockIdx.z == 0)      { W = Wq; bias = bq; out = g_Q; }
    else if (blockIdx.z == 1) { W = Wk; bias = bk; out = g_K; }
    else                      { W = Wv; bias = bv; out = g_V; transposeV = true; }

    const int tid = threadIdx.x;
    const int ty = tid >> 4, tx = tid & 15;
    const int m0 = blockIdx.x * 64;
    const int n0 = blockIdx.y * 64;

    float acc[4][4];
    #pragma unroll
    for (int i = 0; i < 4; i++)
        #pragma unroll
        for (int j = 0; j < 4; j++) acc[i][j] = 0.f;

    for (int k0 = 0; k0 < NE; k0 += 32) {
        #pragma unroll
        for (int i = 0; i < 8; i++) {
            int idx = tid + i * 256;
            int m = idx >> 5, kk = idx & 31;
            As[kk][m] = X[(m0 + m) * NE + k0 + kk];
        }
        #pragma unroll
        for (int i = 0; i < 8; i++) {
            int idx = tid + i * 256;
            int kk = idx >> 6, n = idx & 63;
            Bs[kk][n] = W[(k0 + kk) * NE + n0 + n];
        }
        __syncthreads();
        #pragma unroll 8
        for (int kk = 0; kk < 32; kk++) {
            float a[4], bb[4];
            #pragma unroll
            for (int i = 0; i < 4; i++) a[i] = As[kk][ty + 16 * i];
            #pragma unroll
            for (int j = 0; j < 4; j++) bb[j] = Bs[kk][tx + 16 * j];
            #pragma unroll
            for (int i = 0; i < 4; i++)
                #pragma unroll
                for (int j = 0; j < 4; j++)
                    acc[i][j] += a[i] * bb[j];
        }
        __syncthreads();
    }

    const int h = n0 >> 6;
    #pragma unroll
    for (int i = 0; i < 4; i++) {
        int m = m0 + ty + 16 * i;
        int b = m >> 11, s = m & (NS - 1);
        size_t hb = ((size_t)b * NH + h);
        #pragma unroll
        for (int j = 0; j < 4; j++) {
            int n = n0 + tx + 16 * j;
            int d = n & 63;
            float val = acc[i][j] + bias[n];
            if (transposeV) out[(hb * ND + d) * NS + s] = val;
            else            out[(hb * NS + s) * ND + d] = val;
        }
    }
}

// ---------------------------------------------------------------------------
// Kernel 2: flash attention via mma.sync bf16 split (3-term).
// CTA = 128 queries (8 warps x 16 rows), K-tile = 64 keys.
// Fixed-shift softmax: no running max, O accumulates in mma C frags.
// ---------------------------------------------------------------------------
#define KPAD 72   // row stride (elements) for smem tiles; 36 words -> conflict-free

__device__ __forceinline__ void store_split4(__nv_bfloat16* bh, __nv_bfloat16* bl,
                                             int off, float4 v) {
    float h0,l0,h1,l1,h2,l2,h3,l3;
    split_hi_lo(v.x,h0,l0); split_hi_lo(v.y,h1,l1);
    split_hi_lo(v.z,h2,l2); split_hi_lo(v.w,h3,l3);
    *(uint32_t*)(bh + off)     = pack_bf16x2(h0, h1);
    *(uint32_t*)(bh + off + 2) = pack_bf16x2(h2, h3);
    *(uint32_t*)(bl + off)     = pack_bf16x2(l0, l1);
    *(uint32_t*)(bl + off + 2) = pack_bf16x2(l2, l3);
}

__global__ __launch_bounds__(256, 2) void attn_mma(
    const int* __restrict__ mask,
    const float* __restrict__ explore,
    const float* __restrict__ exploit)
{
    __shared__ __nv_bfloat16 Khs[64*KPAD], Kls[64*KPAD];
    __shared__ __nv_bfloat16 Vhs[64*KPAD], Vls[64*KPAD];
    __shared__ float pens[64];

    const int tid  = threadIdx.x;
    const int w    = tid >> 5;
    const int lane = tid & 31;
    const int g    = lane >> 2;       // 0..7
    const int l4   = lane & 3;        // 0..3
    const int q0   = blockIdx.x * 128;
    const int h    = blockIdx.y, b = blockIdx.z;

    const size_t base = ((size_t)b * NH + h) * NS * ND;
    const float* Qp  = g_Q + base;
    const float* Kp  = g_K + base;
    const float* Vtp = g_V + base;    // [d][s]
    float*       Op  = g_AO + base;

    // ---- per-row scale 0.125/temp, Q fragments (hi/lo bf16) in registers ----
    const int row0 = w * 16 + g;          // within CTA tile
    const int row1 = row0 + 8;
    float rs0, rs1;
    {
        int s0 = q0 + row0, s1 = q0 + row1;
        float t0 = 1.0f + 0.5f * explore[b * NS + s0] - 0.5f * exploit[b * NS + s0];
        t0 = fminf(fmaxf(t0, 0.5f), 2.0f);
        if (mask[b * NS + s0] != 0) t0 = 1.0f;
        rs0 = 0.125f / t0;
        float t1 = 1.0f + 0.5f * explore[b * NS + s1] - 0.5f * exploit[b * NS + s1];
        t1 = fminf(fmaxf(t1, 0.5f), 2.0f);
        if (mask[b * NS + s1] != 0) t1 = 1.0f;
        rs1 = 0.125f / t1;
    }

    uint32_t qh[4][4], ql[4][4];
    #pragma unroll
    for (int kc = 0; kc < 4; kc++) {
        int d0 = kc * 16 + l4 * 2;
        const float2 a00 = *(const float2*)(Qp + (size_t)(q0 + row0) * ND + d0);
        const float2 a10 = *(const float2*)(Qp + (size_t)(q0 + row1) * ND + d0);
        const float2 a01 = *(const float2*)(Qp + (size_t)(q0 + row0) * ND + d0 + 8);
        const float2 a11 = *(const float2*)(Qp + (size_t)(q0 + row1) * ND + d0 + 8);
        float hx, lx, hy, ly;
        split_hi_lo(a00.x * rs0, hx, lx); split_hi_lo(a00.y * rs0, hy, ly);
        qh[kc][0] = pack_bf16x2(hx, hy);  ql[kc][0] = pack_bf16x2(lx, ly);
        split_hi_lo(a10.x * rs1, hx, lx); split_hi_lo(a10.y * rs1, hy, ly);
        qh[kc][1] = pack_bf16x2(hx, hy);  ql[kc][1] = pack_bf16x2(lx, ly);
        split_hi_lo(a01.x * rs0, hx, lx); split_hi_lo(a01.y * rs0, hy, ly);
        qh[kc][2] = pack_bf16x2(hx, hy);  ql[kc][2] = pack_bf16x2(lx, ly);
        split_hi_lo(a11.x * rs1, hx, lx); split_hi_lo(a11.y * rs1, hy, ly);
        qh[kc][3] = pack_bf16x2(hx, hy);  ql[kc][3] = pack_bf16x2(lx, ly);
    }

    float oacc[8][4];
    #pragma unroll
    for (int j = 0; j < 8; j++)
        #pragma unroll
        for (int c = 0; c < 4; c++) oacc[j][c] = 0.f;
    float lsum0 = 0.f, lsum1 = 0.f;

    for (int kt = 0; kt < NS / 64; kt++) {
        const int kk0 = kt * 64;

        // ---- load K[key][d] and Vt[d][key] tiles, split to hi/lo bf16 ----
        #pragma unroll
        for (int it = 0; it < 4; it++) {
            int idx = tid + it * 256;
            int r = idx >> 4, c = (idx & 15) * 4;
            float4 kv = *(const float4*)(Kp + (size_t)(kk0 + r) * ND + c);
            store_split4(Khs, Kls, r * KPAD + c, kv);
            float4 vv = *(const float4*)(Vtp + (size_t)r * NS + kk0 + c);
            store_split4(Vhs, Vls, r * KPAD + c, vv);
        }
        if (tid < 64) pens[tid] = (mask[b * NS + kk0 + tid] != 0) ? -1e30f : 0.f;
        __syncthreads();

        // ---- S = Q K^T (3-term split) ----
        float sacc[8][4];
        #pragma unroll
        for (int j = 0; j < 8; j++)
            #pragma unroll
            for (int c = 0; c < 4; c++) sacc[j][c] = 0.f;

        #pragma unroll
        for (int kc = 0; kc < 4; kc++) {
            #pragma unroll
            for (int j = 0; j < 8; j++) {
                int boff = (j * 8 + g) * KPAD + kc * 16 + l4 * 2;
                uint32_t bh0 = *(const uint32_t*)(Khs + boff);
                uint32_t bh1 = *(const uint32_t*)(Khs + boff + 8);
                uint32_t bl0 = *(const uint32_t*)(Kls + boff);
                uint32_t bl1 = *(const uint32_t*)(Kls + boff + 8);
                mma16816(sacc[j], qh[kc], bh0, bh1);
                mma16816(sacc[j], ql[kc], bh0, bh1);
                mma16816(sacc[j], qh[kc], bl0, bl1);
            }
        }

        // ---- softmax (fixed shift) + repack P into A-fragments (reuse regs) ----
        uint32_t ps[8][4];
        #pragma unroll
        for (int j = 0; j < 8; j++) {
            float2 pen2 = *(const float2*)(pens + j * 8 + l4 * 2);
            float p0 = __expf(sacc[j][0] + pen2.x);
            float p1 = __expf(sacc[j][1] + pen2.y);
            float p2 = __expf(sacc[j][2] + pen2.x);
            float p3 = __expf(sacc[j][3] + pen2.y);
            lsum0 += p0 + p1;
            lsum1 += p2 + p3;
            float h0,l0,h1,l1,h2,l2,h3,l3;
            split_hi_lo(p0,h0,l0); split_hi_lo(p1,h1,l1);
            split_hi_lo(p2,h2,l2); split_hi_lo(p3,h3,l3);
            ps[j][0] = pack_bf16x2(h0, h1);   // c01 hi
            ps[j][1] = pack_bf16x2(h2, h3);   // c23 hi
            ps[j][2] = pack_bf16x2(l0, l1);   // c01 lo
            ps[j][3] = pack_bf16x2(l2, l3);   // c23 lo
        }

        // ---- O += P V (3-term split) ----
        #pragma unroll
        for (int kc = 0; kc < 4; kc++) {
            uint32_t Ah[4] = { ps[2*kc][0], ps[2*kc][1], ps[2*kc+1][0], ps[2*kc+1][1] };
            uint32_t Al[4] = { ps[2*kc][2], ps[2*kc][3], ps[2*kc+1][2], ps[2*kc+1][3] };
            #pragma unroll
            for (int j = 0; j < 8; j++) {
                int boff = (j * 8 + g) * KPAD + kc * 16 + l4 * 2;
                uint32_t bh0 = *(const uint32_t*)(Vhs + boff);
                uint32_t bh1 = *(const uint32_t*)(Vhs + boff + 8);
                uint32_t bl0 = *(const uint32_t*)(Vls + boff);
                uint32_t bl1 = *(const uint32_t*)(Vls + boff + 8);
                mma16816(oacc[j], Ah, bh0, bh1);
                mma16816(oacc[j], Al, bh0, bh1);
                mma16816(oacc[j], Ah, bl0, bl1);
            }
        }
        __syncthreads();
    }

    // ---- finalize: row sums across the quad, divide, store ----
    lsum0 += __shfl_xor_sync(0xffffffffu, lsum0, 1);
    lsum0 += __shfl_xor_sync(0xffffffffu, lsum0, 2);
    lsum1 += __shfl_xor_sync(0xffffffffu, lsum1, 1);
    lsum1 += __shfl_xor_sync(0xffffffffu, lsum1, 2);
    float inv0 = (lsum0 > 0.f) ? 1.f / lsum0 : 0.f;
    float inv1 = (lsum1 > 0.f) ? 1.f / lsum1 : 0.f;

    #pragma unroll
    for (int j = 0; j < 8; j++) {
        int d = j * 8 + l4 * 2;
        float2 v0 = { oacc[j][0] * inv0, oacc[j][1] * inv0 };
        float2 v1 = { oacc[j][2] * inv1, oacc[j][3] * inv1 };
        *(float2*)(Op + (size_t)(q0 + row0) * ND + d) = v0;
        *(float2*)(Op + (size_t)(q0 + row1) * ND + d) = v1;
    }
}

// ---------------------------------------------------------------------------
// Kernel 3: output projection + query-mask zeroing (fp32 SIMT).
// ---------------------------------------------------------------------------
__global__ __launch_bounds__(256) void out_proj(
    const float* __restrict__ Wo, const float* __restrict__ bo,
    const int* __restrict__ mask,
    float* __restrict__ out)
{
    __shared__ float As[32][65];
    __shared__ float Bs[32][65];

    const int tid = threadIdx.x;
    const int ty = tid >> 4, tx = tid & 15;
    const int m0 = blockIdx.x * 64;
    const int n0 = blockIdx.y * 64;

    float acc[4][4];
    #pragma unroll
    for (int i = 0; i < 4; i++)
        #pragma unroll
        for (int j = 0; j < 4; j++) acc[i][j] = 0.f;

    for (int k0 = 0; k0 < NE; k0 += 32) {
        const int hh = k0 >> 6;
        #pragma unroll
        for (int i = 0; i < 8; i++) {
            int idx = tid + i * 256;
            int m = idx >> 5, kk = idx & 31;
            int mm = m0 + m;
            int bb_ = mm >> 11, s = mm & (NS - 1);
            As[kk][m] = g_AO[(((size_t)bb_ * NH + hh) * NS + s) * ND + ((k0 + kk) & 63)];
        }
        #pragma unroll
        for (int i = 0; i < 8; i++) {
            int idx = tid + i * 256;
            int kk = idx >> 6, n = idx & 63;
            Bs[kk][n] = Wo[(k0 + kk) * NE + n0 + n];
        }
        __syncthreads();
        #pragma unroll 8
        for (int kk = 0; kk < 32; kk++) {
            float a[4], bb[4];
            #pragma unroll
            for (int i = 0; i < 4; i++) a[i] = As[kk][ty + 16 * i];
            #pragma unroll
            for (int j = 0; j < 4; j++) bb[j] = Bs[kk][tx + 16 * j];
            #pragma unroll
            for (int i = 0; i < 4; i++)
                #pragma unroll
                for (int j = 0; j < 4; j++)
                    acc[i][j] += a[i] * bb[j];
        }
        __syncthreads();
    }

    #pragma unroll
    for (int i = 0; i < 4; i++) {
        int m = m0 + ty + 16 * i;
        int b = m >> 11, s = m & (NS - 1);
        bool mq = mask[b * NS + s] != 0;
        #pragma unroll
        for (int j = 0; j < 4; j++) {
            int n = n0 + tx + 16 * j;
            out[(size_t)m * NE + n] = mq ? 0.f : (acc[i][j] + bo[n]);
        }
    }
}

// ---------------------------------------------------------------------------
extern "C" void kernel_launch(void* const* d_in, const int* in_sizes, int n_in,
                              void* d_out, int out_size)
{
    const float* his     = (const float*)d_in[0];
    const int*   mask    = (const int*)d_in[1];
    const float* explore = (const float*)d_in[2];
    const float* exploit = (const float*)d_in[3];
    const float* Wq = (const float*)d_in[4];
    const float* bq = (const float*)d_in[5];
    const float* Wk = (const float*)d_in[6];
    const float* bk = (const float*)d_in[7];
    const float* Wv = (const float*)d_in[8];
    const float* bv = (const float*)d_in[9];
    const float* Wo = (const float*)d_in[10];
    const float* bo = (const float*)d_in[11];
    float* out = (float*)d_out;

    qkv_proj<<<dim3(128, 4, 3), 256>>>(his, Wq, bq, Wk, bk, Wv, bv);
    attn_mma<<<dim3(NS / 128, NH, NB), 256>>>(mask, explore, exploit);
    out_proj<<<dim3(128, 4), 256>>>(Wo, bo, mask, out);
}

// round 5
// speedup vs baseline: 3.2092x; 1.3224x over previous
#include <cuda_runtime.h>
#include <cuda_bf16.h>
#include <cstdint>
#include <math.h>

#define NB 4
#define NS 2048
#define NE 256
#define NH 4
#define ND 64

// Scratch (allocation-free). g_V is stored TRANSPOSED: [b,h,d,s].
__device__ float g_Q[NB*NH*NS*ND];
__device__ float g_K[NB*NH*NS*ND];
__device__ float g_V[NB*NH*NS*ND];
__device__ float g_AO[NB*NH*NS*ND];

__device__ __forceinline__ uint32_t pack_bf16x2(float a, float b) {
    __nv_bfloat162 t = __floats2bfloat162_rn(a, b);   // a -> low half
    return *(uint32_t*)&t;
}
__device__ __forceinline__ void split_hi_lo(float x, float& hi, float& lo) {
    __nv_bfloat16 h = __float2bfloat16_rn(x);
    hi = __bfloat162float(h);
    lo = x - hi;
}

// mma.sync m16n8k16 row.col f32.bf16.bf16.f32  (sm_80+ PTX, no arch suffix)
__device__ __forceinline__ void mma16816(float c[4], const uint32_t a[4],
                                         uint32_t b0, uint32_t b1) {
    asm volatile(
        "mma.sync.aligned.m16n8k16.row.col.f32.bf16.bf16.f32 "
        "{%0,%1,%2,%3}, {%4,%5,%6,%7}, {%8,%9}, {%0,%1,%2,%3};"
        : "+f"(c[0]), "+f"(c[1]), "+f"(c[2]), "+f"(c[3])
        : "r"(a[0]), "r"(a[1]), "r"(a[2]), "r"(a[3]), "r"(b0), "r"(b1));
}

#define KPAD 72   // bf16 row stride; word stride 36 -> conflict-free frag LDS

__device__ __forceinline__ void store_split4(__nv_bfloat16* bh, __nv_bfloat16* bl,
                                             int off, float4 v) {
    float h0,l0,h1,l1,h2,l2,h3,l3;
    split_hi_lo(v.x,h0,l0); split_hi_lo(v.y,h1,l1);
    split_hi_lo(v.z,h2,l2); split_hi_lo(v.w,h3,l3);
    *(uint32_t*)(bh + off)     = pack_bf16x2(h0, h1);
    *(uint32_t*)(bh + off + 2) = pack_bf16x2(h2, h3);
    *(uint32_t*)(bl + off)     = pack_bf16x2(l0, l1);
    *(uint32_t*)(bl + off + 2) = pack_bf16x2(l2, l3);
}

// ---------------------------------------------------------------------------
// Kernel 1: fused QKV projection via mma.sync split-bf16.
// grid = (8192/128, NH). CTA: 128 rows x 64 cols (one head), K-loop 4x64.
// X tile split once, reused for Wq/Wk/Wv. V staged via smem -> [b,h,d,s].
// ---------------------------------------------------------------------------
#define XH_OFF   0
#define XL_OFF   (128*KPAD)               // bf16 elements
#define WTH_OFF  (2*128*KPAD)             // 3 mats x 64*KPAD
#define WTL_OFF  (2*128*KPAD + 3*64*KPAD)
#define QKV_SMEM_BF16 (2*128*KPAD + 6*64*KPAD)   // 46080 elems = 92160 B

__global__ __launch_bounds__(256, 1) void qkv_mma(
    const float* __restrict__ X,
    const float* __restrict__ Wq, const float* __restrict__ bq,
    const float* __restrict__ Wk, const float* __restrict__ bk,
    const float* __restrict__ Wv, const float* __restrict__ bv)
{
    extern __shared__ __nv_bfloat16 smb[];
    __nv_bfloat16* Xh = smb + XH_OFF;
    __nv_bfloat16* Xl = smb + XL_OFF;

    const int tid  = threadIdx.x;
    const int w    = tid >> 5;
    const int lane = tid & 31;
    const int g    = lane >> 2;
    const int l4   = lane & 3;
    const int m0   = blockIdx.x * 128;
    const int h    = blockIdx.y;
    const int n0   = h * 64;

    const float* Ws[3]    = { Wq, Wk, Wv };
    const float* bias[3]  = { bq, bk, bv };

    float acc[3][8][4];
    #pragma unroll
    for (int mt = 0; mt < 3; mt++)
        #pragma unroll
        for (int j = 0; j < 8; j++)
            #pragma unroll
            for (int c = 0; c < 4; c++) acc[mt][j][c] = 0.f;

    for (int k0 = 0; k0 < NE; k0 += 64) {
        // ---- load X tile [128 m][64 k], split hi/lo ----
        #pragma unroll
        for (int it = 0; it < 8; it++) {
            int idx = tid + it * 256;
            int r = idx >> 4, c = (idx & 15) * 4;
            float4 v = *(const float4*)(X + (size_t)(m0 + r) * NE + k0 + c);
            store_split4(Xh, Xl, r * KPAD + c, v);
        }
        // ---- load W tiles transposed: Wt[n][k], split hi/lo ----
        #pragma unroll
        for (int mt = 0; mt < 3; mt++) {
            __nv_bfloat16* Wth = smb + WTH_OFF + mt * 64 * KPAD;
            __nv_bfloat16* Wtl = smb + WTL_OFF + mt * 64 * KPAD;
            const float* W = Ws[mt];
            #pragma unroll
            for (int it = 0; it < 4; it++) {
                int idx = tid + it * 256;
                int kk = idx >> 4, nc = (idx & 15) * 4;
                float4 v = *(const float4*)(W + (size_t)(k0 + kk) * NE + n0 + nc);
                float hi, lo;
                split_hi_lo(v.x, hi, lo); Wth[(nc+0)*KPAD + kk] = __float2bfloat16_rn(hi); Wtl[(nc+0)*KPAD + kk] = __float2bfloat16_rn(lo);
                split_hi_lo(v.y, hi, lo); Wth[(nc+1)*KPAD + kk] = __float2bfloat16_rn(hi); Wtl[(nc+1)*KPAD + kk] = __float2bfloat16_rn(lo);
                split_hi_lo(v.z, hi, lo); Wth[(nc+2)*KPAD + kk] = __float2bfloat16_rn(hi); Wtl[(nc+2)*KPAD + kk] = __float2bfloat16_rn(lo);
                split_hi_lo(v.w, hi, lo); Wth[(nc+3)*KPAD + kk] = __float2bfloat16_rn(hi); Wtl[(nc+3)*KPAD + kk] = __float2bfloat16_rn(lo);
            }
        }
        __syncthreads();

        #pragma unroll
        for (int kc = 0; kc < 4; kc++) {
            int aoff = (w * 16 + g) * KPAD + kc * 16 + l4 * 2;
            uint32_t ah[4], al[4];
            ah[0] = *(const uint32_t*)(Xh + aoff);
            ah[1] = *(const uint32_t*)(Xh + aoff + 8 * KPAD);
            ah[2] = *(const uint32_t*)(Xh + aoff + 8);
            ah[3] = *(const uint32_t*)(Xh + aoff + 8 * KPAD + 8);
            al[0] = *(const uint32_t*)(Xl + aoff);
            al[1] = *(const uint32_t*)(Xl + aoff + 8 * KPAD);
            al[2] = *(const uint32_t*)(Xl + aoff + 8);
            al[3] = *(const uint32_t*)(Xl + aoff + 8 * KPAD + 8);

            #pragma unroll
            for (int mt = 0; mt < 3; mt++) {
                const __nv_bfloat16* Wth = smb + WTH_OFF + mt * 64 * KPAD;
                const __nv_bfloat16* Wtl = smb + WTL_OFF + mt * 64 * KPAD;
                #pragma unroll
                for (int j = 0; j < 8; j++) {
                    int boff = (j * 8 + g) * KPAD + kc * 16 + l4 * 2;
                    uint32_t bh0 = *(const uint32_t*)(Wth + boff);
                    uint32_t bh1 = *(const uint32_t*)(Wth + boff + 8);
                    uint32_t bl0 = *(const uint32_t*)(Wtl + boff);
                    uint32_t bl1 = *(const uint32_t*)(Wtl + boff + 8);
                    mma16816(acc[mt][j], ah, bh0, bh1);
                    mma16816(acc[mt][j], al, bh0, bh1);
                    mma16816(acc[mt][j], ah, bl0, bl1);
                }
            }
        }
        __syncthreads();
    }

    // ---- epilogue: Q, K direct scatter [b,h,s,d] ----
    const int row0 = m0 + w * 16 + g;
    const int row1 = row0 + 8;
    const int b0_ = row0 >> 11, s0 = row0 & (NS - 1);
    const int b1_ = row1 >> 11, s1 = row1 & (NS - 1);
    float* outQK[2] = { g_Q, g_K };
    #pragma unroll
    for (int mt = 0; mt < 2; mt++) {
        float* O0 = outQK[mt] + (((size_t)b0_ * NH + h) * NS + s0) * ND;
        float* O1 = outQK[mt] + (((size_t)b1_ * NH + h) * NS + s1) * ND;
        const float* bb = bias[mt];
        #pragma unroll
        for (int j = 0; j < 8; j++) {
            int d = j * 8 + 2 * l4;
            float bx = bb[n0 + d], by = bb[n0 + d + 1];
            float2 v0 = { acc[mt][j][0] + bx, acc[mt][j][1] + by };
            float2 v1 = { acc[mt][j][2] + bx, acc[mt][j][3] + by };
            *(float2*)(O0 + d) = v0;
            *(float2*)(O1 + d) = v1;
        }
    }

    // ---- V: stage [d][s] in smem, then coalesced write to [b,h,d,s] ----
    #define VPAD 132
    float* Vb = (float*)smb;   // 64*132*4 = 33792 B, overlays X tiles
    #pragma unroll
    for (int j = 0; j < 8; j++) {
        int d = j * 8 + 2 * l4;
        float bx = bv[n0 + d], by = bv[n0 + d + 1];
        int sr0 = w * 16 + g, sr1 = sr0 + 8;
        Vb[(d    ) * VPAD + sr0] = acc[2][j][0] + bx;
        Vb[(d + 1) * VPAD + sr0] = acc[2][j][1] + by;
        Vb[(d    ) * VPAD + sr1] = acc[2][j][2] + bx;
        Vb[(d + 1) * VPAD + sr1] = acc[2][j][3] + by;
    }
    __syncthreads();
    // rows of Vb: 64 d x 128 s. write float4 along s.
    #pragma unroll
    for (int it = 0; it < 8; it++) {
        int idx = tid + it * 256;
        int d = idx >> 5, c4 = (idx & 31) * 4;
        int m = m0 + c4;
        int bb_ = m >> 11, s = m & (NS - 1);
        float4 v = { Vb[d * VPAD + c4], Vb[d * VPAD + c4 + 1],
                     Vb[d * VPAD + c4 + 2], Vb[d * VPAD + c4 + 3] };
        *(float4*)(g_V + (((size_t)bb_ * NH + h) * ND + d) * NS + s) = v;
    }
}

// ---------------------------------------------------------------------------
// Kernel 2: flash attention via mma.sync bf16 split (3-term). (unchanged)
// ---------------------------------------------------------------------------
__global__ __launch_bounds__(256, 2) void attn_mma(
    const int* __restrict__ mask,
    const float* __restrict__ explore,
    const float* __restrict__ exploit)
{
    __shared__ __nv_bfloat16 Khs[64*KPAD], Kls[64*KPAD];
    __shared__ __nv_bfloat16 Vhs[64*KPAD], Vls[64*KPAD];
    __shared__ float pens[64];

    const int tid  = threadIdx.x;
    const int w    = tid >> 5;
    const int lane = tid & 31;
    const int g    = lane >> 2;
    const int l4   = lane & 3;
    const int q0   = blockIdx.x * 128;
    const int h    = blockIdx.y, b = blockIdx.z;

    const size_t base = ((size_t)b * NH + h) * NS * ND;
    const float* Qp  = g_Q + base;
    const float* Kp  = g_K + base;
    const float* Vtp = g_V + base;    // [d][s]
    float*       Op  = g_AO + base;

    const int row0 = w * 16 + g;
    const int row1 = row0 + 8;
    float rs0, rs1;
    {
        int s0 = q0 + row0, s1 = q0 + row1;
        float t0 = 1.0f + 0.5f * explore[b * NS + s0] - 0.5f * exploit[b * NS + s0];
        t0 = fminf(fmaxf(t0, 0.5f), 2.0f);
        if (mask[b * NS + s0] != 0) t0 = 1.0f;
        rs0 = 0.125f / t0;
        float t1 = 1.0f + 0.5f * explore[b * NS + s1] - 0.5f * exploit[b * NS + s1];
        t1 = fminf(fmaxf(t1, 0.5f), 2.0f);
        if (mask[b * NS + s1] != 0) t1 = 1.0f;
        rs1 = 0.125f / t1;
    }

    uint32_t qh[4][4], ql[4][4];
    #pragma unroll
    for (int kc = 0; kc < 4; kc++) {
        int d0 = kc * 16 + l4 * 2;
        const float2 a00 = *(const float2*)(Qp + (size_t)(q0 + row0) * ND + d0);
        const float2 a10 = *(const float2*)(Qp + (size_t)(q0 + row1) * ND + d0);
        const float2 a01 = *(const float2*)(Qp + (size_t)(q0 + row0) * ND + d0 + 8);
        const float2 a11 = *(const float2*)(Qp + (size_t)(q0 + row1) * ND + d0 + 8);
        float hx, lx, hy, ly;
        split_hi_lo(a00.x * rs0, hx, lx); split_hi_lo(a00.y * rs0, hy, ly);
        qh[kc][0] = pack_bf16x2(hx, hy);  ql[kc][0] = pack_bf16x2(lx, ly);
        split_hi_lo(a10.x * rs1, hx, lx); split_hi_lo(a10.y * rs1, hy, ly);
        qh[kc][1] = pack_bf16x2(hx, hy);  ql[kc][1] = pack_bf16x2(lx, ly);
        split_hi_lo(a01.x * rs0, hx, lx); split_hi_lo(a01.y * rs0, hy, ly);
        qh[kc][2] = pack_bf16x2(hx, hy);  ql[kc][2] = pack_bf16x2(lx, ly);
        split_hi_lo(a11.x * rs1, hx, lx); split_hi_lo(a11.y * rs1, hy, ly);
        qh[kc][3] = pack_bf16x2(hx, hy);  ql[kc][3] = pack_bf16x2(lx, ly);
    }

    float oacc[8][4];
    #pragma unroll
    for (int j = 0; j < 8; j++)
        #pragma unroll
        for (int c = 0; c < 4; c++) oacc[j][c] = 0.f;
    float lsum0 = 0.f, lsum1 = 0.f;

    for (int kt = 0; kt < NS / 64; kt++) {
        const int kk0 = kt * 64;

        #pragma unroll
        for (int it = 0; it < 4; it++) {
            int idx = tid + it * 256;
            int r = idx >> 4, c = (idx & 15) * 4;
            float4 kv = *(const float4*)(Kp + (size_t)(kk0 + r) * ND + c);
            store_split4(Khs, Kls, r * KPAD + c, kv);
            float4 vv = *(const float4*)(Vtp + (size_t)r * NS + kk0 + c);
            store_split4(Vhs, Vls, r * KPAD + c, vv);
        }
        if (tid < 64) pens[tid] = (mask[b * NS + kk0 + tid] != 0) ? -1e30f : 0.f;
        __syncthreads();

        float sacc[8][4];
        #pragma unroll
        for (int j = 0; j < 8; j++)
            #pragma unroll
            for (int c = 0; c < 4; c++) sacc[j][c] = 0.f;

        #pragma unroll
        for (int kc = 0; kc < 4; kc++) {
            #pragma unroll
            for (int j = 0; j < 8; j++) {
                int boff = (j * 8 + g) * KPAD + kc * 16 + l4 * 2;
                uint32_t bh0 = *(const uint32_t*)(Khs + boff);
                uint32_t bh1 = *(const uint32_t*)(Khs + boff + 8);
                uint32_t bl0 = *(const uint32_t*)(Kls + boff);
                uint32_t bl1 = *(const uint32_t*)(Kls + boff + 8);
                mma16816(sacc[j], qh[kc], bh0, bh1);
                mma16816(sacc[j], ql[kc], bh0, bh1);
                mma16816(sacc[j], qh[kc], bl0, bl1);
            }
        }

        uint32_t ps[8][4];
        #pragma unroll
        for (int j = 0; j < 8; j++) {
            float2 pen2 = *(const float2*)(pens + j * 8 + l4 * 2);
            float p0 = __expf(sacc[j][0] + pen2.x);
            float p1 = __expf(sacc[j][1] + pen2.y);
            float p2 = __expf(sacc[j][2] + pen2.x);
            float p3 = __expf(sacc[j][3] + pen2.y);
            lsum0 += p0 + p1;
            lsum1 += p2 + p3;
            float h0,l0,h1,l1,h2,l2,h3,l3;
            split_hi_lo(p0,h0,l0); split_hi_lo(p1,h1,l1);
            split_hi_lo(p2,h2,l2); split_hi_lo(p3,h3,l3);
            ps[j][0] = pack_bf16x2(h0, h1);
            ps[j][1] = pack_bf16x2(h2, h3);
            ps[j][2] = pack_bf16x2(l0, l1);
            ps[j][3] = pack_bf16x2(l2, l3);
        }

        #pragma unroll
        for (int kc = 0; kc < 4; kc++) {
            uint32_t Ah[4] = { ps[2*kc][0], ps[2*kc][1], ps[2*kc+1][0], ps[2*kc+1][1] };
            uint32_t Al[4] = { ps[2*kc][2], ps[2*kc][3], ps[2*kc+1][2], ps[2*kc+1][3] };
            #pragma unroll
            for (int j = 0; j < 8; j++) {
                int boff = (j * 8 + g) * KPAD + kc * 16 + l4 * 2;
                uint32_t bh0 = *(const uint32_t*)(Vhs + boff);
                uint32_t bh1 = *(const uint32_t*)(Vhs + boff + 8);
                uint32_t bl0 = *(const uint32_t*)(Vls + boff);
                uint32_t bl1 = *(const uint32_t*)(Vls + boff + 8);
                mma16816(oacc[j], Ah, bh0, bh1);
                mma16816(oacc[j], Al, bh0, bh1);
                mma16816(oacc[j], Ah, bl0, bl1);
            }
        }
        __syncthreads();
    }

    lsum0 += __shfl_xor_sync(0xffffffffu, lsum0, 1);
    lsum0 += __shfl_xor_sync(0xffffffffu, lsum0, 2);
    lsum1 += __shfl_xor_sync(0xffffffffu, lsum1, 1);
    lsum1 += __shfl_xor_sync(0xffffffffu, lsum1, 2);
    float inv0 = (lsum0 > 0.f) ? 1.f / lsum0 : 0.f;
    float inv1 = (lsum1 > 0.f) ? 1.f / lsum1 : 0.f;

    #pragma unroll
    for (int j = 0; j < 8; j++) {
        int d = j * 8 + l4 * 2;
        float2 v0 = { oacc[j][0] * inv0, oacc[j][1] * inv0 };
        float2 v1 = { oacc[j][2] * inv1, oacc[j][3] * inv1 };
        *(float2*)(Op + (size_t)(q0 + row0) * ND + d) = v0;
        *(float2*)(Op + (size_t)(q0 + row1) * ND + d) = v1;
    }
}

// ---------------------------------------------------------------------------
// Kernel 3: output projection via mma.sync split-bf16 + mask zeroing.
// grid = (64, 4). CTA: 128 rows x 64 cols, K-loop 4x64 (one head per chunk).
// ---------------------------------------------------------------------------
#define OP_WTH_OFF (2*128*KPAD)
#define OP_WTL_OFF (2*128*KPAD + 64*KPAD)
#define OP_SMEM_BF16 (2*128*KPAD + 2*64*KPAD)   // 27648 elems = 55296 B

__global__ __launch_bounds__(256, 1) void out_proj_mma(
    const float* __restrict__ Wo, const float* __restrict__ bo,
    const int* __restrict__ mask,
    float* __restrict__ out)
{
    extern __shared__ __nv_bfloat16 smb[];
    __nv_bfloat16* Xh  = smb + XH_OFF;
    __nv_bfloat16* Xl  = smb + XL_OFF;
    __nv_bfloat16* Wth = smb + OP_WTH_OFF;
    __nv_bfloat16* Wtl = smb + OP_WTL_OFF;

    const int tid  = threadIdx.x;
    const int w    = tid >> 5;
    const int lane = tid & 31;
    const int g    = lane >> 2;
    const int l4   = lane & 3;
    const int m0   = blockIdx.x * 128;
    const int n0   = blockIdx.y * 64;

    float acc[8][4];
    #pragma unroll
    for (int j = 0; j < 8; j++)
        #pragma unroll
        for (int c = 0; c < 4; c++) acc[j][c] = 0.f;

    for (int k0 = 0; k0 < NE; k0 += 64) {
        const int hh = k0 >> 6;
        #pragma unroll
        for (int it = 0; it < 8; it++) {
            int idx = tid + it * 256;
            int r = idx >> 4, c = (idx & 15) * 4;
            int m = m0 + r;
            int bb_ = m >> 11, s = m & (NS - 1);
            float4 v = *(const float4*)(g_AO + (((size_t)bb_ * NH + hh) * NS + s) * ND + c);
            store_split4(Xh, Xl, r * KPAD + c, v);
        }
        #pragma unroll
        for (int it = 0; it < 4; it++) {
            int idx = tid + it * 256;
            int kk = idx >> 4, nc = (idx & 15) * 4;
            float4 v = *(const float4*)(Wo + (size_t)(k0 + kk) * NE + n0 + nc);
            float hi, lo;
            split_hi_lo(v.x, hi, lo); Wth[(nc+0)*KPAD + kk] = __float2bfloat16_rn(hi); Wtl[(nc+0)*KPAD + kk] = __float2bfloat16_rn(lo);
            split_hi_lo(v.y, hi, lo); Wth[(nc+1)*KPAD + kk] = __float2bfloat16_rn(hi); Wtl[(nc+1)*KPAD + kk] = __float2bfloat16_rn(lo);
            split_hi_lo(v.z, hi, lo); Wth[(nc+2)*KPAD + kk] = __float2bfloat16_rn(hi); Wtl[(nc+2)*KPAD + kk] = __float2bfloat16_rn(lo);
            split_hi_lo(v.w, hi, lo); Wth[(nc+3)*KPAD + kk] = __float2bfloat16_rn(hi); Wtl[(nc+3)*KPAD + kk] = __float2bfloat16_rn(lo);
        }
        __syncthreads();

        #pragma unroll
        for (int kc = 0; kc < 4; kc++) {
            int aoff = (w * 16 + g) * KPAD + kc * 16 + l4 * 2;
            uint32_t ah[4], al[4];
            ah[0] = *(const uint32_t*)(Xh + aoff);
            ah[1] = *(const uint32_t*)(Xh + aoff + 8 * KPAD);
            ah[2] = *(const uint32_t*)(Xh + aoff + 8);
            ah[3] = *(const uint32_t*)(Xh + aoff + 8 * KPAD + 8);
            al[0] = *(const uint32_t*)(Xl + aoff);
            al[1] = *(const uint32_t*)(Xl + aoff + 8 * KPAD);
            al[2] = *(const uint32_t*)(Xl + aoff + 8);
            al[3] = *(const uint32_t*)(Xl + aoff + 8 * KPAD + 8);
            #pragma unroll
            for (int j = 0; j < 8; j++) {
                int boff = (j * 8 + g) * KPAD + kc * 16 + l4 * 2;
                uint32_t bh0 = *(const uint32_t*)(Wth + boff);
                uint32_t bh1 = *(const uint32_t*)(Wth + boff + 8);
                uint32_t bl0 = *(const uint32_t*)(Wtl + boff);
                uint32_t bl1 = *(const uint32_t*)(Wtl + boff + 8);
                mma16816(acc[j], ah, bh0, bh1);
                mma16816(acc[j], al, bh0, bh1);
                mma16816(acc[j], ah, bl0, bl1);
            }
        }
        __syncthreads();
    }

    const int row0 = m0 + w * 16 + g;
    const int row1 = row0 + 8;
    const int b0_ = row0 >> 11, s0 = row0 & (NS - 1);
    const int b1_ = row1 >> 11, s1 = row1 & (NS - 1);
    const bool mq0 = mask[b0_ * NS + s0] != 0;
    const bool mq1 = mask[b1_ * NS + s1] != 0;
    #pragma unroll
    for (int j = 0; j < 8; j++) {
        int d = j * 8 + 2 * l4;
        float bx = bo[n0 + d], by = bo[n0 + d + 1];
        float2 v0 = { mq0 ? 0.f : acc[j][0] + bx, mq0 ? 0.f : acc[j][1] + by };
        float2 v1 = { mq1 ? 0.f : acc[j][2] + bx, mq1 ? 0.f : acc[j][3] + by };
        *(float2*)(out + (size_t)row0 * NE + n0 + d) = v0;
        *(float2*)(out + (size_t)row1 * NE + n0 + d) = v1;
    }
}

// ---------------------------------------------------------------------------
extern "C" void kernel_launch(void* const* d_in, const int* in_sizes, int n_in,
                              void* d_out, int out_size)
{
    const float* his     = (const float*)d_in[0];
    const int*   mask    = (const int*)d_in[1];
    const float* explore = (const float*)d_in[2];
    const float* exploit = (const float*)d_in[3];
    const float* Wq = (const float*)d_in[4];
    const float* bq = (const float*)d_in[5];
    const float* Wk = (const float*)d_in[6];
    const float* bk = (const float*)d_in[7];
    const float* Wv = (const float*)d_in[8];
    const float* bv = (const float*)d_in[9];
    const float* Wo = (const float*)d_in[10];
    const float* bo = (const float*)d_in[11];
    float* out = (float*)d_out;

    const int qkv_smem = QKV_SMEM_BF16 * 2;     // 92160 B
    const int op_smem  = OP_SMEM_BF16 * 2;      // 55296 B
    static bool attr_done = false;
    if (!attr_done) {
        cudaFuncSetAttribute(qkv_mma, cudaFuncAttributeMaxDynamicSharedMemorySize, qkv_smem);
        cudaFuncSetAttribute(out_proj_mma, cudaFuncAttributeMaxDynamicSharedMemorySize, op_smem);
        attr_done = true;
    }

    qkv_mma<<<dim3(8192 / 128, NH), 256, qkv_smem>>>(his, Wq, bq, Wk, bk, Wv, bv);
    attn_mma<<<dim3(NS / 128, NH, NB), 256>>>(mask, explore, exploit);
    out_proj_mma<<<dim3(8192 / 128, 4), 256, op_smem>>>(Wo, bo, mask, out);
}

// round 6
// speedup vs baseline: 3.4757x; 1.0830x over previous
#include <cuda_runtime.h>
#include <cuda_bf16.h>
#include <cstdint>
#include <math.h>

#define NB 4
#define NS 2048
#define NE 256
#define NH 4
#define ND 64

// Scratch (allocation-free).
__device__ float g_Q[NB*NH*NS*ND];                                  // [b,h,s,d] fp32
__device__ __align__(16) __nv_bfloat16 g_Kh[NB*NH*NS*ND];           // [b,h,s,d]
__device__ __align__(16) __nv_bfloat16 g_Kl[NB*NH*NS*ND];
__device__ __align__(16) __nv_bfloat16 g_Vh[NB*NH*ND*NS];           // [b,h,d,s]
__device__ __align__(16) __nv_bfloat16 g_Vl[NB*NH*ND*NS];
__device__ __align__(16) __nv_bfloat16 g_AOh[NB*NH*NS*ND];          // [b,h,s,d]
__device__ __align__(16) __nv_bfloat16 g_AOl[NB*NH*NS*ND];
__device__ __align__(16) __nv_bfloat16 g_Wth[4*NE*NE];              // [mat][n][k]
__device__ __align__(16) __nv_bfloat16 g_Wtl[4*NE*NE];

__device__ __forceinline__ uint32_t pack_bf16x2(float a, float b) {
    __nv_bfloat162 t = __floats2bfloat162_rn(a, b);   // a -> low half
    return *(uint32_t*)&t;
}
__device__ __forceinline__ void split_hi_lo(float x, float& hi, float& lo) {
    __nv_bfloat16 h = __float2bfloat16_rn(x);
    hi = __bfloat162float(h);
    lo = x - hi;
}

// mma.sync m16n8k16 row.col f32.bf16.bf16.f32  (sm_80+ PTX, no arch suffix)
__device__ __forceinline__ void mma16816(float c[4], const uint32_t a[4],
                                         uint32_t b0, uint32_t b1) {
    asm volatile(
        "mma.sync.aligned.m16n8k16.row.col.f32.bf16.bf16.f32 "
        "{%0,%1,%2,%3}, {%4,%5,%6,%7}, {%8,%9}, {%0,%1,%2,%3};"
        : "+f"(c[0]), "+f"(c[1]), "+f"(c[2]), "+f"(c[3])
        : "r"(a[0]), "r"(a[1]), "r"(a[2]), "r"(a[3]), "r"(b0), "r"(b1));
}

#define KPAD 72   // bf16 row stride; word stride 36 -> conflict-free frag LDS

__device__ __forceinline__ void store_split4(__nv_bfloat16* bh, __nv_bfloat16* bl,
                                             int off, float4 v) {
    float h0,l0,h1,l1,h2,l2,h3,l3;
    split_hi_lo(v.x,h0,l0); split_hi_lo(v.y,h1,l1);
    split_hi_lo(v.z,h2,l2); split_hi_lo(v.w,h3,l3);
    *(uint32_t*)(bh + off)     = pack_bf16x2(h0, h1);
    *(uint32_t*)(bh + off + 2) = pack_bf16x2(h2, h3);
    *(uint32_t*)(bl + off)     = pack_bf16x2(l0, l1);
    *(uint32_t*)(bl + off + 2) = pack_bf16x2(l2, l3);
}

// ---------------------------------------------------------------------------
// Kernel 0: pre-split weights -> transposed hi/lo bf16 [mat][n][k].
// grid = (4 ktiles, 4 ntiles, 4 mats), 256 threads.
// ---------------------------------------------------------------------------
__global__ __launch_bounds__(256) void prep_w(
    const float* __restrict__ Wq, const float* __restrict__ Wk,
    const float* __restrict__ Wv, const float* __restrict__ Wo)
{
    __shared__ float t[64][65];
    const float* Ws[4] = { Wq, Wk, Wv, Wo };
    const int mt = blockIdx.z;
    const int k0 = blockIdx.x * 64, n0 = blockIdx.y * 64;
    const int tid = threadIdx.x;
    const float* W = Ws[mt];

    #pragma unroll
    for (int it = 0; it < 16; it++) {
        int idx = tid + it * 256;
        int kk = idx >> 6, nn = idx & 63;
        t[kk][nn] = W[(k0 + kk) * NE + n0 + nn];
    }
    __syncthreads();

    #pragma unroll
    for (int it = 0; it < 2; it++) {
        int idx = tid + it * 256;
        int n = idx >> 3, c8 = (idx & 7) * 8;
        uint32_t hw[4], lw[4];
        #pragma unroll
        for (int p = 0; p < 4; p++) {
            float hi0, lo0, hi1, lo1;
            split_hi_lo(t[c8 + 2*p][n],     hi0, lo0);
            split_hi_lo(t[c8 + 2*p + 1][n], hi1, lo1);
            hw[p] = pack_bf16x2(hi0, hi1);
            lw[p] = pack_bf16x2(lo0, lo1);
        }
        size_t o = (size_t)mt * NE * NE + (size_t)(n0 + n) * NE + k0 + c8;
        *(uint4*)(g_Wth + o) = *(uint4*)hw;
        *(uint4*)(g_Wtl + o) = *(uint4*)lw;
    }
}

// ---------------------------------------------------------------------------
// Kernel 1: fused QKV projection via mma.sync split-bf16.
// grid = (8192/128, NH). X split once/CTA; W tiles copied pre-split.
// Writes: g_Q fp32; g_Kh/g_Kl bf16 [b,h,s,d]; g_Vh/g_Vl bf16 [b,h,d,s].
// ---------------------------------------------------------------------------
#define XH_OFF   0
#define XL_OFF   (128*KPAD)
#define WTH_OFF  (2*128*KPAD)
#define WTL_OFF  (2*128*KPAD + 3*64*KPAD)
#define QKV_SMEM_BF16 (2*128*KPAD + 6*64*KPAD)   // 92160 B

__global__ __launch_bounds__(256, 1) void qkv_mma(
    const float* __restrict__ X,
    const float* __restrict__ bq, const float* __restrict__ bk,
    const float* __restrict__ bv)
{
    extern __shared__ __nv_bfloat16 smb[];
    __nv_bfloat16* Xh = smb + XH_OFF;
    __nv_bfloat16* Xl = smb + XL_OFF;

    const int tid  = threadIdx.x;
    const int w    = tid >> 5;
    const int lane = tid & 31;
    const int g    = lane >> 2;
    const int l4   = lane & 3;
    const int m0   = blockIdx.x * 128;
    const int h    = blockIdx.y;
    const int n0   = h * 64;

    float acc[3][8][4];
    #pragma unroll
    for (int mt = 0; mt < 3; mt++)
        #pragma unroll
        for (int j = 0; j < 8; j++)
            #pragma unroll
            for (int c = 0; c < 4; c++) acc[mt][j][c] = 0.f;

    for (int k0 = 0; k0 < NE; k0 += 64) {
        // ---- X tile [128 m][64 k], split hi/lo ----
        #pragma unroll
        for (int it = 0; it < 8; it++) {
            int idx = tid + it * 256;
            int r = idx >> 4, c = (idx & 15) * 4;
            float4 v = *(const float4*)(X + (size_t)(m0 + r) * NE + k0 + c);
            store_split4(Xh, Xl, r * KPAD + c, v);
        }
        // ---- W tiles (pre-split, transposed) straight copy ----
        #pragma unroll
        for (int mt = 0; mt < 3; mt++) {
            __nv_bfloat16* Wth = smb + WTH_OFF + mt * 64 * KPAD;
            __nv_bfloat16* Wtl = smb + WTL_OFF + mt * 64 * KPAD;
            const size_t wb = (size_t)mt * NE * NE;
            #pragma unroll
            for (int it = 0; it < 2; it++) {
                int idx = tid + it * 256;
                int r = idx >> 3, c8 = (idx & 7) * 8;
                size_t o = wb + (size_t)(n0 + r) * NE + k0 + c8;
                *(uint4*)(Wth + r * KPAD + c8) = *(const uint4*)(g_Wth + o);
                *(uint4*)(Wtl + r * KPAD + c8) = *(const uint4*)(g_Wtl + o);
            }
        }
        __syncthreads();

        #pragma unroll
        for (int kc = 0; kc < 4; kc++) {
            int aoff = (w * 16 + g) * KPAD + kc * 16 + l4 * 2;
            uint32_t ah[4], al[4];
            ah[0] = *(const uint32_t*)(Xh + aoff);
            ah[1] = *(const uint32_t*)(Xh + aoff + 8 * KPAD);
            ah[2] = *(const uint32_t*)(Xh + aoff + 8);
            ah[3] = *(const uint32_t*)(Xh + aoff + 8 * KPAD + 8);
            al[0] = *(const uint32_t*)(Xl + aoff);
            al[1] = *(const uint32_t*)(Xl + aoff + 8 * KPAD);
            al[2] = *(const uint32_t*)(Xl + aoff + 8);
            al[3] = *(const uint32_t*)(Xl + aoff + 8 * KPAD + 8);

            #pragma unroll
            for (int mt = 0; mt < 3; mt++) {
                const __nv_bfloat16* Wth = smb + WTH_OFF + mt * 64 * KPAD;
                const __nv_bfloat16* Wtl = smb + WTL_OFF + mt * 64 * KPAD;
                #pragma unroll
                for (int j = 0; j < 8; j++) {
                    int boff = (j * 8 + g) * KPAD + kc * 16 + l4 * 2;
                    uint32_t bh0 = *(const uint32_t*)(Wth + boff);
                    uint32_t bh1 = *(const uint32_t*)(Wth + boff + 8);
                    uint32_t bl0 = *(const uint32_t*)(Wtl + boff);
                    uint32_t bl1 = *(const uint32_t*)(Wtl + boff + 8);
                    mma16816(acc[mt][j], ah, bh0, bh1);
                    mma16816(acc[mt][j], al, bh0, bh1);
                    mma16816(acc[mt][j], ah, bl0, bl1);
                }
            }
        }
        __syncthreads();
    }

    const int row0 = m0 + w * 16 + g;
    const int row1 = row0 + 8;
    const int b0_ = row0 >> 11, s0 = row0 & (NS - 1);
    const int b1_ = row1 >> 11, s1 = row1 & (NS - 1);

    // ---- Q: fp32 scatter ----
    {
        float* O0 = g_Q + (((size_t)b0_ * NH + h) * NS + s0) * ND;
        float* O1 = g_Q + (((size_t)b1_ * NH + h) * NS + s1) * ND;
        #pragma unroll
        for (int j = 0; j < 8; j++) {
            int d = j * 8 + 2 * l4;
            float bx = bq[n0 + d], by = bq[n0 + d + 1];
            float2 v0 = { acc[0][j][0] + bx, acc[0][j][1] + by };
            float2 v1 = { acc[0][j][2] + bx, acc[0][j][3] + by };
            *(float2*)(O0 + d) = v0;
            *(float2*)(O1 + d) = v1;
        }
    }
    // ---- K: hi/lo bf16 scatter ----
    {
        size_t o0 = (((size_t)b0_ * NH + h) * NS + s0) * ND;
        size_t o1 = (((size_t)b1_ * NH + h) * NS + s1) * ND;
        #pragma unroll
        for (int j = 0; j < 8; j++) {
            int d = j * 8 + 2 * l4;
            float bx = bk[n0 + d], by = bk[n0 + d + 1];
            float h0,l0,h1,l1;
            split_hi_lo(acc[1][j][0] + bx, h0, l0);
            split_hi_lo(acc[1][j][1] + by, h1, l1);
            *(uint32_t*)(g_Kh + o0 + d) = pack_bf16x2(h0, h1);
            *(uint32_t*)(g_Kl + o0 + d) = pack_bf16x2(l0, l1);
            split_hi_lo(acc[1][j][2] + bx, h0, l0);
            split_hi_lo(acc[1][j][3] + by, h1, l1);
            *(uint32_t*)(g_Kh + o1 + d) = pack_bf16x2(h0, h1);
            *(uint32_t*)(g_Kl + o1 + d) = pack_bf16x2(l0, l1);
        }
    }
    // ---- V: stage [d][s] fp32 in smem, split-write to [b,h,d,s] hi/lo ----
    #define VPAD 132
    __syncthreads();
    float* Vb = (float*)smb;   // 64*132*4 = 33792 B, overlays tiles
    #pragma unroll
    for (int j = 0; j < 8; j++) {
        int d = j * 8 + 2 * l4;
        float bx = bv[n0 + d], by = bv[n0 + d + 1];
        int sr0 = w * 16 + g, sr1 = sr0 + 8;
        Vb[(d    ) * VPAD + sr0] = acc[2][j][0] + bx;
        Vb[(d + 1) * VPAD + sr0] = acc[2][j][1] + by;
        Vb[(d    ) * VPAD + sr1] = acc[2][j][2] + bx;
        Vb[(d + 1) * VPAD + sr1] = acc[2][j][3] + by;
    }
    __syncthreads();
    #pragma unroll
    for (int it = 0; it < 8; it++) {
        int idx = tid + it * 256;
        int d = idx >> 5, c4 = (idx & 31) * 4;
        int m = m0 + c4;
        int bb_ = m >> 11, s = m & (NS - 1);
        float h0,l0,h1,l1,h2,l2,h3,l3;
        split_hi_lo(Vb[d * VPAD + c4],     h0, l0);
        split_hi_lo(Vb[d * VPAD + c4 + 1], h1, l1);
        split_hi_lo(Vb[d * VPAD + c4 + 2], h2, l2);
        split_hi_lo(Vb[d * VPAD + c4 + 3], h3, l3);
        size_t o = (((size_t)bb_ * NH + h) * ND + d) * NS + s;
        uint32_t hw[2] = { pack_bf16x2(h0, h1), pack_bf16x2(h2, h3) };
        uint32_t lw[2] = { pack_bf16x2(l0, l1), pack_bf16x2(l2, l3) };
        *(uint2*)(g_Vh + o) = *(uint2*)hw;
        *(uint2*)(g_Vl + o) = *(uint2*)lw;
    }
}

// ---------------------------------------------------------------------------
// Kernel 2: flash attention via mma.sync bf16 split. K/V pre-split bf16.
// ---------------------------------------------------------------------------
__global__ __launch_bounds__(256, 2) void attn_mma(
    const int* __restrict__ mask,
    const float* __restrict__ explore,
    const float* __restrict__ exploit)
{
    __shared__ __align__(16) __nv_bfloat16 Khs[64*KPAD], Kls[64*KPAD];
    __shared__ __align__(16) __nv_bfloat16 Vhs[64*KPAD], Vls[64*KPAD];
    __shared__ float pens[64];

    const int tid  = threadIdx.x;
    const int w    = tid >> 5;
    const int lane = tid & 31;
    const int g    = lane >> 2;
    const int l4   = lane & 3;
    const int q0   = blockIdx.x * 128;
    const int h    = blockIdx.y, b = blockIdx.z;

    const size_t base = ((size_t)b * NH + h) * NS * ND;
    const float* Qp = g_Q + base;
    const __nv_bfloat16* Khp = g_Kh + base;
    const __nv_bfloat16* Klp = g_Kl + base;
    const __nv_bfloat16* Vhp = g_Vh + base;   // [d][s]
    const __nv_bfloat16* Vlp = g_Vl + base;

    const int row0 = w * 16 + g;
    const int row1 = row0 + 8;
    float rs0, rs1;
    {
        int s0 = q0 + row0, s1 = q0 + row1;
        float t0 = 1.0f + 0.5f * explore[b * NS + s0] - 0.5f * exploit[b * NS + s0];
        t0 = fminf(fmaxf(t0, 0.5f), 2.0f);
        if (mask[b * NS + s0] != 0) t0 = 1.0f;
        rs0 = 0.125f / t0;
        float t1 = 1.0f + 0.5f * explore[b * NS + s1] - 0.5f * exploit[b * NS + s1];
        t1 = fminf(fmaxf(t1, 0.5f), 2.0f);
        if (mask[b * NS + s1] != 0) t1 = 1.0f;
        rs1 = 0.125f / t1;
    }

    uint32_t qh[4][4], ql[4][4];
    #pragma unroll
    for (int kc = 0; kc < 4; kc++) {
        int d0 = kc * 16 + l4 * 2;
        const float2 a00 = *(const float2*)(Qp + (size_t)(q0 + row0) * ND + d0);
        const float2 a10 = *(const float2*)(Qp + (size_t)(q0 + row1) * ND + d0);
        const float2 a01 = *(const float2*)(Qp + (size_t)(q0 + row0) * ND + d0 + 8);
        const float2 a11 = *(const float2*)(Qp + (size_t)(q0 + row1) * ND + d0 + 8);
        float hx, lx, hy, ly;
        split_hi_lo(a00.x * rs0, hx, lx); split_hi_lo(a00.y * rs0, hy, ly);
        qh[kc][0] = pack_bf16x2(hx, hy);  ql[kc][0] = pack_bf16x2(lx, ly);
        split_hi_lo(a10.x * rs1, hx, lx); split_hi_lo(a10.y * rs1, hy, ly);
        qh[kc][1] = pack_bf16x2(hx, hy);  ql[kc][1] = pack_bf16x2(lx, ly);
        split_hi_lo(a01.x * rs0, hx, lx); split_hi_lo(a01.y * rs0, hy, ly);
        qh[kc][2] = pack_bf16x2(hx, hy);  ql[kc][2] = pack_bf16x2(lx, ly);
        split_hi_lo(a11.x * rs1, hx, lx); split_hi_lo(a11.y * rs1, hy, ly);
        qh[kc][3] = pack_bf16x2(hx, hy);  ql[kc][3] = pack_bf16x2(lx, ly);
    }

    float oacc[8][4];
    #pragma unroll
    for (int j = 0; j < 8; j++)
        #pragma unroll
        for (int c = 0; c < 4; c++) oacc[j][c] = 0.f;
    float lsum0 = 0.f, lsum1 = 0.f;

    for (int kt = 0; kt < NS / 64; kt++) {
        const int kk0 = kt * 64;

        // ---- straight bf16 tile copies (no conversion math) ----
        #pragma unroll
        for (int it = 0; it < 2; it++) {
            int idx = tid + it * 256;
            int r = idx >> 3, c8 = (idx & 7) * 8;
            *(uint4*)(Khs + r * KPAD + c8) = *(const uint4*)(Khp + (size_t)(kk0 + r) * ND + c8);
            *(uint4*)(Kls + r * KPAD + c8) = *(const uint4*)(Klp + (size_t)(kk0 + r) * ND + c8);
            *(uint4*)(Vhs + r * KPAD + c8) = *(const uint4*)(Vhp + (size_t)r * NS + kk0 + c8);
            *(uint4*)(Vls + r * KPAD + c8) = *(const uint4*)(Vlp + (size_t)r * NS + kk0 + c8);
        }
        if (tid < 64) pens[tid] = (mask[b * NS + kk0 + tid] != 0) ? -1e30f : 0.f;
        __syncthreads();

        float sacc[8][4];
        #pragma unroll
        for (int j = 0; j < 8; j++)
            #pragma unroll
            for (int c = 0; c < 4; c++) sacc[j][c] = 0.f;

        #pragma unroll
        for (int kc = 0; kc < 4; kc++) {
            #pragma unroll
            for (int j = 0; j < 8; j++) {
                int boff = (j * 8 + g) * KPAD + kc * 16 + l4 * 2;
                uint32_t bh0 = *(const uint32_t*)(Khs + boff);
                uint32_t bh1 = *(const uint32_t*)(Khs + boff + 8);
                uint32_t bl0 = *(const uint32_t*)(Kls + boff);
                uint32_t bl1 = *(const uint32_t*)(Kls + boff + 8);
                mma16816(sacc[j], qh[kc], bh0, bh1);
                mma16816(sacc[j], ql[kc], bh0, bh1);
                mma16816(sacc[j], qh[kc], bl0, bl1);
            }
        }

        uint32_t ps[8][4];
        #pragma unroll
        for (int j = 0; j < 8; j++) {
            float2 pen2 = *(const float2*)(pens + j * 8 + l4 * 2);
            float p0 = __expf(sacc[j][0] + pen2.x);
            float p1 = __expf(sacc[j][1] + pen2.y);
            float p2 = __expf(sacc[j][2] + pen2.x);
            float p3 = __expf(sacc[j][3] + pen2.y);
            lsum0 += p0 + p1;
            lsum1 += p2 + p3;
            float h0,l0,h1,l1,h2,l2,h3,l3;
            split_hi_lo(p0,h0,l0); split_hi_lo(p1,h1,l1);
            split_hi_lo(p2,h2,l2); split_hi_lo(p3,h3,l3);
            ps[j][0] = pack_bf16x2(h0, h1);
            ps[j][1] = pack_bf16x2(h2, h3);
            ps[j][2] = pack_bf16x2(l0, l1);
            ps[j][3] = pack_bf16x2(l2, l3);
        }

        #pragma unroll
        for (int kc = 0; kc < 4; kc++) {
            uint32_t Ah[4] = { ps[2*kc][0], ps[2*kc][1], ps[2*kc+1][0], ps[2*kc+1][1] };
            uint32_t Al[4] = { ps[2*kc][2], ps[2*kc][3], ps[2*kc+1][2], ps[2*kc+1][3] };
            #pragma unroll
            for (int j = 0; j < 8; j++) {
                int boff = (j * 8 + g) * KPAD + kc * 16 + l4 * 2;
                uint32_t bh0 = *(const uint32_t*)(Vhs + boff);
                uint32_t bh1 = *(const uint32_t*)(Vhs + boff + 8);
                uint32_t bl0 = *(const uint32_t*)(Vls + boff);
                uint32_t bl1 = *(const uint32_t*)(Vls + boff + 8);
                mma16816(oacc[j], Ah, bh0, bh1);
                mma16816(oacc[j], Al, bh0, bh1);
                mma16816(oacc[j], Ah, bl0, bl1);
            }
        }
        __syncthreads();
    }

    lsum0 += __shfl_xor_sync(0xffffffffu, lsum0, 1);
    lsum0 += __shfl_xor_sync(0xffffffffu, lsum0, 2);
    lsum1 += __shfl_xor_sync(0xffffffffu, lsum1, 1);
    lsum1 += __shfl_xor_sync(0xffffffffu, lsum1, 2);
    float inv0 = (lsum0 > 0.f) ? 1.f / lsum0 : 0.f;
    float inv1 = (lsum1 > 0.f) ? 1.f / lsum1 : 0.f;

    // ---- write AO pre-split hi/lo bf16 ----
    {
        size_t o0 = base + (size_t)(q0 + row0) * ND;
        size_t o1 = base + (size_t)(q0 + row1) * ND;
        #pragma unroll
        for (int j = 0; j < 8; j++) {
            int d = j * 8 + l4 * 2;
            float h0,l0,h1,l1;
            split_hi_lo(oacc[j][0] * inv0, h0, l0);
            split_hi_lo(oacc[j][1] * inv0, h1, l1);
            *(uint32_t*)(g_AOh + o0 + d) = pack_bf16x2(h0, h1);
            *(uint32_t*)(g_AOl + o0 + d) = pack_bf16x2(l0, l1);
            split_hi_lo(oacc[j][2] * inv1, h0, l0);
            split_hi_lo(oacc[j][3] * inv1, h1, l1);
            *(uint32_t*)(g_AOh + o1 + d) = pack_bf16x2(h0, h1);
            *(uint32_t*)(g_AOl + o1 + d) = pack_bf16x2(l0, l1);
        }
    }
}

// ---------------------------------------------------------------------------
// Kernel 3: output projection via mma.sync (pre-split A and W) + mask zero.
// ---------------------------------------------------------------------------
#define OP_WTH_OFF (2*128*KPAD)
#define OP_WTL_OFF (2*128*KPAD + 64*KPAD)
#define OP_SMEM_BF16 (2*128*KPAD + 2*64*KPAD)   // 55296 B

__global__ __launch_bounds__(256, 2) void out_proj_mma(
    const float* __restrict__ bo,
    const int* __restrict__ mask,
    float* __restrict__ out)
{
    extern __shared__ __nv_bfloat16 smb[];
    __nv_bfloat16* Xh  = smb + XH_OFF;
    __nv_bfloat16* Xl  = smb + XL_OFF;
    __nv_bfloat16* Wth = smb + OP_WTH_OFF;
    __nv_bfloat16* Wtl = smb + OP_WTL_OFF;

    const int tid  = threadIdx.x;
    const int w    = tid >> 5;
    const int lane = tid & 31;
    const int g    = lane >> 2;
    const int l4   = lane & 3;
    const int m0   = blockIdx.x * 128;
    const int n0   = blockIdx.y * 64;

    float acc[8][4];
    #pragma unroll
    for (int j = 0; j < 8; j++)
        #pragma unroll
        for (int c = 0; c < 4; c++) acc[j][c] = 0.f;

    for (int k0 = 0; k0 < NE; k0 += 64) {
        const int hh = k0 >> 6;
        #pragma unroll
        for (int it = 0; it < 4; it++) {
            int idx = tid + it * 256;
            int r = idx >> 3, c8 = (idx & 7) * 8;
            int m = m0 + r;
            int bb_ = m >> 11, s = m & (NS - 1);
            size_t o = (((size_t)bb_ * NH + hh) * NS + s) * ND + c8;
            *(uint4*)(Xh + r * KPAD + c8) = *(const uint4*)(g_AOh + o);
            *(uint4*)(Xl + r * KPAD + c8) = *(const uint4*)(g_AOl + o);
        }
        #pragma unroll
        for (int it = 0; it < 2; it++) {
            int idx = tid + it * 256;
            int r = idx >> 3, c8 = (idx & 7) * 8;
            size_t o = (size_t)3 * NE * NE + (size_t)(n0 + r) * NE + k0 + c8;
            *(uint4*)(Wth + r * KPAD + c8) = *(const uint4*)(g_Wth + o);
            *(uint4*)(Wtl + r * KPAD + c8) = *(const uint4*)(g_Wtl + o);
        }
        __syncthreads();

        #pragma unroll
        for (int kc = 0; kc < 4; kc++) {
            int aoff = (w * 16 + g) * KPAD + kc * 16 + l4 * 2;
            uint32_t ah[4], al[4];
            ah[0] = *(const uint32_t*)(Xh + aoff);
            ah[1] = *(const uint32_t*)(Xh + aoff + 8 * KPAD);
            ah[2] = *(const uint32_t*)(Xh + aoff + 8);
            ah[3] = *(const uint32_t*)(Xh + aoff + 8 * KPAD + 8);
            al[0] = *(const uint32_t*)(Xl + aoff);
            al[1] = *(const uint32_t*)(Xl + aoff + 8 * KPAD);
            al[2] = *(const uint32_t*)(Xl + aoff + 8);
            al[3] = *(const uint32_t*)(Xl + aoff + 8 * KPAD + 8);
            #pragma unroll
            for (int j = 0; j < 8; j++) {
                int boff = (j * 8 + g) * KPAD + kc * 16 + l4 * 2;
                uint32_t bh0 = *(const uint32_t*)(Wth + boff);
                uint32_t bh1 = *(const uint32_t*)(Wth + boff + 8);
                uint32_t bl0 = *(const uint32_t*)(Wtl + boff);
                uint32_t bl1 = *(const uint32_t*)(Wtl + boff + 8);
                mma16816(acc[j], ah, bh0, bh1);
                mma16816(acc[j], al, bh0, bh1);
                mma16816(acc[j], ah, bl0, bl1);
            }
        }
        __syncthreads();
    }

    const int row0 = m0 + w * 16 + g;
    const int row1 = row0 + 8;
    const int b0_ = row0 >> 11, s0 = row0 & (NS - 1);
    const int b1_ = row1 >> 11, s1 = row1 & (NS - 1);
    const bool mq0 = mask[b0_ * NS + s0] != 0;
    const bool mq1 = mask[b1_ * NS + s1] != 0;
    #pragma unroll
    for (int j = 0; j < 8; j++) {
        int d = j * 8 + 2 * l4;
        float bx = bo[n0 + d], by = bo[n0 + d + 1];
        float2 v0 = { mq0 ? 0.f : acc[j][0] + bx, mq0 ? 0.f : acc[j][1] + by };
        float2 v1 = { mq1 ? 0.f : acc[j][2] + bx, mq1 ? 0.f : acc[j][3] + by };
        *(float2*)(out + (size_t)row0 * NE + n0 + d) = v0;
        *(float2*)(out + (size_t)row1 * NE + n0 + d) = v1;
    }
}

// ---------------------------------------------------------------------------
extern "C" void kernel_launch(void* const* d_in, const int* in_sizes, int n_in,
                              void* d_out, int out_size)
{
    const float* his     = (const float*)d_in[0];
    const int*   mask    = (const int*)d_in[1];
    const float* explore = (const float*)d_in[2];
    const float* exploit = (const float*)d_in[3];
    const float* Wq = (const float*)d_in[4];
    const float* bq = (const float*)d_in[5];
    const float* Wk = (const float*)d_in[6];
    const float* bk = (const float*)d_in[7];
    const float* Wv = (const float*)d_in[8];
    const float* bv = (const float*)d_in[9];
    const float* Wo = (const float*)d_in[10];
    const float* bo = (const float*)d_in[11];
    float* out = (float*)d_out;

    const int qkv_smem = QKV_SMEM_BF16 * 2;     // 92160 B
    const int op_smem  = OP_SMEM_BF16 * 2;      // 55296 B
    static bool attr_done = false;
    if (!attr_done) {
        cudaFuncSetAttribute(qkv_mma, cudaFuncAttributeMaxDynamicSharedMemorySize, qkv_smem);
        cudaFuncSetAttribute(out_proj_mma, cudaFuncAttributeMaxDynamicSharedMemorySize, op_smem);
        attr_done = true;
    }

    prep_w<<<dim3(4, 4, 4), 256>>>(Wq, Wk, Wv, Wo);
    qkv_mma<<<dim3(8192 / 128, NH), 256, qkv_smem>>>(his, bq, bk, bv);
    attn_mma<<<dim3(NS / 128, NH, NB), 256>>>(mask, explore, exploit);
    out_proj_mma<<<dim3(8192 / 128, 4), 256, op_smem>>>(bo, mask, out);
}

// round 8
// speedup vs baseline: 6.1999x; 1.7838x over previous
#include <cuda_runtime.h>
#include <cuda_bf16.h>
#include <cuda_fp16.h>
#include <cstdint>
#include <math.h>

#define NB 4
#define NS 2048
#define NE 256
#define NH 4
#define ND 64

// Scratch (allocation-free).
__device__ float g_Q[NB*NH*NS*ND];                                  // [b,h,s,d] fp32
__device__ __align__(16) __half g_Kf[NB*NH*NS*ND];                  // [b,h,s,d] fp16
__device__ __align__(16) __half g_Vf[NB*NH*ND*NS];                  // [b,h,d,s] fp16
__device__ __align__(16) __nv_bfloat16 g_AOh[NB*NH*NS*ND];          // [b,h,s,d]
__device__ __align__(16) __nv_bfloat16 g_AOl[NB*NH*NS*ND];
__device__ __align__(16) __nv_bfloat16 g_Wth[4*NE*NE];              // [mat][n][k]
__device__ __align__(16) __nv_bfloat16 g_Wtl[4*NE*NE];

__device__ __forceinline__ uint32_t pack_bf16x2(float a, float b) {
    __nv_bfloat162 t = __floats2bfloat162_rn(a, b);   // a -> low half
    return *(uint32_t*)&t;
}
__device__ __forceinline__ uint32_t pack_h2(float a, float b) {
    __half2 t = __floats2half2_rn(a, b);              // a -> low half
    return *(uint32_t*)&t;
}
__device__ __forceinline__ void split_hi_lo(float x, float& hi, float& lo) {
    __nv_bfloat16 h = __float2bfloat16_rn(x);
    hi = __bfloat162float(h);
    lo = x - hi;
}

// mma.sync m16n8k16 row.col (sm_80+ PTX, no arch suffix)
__device__ __forceinline__ void mma16816(float c[4], const uint32_t a[4],
                                         uint32_t b0, uint32_t b1) {
    asm volatile(
        "mma.sync.aligned.m16n8k16.row.col.f32.bf16.bf16.f32 "
        "{%0,%1,%2,%3}, {%4,%5,%6,%7}, {%8,%9}, {%0,%1,%2,%3};"
        : "+f"(c[0]), "+f"(c[1]), "+f"(c[2]), "+f"(c[3])
        : "r"(a[0]), "r"(a[1]), "r"(a[2]), "r"(a[3]), "r"(b0), "r"(b1));
}
__device__ __forceinline__ void mma16816h(float c[4], const uint32_t a[4],
                                          uint32_t b0, uint32_t b1) {
    asm volatile(
        "mma.sync.aligned.m16n8k16.row.col.f32.f16.f16.f32 "
        "{%0,%1,%2,%3}, {%4,%5,%6,%7}, {%8,%9}, {%0,%1,%2,%3};"
        : "+f"(c[0]), "+f"(c[1]), "+f"(c[2]), "+f"(c[3])
        : "r"(a[0]), "r"(a[1]), "r"(a[2]), "r"(a[3]), "r"(b0), "r"(b1));
}

#define KPAD 72   // 16-bit row stride; word stride 36 -> conflict-free frag LDS

__device__ __forceinline__ void store_split4(__nv_bfloat16* bh, __nv_bfloat16* bl,
                                             int off, float4 v) {
    float h0,l0,h1,l1,h2,l2,h3,l3;
    split_hi_lo(v.x,h0,l0); split_hi_lo(v.y,h1,l1);
    split_hi_lo(v.z,h2,l2); split_hi_lo(v.w,h3,l3);
    *(uint32_t*)(bh + off)     = pack_bf16x2(h0, h1);
    *(uint32_t*)(bh + off + 2) = pack_bf16x2(h2, h3);
    *(uint32_t*)(bl + off)     = pack_bf16x2(l0, l1);
    *(uint32_t*)(bl + off + 2) = pack_bf16x2(l2, l3);
}

// ---------------------------------------------------------------------------
// Kernel 0: pre-split weights -> transposed hi/lo bf16 [mat][n][k].
// ---------------------------------------------------------------------------
__global__ __launch_bounds__(256) void prep_w(
    const float* __restrict__ Wq, const float* __restrict__ Wk,
    const float* __restrict__ Wv, const float* __restrict__ Wo)
{
    __shared__ float t[64][65];
    const float* Ws[4] = { Wq, Wk, Wv, Wo };
    const int mt = blockIdx.z;
    const int k0 = blockIdx.x * 64, n0 = blockIdx.y * 64;
    const int tid = threadIdx.x;
    const float* W = Ws[mt];

    #pragma unroll
    for (int it = 0; it < 16; it++) {
        int idx = tid + it * 256;
        int kk = idx >> 6, nn = idx & 63;
        t[kk][nn] = W[(k0 + kk) * NE + n0 + nn];
    }
    __syncthreads();

    #pragma unroll
    for (int it = 0; it < 2; it++) {
        int idx = tid + it * 256;
        int n = idx >> 3, c8 = (idx & 7) * 8;
        uint32_t hw[4], lw[4];
        #pragma unroll
        for (int p = 0; p < 4; p++) {
            float hi0, lo0, hi1, lo1;
            split_hi_lo(t[c8 + 2*p][n],     hi0, lo0);
            split_hi_lo(t[c8 + 2*p + 1][n], hi1, lo1);
            hw[p] = pack_bf16x2(hi0, hi1);
            lw[p] = pack_bf16x2(lo0, lo1);
        }
        size_t o = (size_t)mt * NE * NE + (size_t)(n0 + n) * NE + k0 + c8;
        *(uint4*)(g_Wth + o) = *(uint4*)hw;
        *(uint4*)(g_Wtl + o) = *(uint4*)lw;
    }
}

// ---------------------------------------------------------------------------
// Kernel 1: fused QKV projection via mma.sync split-bf16 (high precision).
// Writes: g_Q fp32 [b,h,s,d]; g_Kf fp16 [b,h,s,d]; g_Vf fp16 [b,h,d,s].
// ---------------------------------------------------------------------------
#define XH_OFF   0
#define XL_OFF   (128*KPAD)
#define WTH_OFF  (2*128*KPAD)
#define WTL_OFF  (2*128*KPAD + 3*64*KPAD)
#define QKV_SMEM_BF16 (2*128*KPAD + 6*64*KPAD)   // 92160 B

__global__ __launch_bounds__(256, 1) void qkv_mma(
    const float* __restrict__ X,
    const float* __restrict__ bq, const float* __restrict__ bk,
    const float* __restrict__ bv)
{
    extern __shared__ __nv_bfloat16 smb[];
    __nv_bfloat16* Xh = smb + XH_OFF;
    __nv_bfloat16* Xl = smb + XL_OFF;

    const int tid  = threadIdx.x;
    const int w    = tid >> 5;
    const int lane = tid & 31;
    const int g    = lane >> 2;
    const int l4   = lane & 3;
    const int m0   = blockIdx.x * 128;
    const int h    = blockIdx.y;
    const int n0   = h * 64;

    float acc[3][8][4];
    #pragma unroll
    for (int mt = 0; mt < 3; mt++)
        #pragma unroll
        for (int j = 0; j < 8; j++)
            #pragma unroll
            for (int c = 0; c < 4; c++) acc[mt][j][c] = 0.f;

    for (int k0 = 0; k0 < NE; k0 += 64) {
        #pragma unroll
        for (int it = 0; it < 8; it++) {
            int idx = tid + it * 256;
            int r = idx >> 4, c = (idx & 15) * 4;
            float4 v = *(const float4*)(X + (size_t)(m0 + r) * NE + k0 + c);
            store_split4(Xh, Xl, r * KPAD + c, v);
        }
        #pragma unroll
        for (int mt = 0; mt < 3; mt++) {
            __nv_bfloat16* Wth = smb + WTH_OFF + mt * 64 * KPAD;
            __nv_bfloat16* Wtl = smb + WTL_OFF + mt * 64 * KPAD;
            const size_t wb = (size_t)mt * NE * NE;
            #pragma unroll
            for (int it = 0; it < 2; it++) {
                int idx = tid + it * 256;
                int r = idx >> 3, c8 = (idx & 7) * 8;
                size_t o = wb + (size_t)(n0 + r) * NE + k0 + c8;
                *(uint4*)(Wth + r * KPAD + c8) = *(const uint4*)(g_Wth + o);
                *(uint4*)(Wtl + r * KPAD + c8) = *(const uint4*)(g_Wtl + o);
            }
        }
        __syncthreads();

        #pragma unroll
        for (int kc = 0; kc < 4; kc++) {
            int aoff = (w * 16 + g) * KPAD + kc * 16 + l4 * 2;
            uint32_t ah[4], al[4];
            ah[0] = *(const uint32_t*)(Xh + aoff);
            ah[1] = *(const uint32_t*)(Xh + aoff + 8 * KPAD);
            ah[2] = *(const uint32_t*)(Xh + aoff + 8);
            ah[3] = *(const uint32_t*)(Xh + aoff + 8 * KPAD + 8);
            al[0] = *(const uint32_t*)(Xl + aoff);
            al[1] = *(const uint32_t*)(Xl + aoff + 8 * KPAD);
            al[2] = *(const uint32_t*)(Xl + aoff + 8);
            al[3] = *(const uint32_t*)(Xl + aoff + 8 * KPAD + 8);

            #pragma unroll
            for (int mt = 0; mt < 3; mt++) {
                const __nv_bfloat16* Wth = smb + WTH_OFF + mt * 64 * KPAD;
                const __nv_bfloat16* Wtl = smb + WTL_OFF + mt * 64 * KPAD;
                #pragma unroll
                for (int j = 0; j < 8; j++) {
                    int boff = (j * 8 + g) * KPAD + kc * 16 + l4 * 2;
                    uint32_t bh0 = *(const uint32_t*)(Wth + boff);
                    uint32_t bh1 = *(const uint32_t*)(Wth + boff + 8);
                    uint32_t bl0 = *(const uint32_t*)(Wtl + boff);
                    uint32_t bl1 = *(const uint32_t*)(Wtl + boff + 8);
                    mma16816(acc[mt][j], ah, bh0, bh1);
                    mma16816(acc[mt][j], al, bh0, bh1);
                    mma16816(acc[mt][j], ah, bl0, bl1);
                }
            }
        }
        __syncthreads();
    }

    const int row0 = m0 + w * 16 + g;
    const int row1 = row0 + 8;
    const int b0_ = row0 >> 11, s0 = row0 & (NS - 1);
    const int b1_ = row1 >> 11, s1 = row1 & (NS - 1);

    // ---- Q: fp32 scatter ----
    {
        float* O0 = g_Q + (((size_t)b0_ * NH + h) * NS + s0) * ND;
        float* O1 = g_Q + (((size_t)b1_ * NH + h) * NS + s1) * ND;
        #pragma unroll
        for (int j = 0; j < 8; j++) {
            int d = j * 8 + 2 * l4;
            float bx = bq[n0 + d], by = bq[n0 + d + 1];
            float2 v0 = { acc[0][j][0] + bx, acc[0][j][1] + by };
            float2 v1 = { acc[0][j][2] + bx, acc[0][j][3] + by };
            *(float2*)(O0 + d) = v0;
            *(float2*)(O1 + d) = v1;
        }
    }
    // ---- K: fp16 scatter ----
    {
        size_t o0 = (((size_t)b0_ * NH + h) * NS + s0) * ND;
        size_t o1 = (((size_t)b1_ * NH + h) * NS + s1) * ND;
        #pragma unroll
        for (int j = 0; j < 8; j++) {
            int d = j * 8 + 2 * l4;
            float bx = bk[n0 + d], by = bk[n0 + d + 1];
            *(uint32_t*)(g_Kf + o0 + d) = pack_h2(acc[1][j][0] + bx, acc[1][j][1] + by);
            *(uint32_t*)(g_Kf + o1 + d) = pack_h2(acc[1][j][2] + bx, acc[1][j][3] + by);
        }
    }
    // ---- V: stage [d][s] fp32 in smem, write fp16 [b,h,d,s] ----
    #define VPAD 132
    __syncthreads();
    float* Vb = (float*)smb;   // 64*132*4 = 33792 B, overlays tiles
    #pragma unroll
    for (int j = 0; j < 8; j++) {
        int d = j * 8 + 2 * l4;
        float bx = bv[n0 + d], by = bv[n0 + d + 1];
        int sr0 = w * 16 + g, sr1 = sr0 + 8;
        Vb[(d    ) * VPAD + sr0] = acc[2][j][0] + bx;
        Vb[(d + 1) * VPAD + sr0] = acc[2][j][1] + by;
        Vb[(d    ) * VPAD + sr1] = acc[2][j][2] + bx;
        Vb[(d + 1) * VPAD + sr1] = acc[2][j][3] + by;
    }
    __syncthreads();
    #pragma unroll
    for (int it = 0; it < 8; it++) {
        int idx = tid + it * 256;
        int d = idx >> 5, c4 = (idx & 31) * 4;
        int m = m0 + c4;
        int bb_ = m >> 11, s = m & (NS - 1);
        size_t o = (((size_t)bb_ * NH + h) * ND + d) * NS + s;
        uint32_t hw[2] = { pack_h2(Vb[d * VPAD + c4],     Vb[d * VPAD + c4 + 1]),
                           pack_h2(Vb[d * VPAD + c4 + 2], Vb[d * VPAD + c4 + 3]) };
        *(uint2*)(g_Vf + o) = *(uint2*)hw;
    }
}

// ---------------------------------------------------------------------------
// Kernel 2: flash attention, single-term fp16 mma (errors wash in softmax avg).
// Fixed shift -11 folded into pens to keep exp(s) in fp16 range.
// ---------------------------------------------------------------------------
__global__ __launch_bounds__(256, 2) void attn_mma(
    const int* __restrict__ mask,
    const float* __restrict__ explore,
    const float* __restrict__ exploit)
{
    __shared__ __align__(16) __half Ks[64*KPAD], Vs[64*KPAD];
    __shared__ float pens[64];

    const int tid  = threadIdx.x;
    const int w    = tid >> 5;
    const int lane = tid & 31;
    const int g    = lane >> 2;
    const int l4   = lane & 3;
    const int q0   = blockIdx.x * 128;
    const int h    = blockIdx.y, b = blockIdx.z;

    const size_t base = ((size_t)b * NH + h) * NS * ND;
    const float* Qp = g_Q + base;
    const __half* Kp = g_Kf + base;
    const __half* Vp = g_Vf + base;   // [d][s]

    const int row0 = w * 16 + g;
    const int row1 = row0 + 8;
    float rs0, rs1;
    {
        int s0 = q0 + row0, s1 = q0 + row1;
        float t0 = 1.0f + 0.5f * explore[b * NS + s0] - 0.5f * exploit[b * NS + s0];
        t0 = fminf(fmaxf(t0, 0.5f), 2.0f);
        if (mask[b * NS + s0] != 0) t0 = 1.0f;
        rs0 = 0.125f / t0;
        float t1 = 1.0f + 0.5f * explore[b * NS + s1] - 0.5f * exploit[b * NS + s1];
        t1 = fminf(fmaxf(t1, 0.5f), 2.0f);
        if (mask[b * NS + s1] != 0) t1 = 1.0f;
        rs1 = 0.125f / t1;
    }

    // Q fragments: fp16 single
    uint32_t qf[4][4];
    #pragma unroll
    for (int kc = 0; kc < 4; kc++) {
        int d0 = kc * 16 + l4 * 2;
        const float2 a00 = *(const float2*)(Qp + (size_t)(q0 + row0) * ND + d0);
        const float2 a10 = *(const float2*)(Qp + (size_t)(q0 + row1) * ND + d0);
        const float2 a01 = *(const float2*)(Qp + (size_t)(q0 + row0) * ND + d0 + 8);
        const float2 a11 = *(const float2*)(Qp + (size_t)(q0 + row1) * ND + d0 + 8);
        qf[kc][0] = pack_h2(a00.x * rs0, a00.y * rs0);
        qf[kc][1] = pack_h2(a10.x * rs1, a10.y * rs1);
        qf[kc][2] = pack_h2(a01.x * rs0, a01.y * rs0);
        qf[kc][3] = pack_h2(a11.x * rs1, a11.y * rs1);
    }

    float oacc[8][4];
    #pragma unroll
    for (int j = 0; j < 8; j++)
        #pragma unroll
        for (int c = 0; c < 4; c++) oacc[j][c] = 0.f;
    float lsum0 = 0.f, lsum1 = 0.f;

    for (int kt = 0; kt < NS / 64; kt++) {
        const int kk0 = kt * 64;

        // ---- straight fp16 tile copies ----
        #pragma unroll
        for (int it = 0; it < 2; it++) {
            int idx = tid + it * 256;
            int r = idx >> 3, c8 = (idx & 7) * 8;
            *(uint4*)(Ks + r * KPAD + c8) = *(const uint4*)(Kp + (size_t)(kk0 + r) * ND + c8);
            *(uint4*)(Vs + r * KPAD + c8) = *(const uint4*)(Vp + (size_t)r * NS + kk0 + c8);
        }
        // pens: mask penalty + fixed softmax shift (-11, cancels in normalize)
        if (tid < 64) pens[tid] = (mask[b * NS + kk0 + tid] != 0) ? -1e30f : -11.0f;
        __syncthreads();

        float sacc[8][4];
        #pragma unroll
        for (int j = 0; j < 8; j++)
            #pragma unroll
            for (int c = 0; c < 4; c++) sacc[j][c] = 0.f;

        #pragma unroll
        for (int kc = 0; kc < 4; kc++) {
            #pragma unroll
            for (int j = 0; j < 8; j++) {
                int boff = (j * 8 + g) * KPAD + kc * 16 + l4 * 2;
                uint32_t b0 = *(const uint32_t*)(Ks + boff);
                uint32_t b1 = *(const uint32_t*)(Ks + boff + 8);
                mma16816h(sacc[j], qf[kc], b0, b1);
            }
        }

        uint32_t ps[8][2];
        #pragma unroll
        for (int j = 0; j < 8; j++) {
            float2 pen2 = *(const float2*)(pens + j * 8 + l4 * 2);
            float p0 = __expf(sacc[j][0] + pen2.x);
            float p1 = __expf(sacc[j][1] + pen2.y);
            float p2 = __expf(sacc[j][2] + pen2.x);
            float p3 = __expf(sacc[j][3] + pen2.y);
            lsum0 += p0 + p1;
            lsum1 += p2 + p3;
            ps[j][0] = pack_h2(p0, p1);
            ps[j][1] = pack_h2(p2, p3);
        }

        #pragma unroll
        for (int kc = 0; kc < 4; kc++) {
            uint32_t Af[4] = { ps[2*kc][0], ps[2*kc][1], ps[2*kc+1][0], ps[2*kc+1][1] };
            #pragma unroll
            for (int j = 0; j < 8; j++) {
                int boff = (j * 8 + g) * KPAD + kc * 16 + l4 * 2;
                uint32_t b0 = *(const uint32_t*)(Vs + boff);
                uint32_t b1 = *(const uint32_t*)(Vs + boff + 8);
                mma16816h(oacc[j], Af, b0, b1);
            }
        }
        __syncthreads();
    }

    lsum0 += __shfl_xor_sync(0xffffffffu, lsum0, 1);
    lsum0 += __shfl_xor_sync(0xffffffffu, lsum0, 2);
    lsum1 += __shfl_xor_sync(0xffffffffu, lsum1, 1);
    lsum1 += __shfl_xor_sync(0xffffffffu, lsum1, 2);
    float inv0 = (lsum0 > 0.f) ? 1.f / lsum0 : 0.f;
    float inv1 = (lsum1 > 0.f) ? 1.f / lsum1 : 0.f;

    // ---- write AO pre-split hi/lo bf16 ----
    {
        size_t o0 = base + (size_t)(q0 + row0) * ND;
        size_t o1 = base + (size_t)(q0 + row1) * ND;
        #pragma unroll
        for (int j = 0; j < 8; j++) {
            int d = j * 8 + l4 * 2;
            float h0,l0,h1,l1;
            split_hi_lo(oacc[j][0] * inv0, h0, l0);
            split_hi_lo(oacc[j][1] * inv0, h1, l1);
            *(uint32_t*)(g_AOh + o0 + d) = pack_bf16x2(h0, h1);
            *(uint32_t*)(g_AOl + o0 + d) = pack_bf16x2(l0, l1);
            split_hi_lo(oacc[j][2] * inv1, h0, l0);
            split_hi_lo(oacc[j][3] * inv1, h1, l1);
            *(uint32_t*)(g_AOh + o1 + d) = pack_bf16x2(h0, h1);
            *(uint32_t*)(g_AOl + o1 + d) = pack_bf16x2(l0, l1);
        }
    }
}

// ---------------------------------------------------------------------------
// Kernel 3: output projection via mma.sync (pre-split A and W) + mask zero.
// ---------------------------------------------------------------------------
#define OP_WTH_OFF (2*128*KPAD)
#define OP_WTL_OFF (2*128*KPAD + 64*KPAD)
#define OP_SMEM_BF16 (2*128*KPAD + 2*64*KPAD)   // 55296 B

__global__ __launch_bounds__(256, 2) void out_proj_mma(
    const float* __restrict__ bo,
    const int* __restrict__ mask,
    float* __restrict__ out)
{
    extern __shared__ __nv_bfloat16 smb[];
    __nv_bfloat16* Xh  = smb + XH_OFF;
    __nv_bfloat16* Xl  = smb + XL_OFF;
    __nv_bfloat16* Wth = smb + OP_WTH_OFF;
    __nv_bfloat16* Wtl = smb + OP_WTL_OFF;

    const int tid  = threadIdx.x;
    const int w    = tid >> 5;
    const int lane = tid & 31;
    const int g    = lane >> 2;
    const int l4   = lane & 3;
    const int m0   = blockIdx.x * 128;
    const int n0   = blockIdx.y * 64;

    float acc[8][4];
    #pragma unroll
    for (int j = 0; j < 8; j++)
        #pragma unroll
        for (int c = 0; c < 4; c++) acc[j][c] = 0.f;

    for (int k0 = 0; k0 < NE; k0 += 64) {
        const int hh = k0 >> 6;
        #pragma unroll
        for (int it = 0; it < 4; it++) {
            int idx = tid + it * 256;
            int r = idx >> 3, c8 = (idx & 7) * 8;
            int m = m0 + r;
            int bb_ = m >> 11, s = m & (NS - 1);
            size_t o = (((size_t)bb_ * NH + hh) * NS + s) * ND + c8;
            *(uint4*)(Xh + r * KPAD + c8) = *(const uint4*)(g_AOh + o);
            *(uint4*)(Xl + r * KPAD + c8) = *(const uint4*)(g_AOl + o);
        }
        #pragma unroll
        for (int it = 0; it < 2; it++) {
            int idx = tid + it * 256;
            int r = idx >> 3, c8 = (idx & 7) * 8;
            size_t o = (size_t)3 * NE * NE + (size_t)(n0 + r) * NE + k0 + c8;
            *(uint4*)(Wth + r * KPAD + c8) = *(const uint4*)(g_Wth + o);
            *(uint4*)(Wtl + r * KPAD + c8) = *(const uint4*)(g_Wtl + o);
        }
        __syncthreads();

        #pragma unroll
        for (int kc = 0; kc < 4; kc++) {
            int aoff = (w * 16 + g) * KPAD + kc * 16 + l4 * 2;
            uint32_t ah[4], al[4];
            ah[0] = *(const uint32_t*)(Xh + aoff);
            ah[1] = *(const uint32_t*)(Xh + aoff + 8 * KPAD);
            ah[2] = *(const uint32_t*)(Xh + aoff + 8);
            ah[3] = *(const uint32_t*)(Xh + aoff + 8 * KPAD + 8);
            al[0] = *(const uint32_t*)(Xl + aoff);
            al[1] = *(const uint32_t*)(Xl + aoff + 8 * KPAD);
            al[2] = *(const uint32_t*)(Xl + aoff + 8);
            al[3] = *(const uint32_t*)(Xl + aoff + 8 * KPAD + 8);
            #pragma unroll
            for (int j = 0; j < 8; j++) {
                int boff = (j * 8 + g) * KPAD + kc * 16 + l4 * 2;
                uint32_t bh0 = *(const uint32_t*)(Wth + boff);
                uint32_t bh1 = *(const uint32_t*)(Wth + boff + 8);
                uint32_t bl0 = *(const uint32_t*)(Wtl + boff);
                uint32_t bl1 = *(const uint32_t*)(Wtl + boff + 8);
                mma16816(acc[j], ah, bh0, bh1);
                mma16816(acc[j], al, bh0, bh1);
                mma16816(acc[j], ah, bl0, bl1);
            }
        }
        __syncthreads();
    }

    const int row0 = m0 + w * 16 + g;
    const int row1 = row0 + 8;
    const int b0_ = row0 >> 11, s0 = row0 & (NS - 1);
    const int b1_ = row1 >> 11, s1 = row1 & (NS - 1);
    const bool mq0 = mask[b0_ * NS + s0] != 0;
    const bool mq1 = mask[b1_ * NS + s1] != 0;
    #pragma unroll
    for (int j = 0; j < 8; j++) {
        int d = j * 8 + 2 * l4;
        float bx = bo[n0 + d], by = bo[n0 + d + 1];
        float2 v0 = { mq0 ? 0.f : acc[j][0] + bx, mq0 ? 0.f : acc[j][1] + by };
        float2 v1 = { mq1 ? 0.f : acc[j][2] + bx, mq1 ? 0.f : acc[j][3] + by };
        *(float2*)(out + (size_t)row0 * NE + n0 + d) = v0;
        *(float2*)(out + (size_t)row1 * NE + n0 + d) = v1;
    }
}

// ---------------------------------------------------------------------------
extern "C" void kernel_launch(void* const* d_in, const int* in_sizes, int n_in,
                              void* d_out, int out_size)
{
    const float* his     = (const float*)d_in[0];
    const int*   mask    = (const int*)d_in[1];
    const float* explore = (const float*)d_in[2];
    const float* exploit = (const float*)d_in[3];
    const float* Wq = (const float*)d_in[4];
    const float* bq = (const float*)d_in[5];
    const float* Wk = (const float*)d_in[6];
    const float* bk = (const float*)d_in[7];
    const float* Wv = (const float*)d_in[8];
    const float* bv = (const float*)d_in[9];
    const float* Wo = (const float*)d_in[10];
    const float* bo = (const float*)d_in[11];
    float* out = (float*)d_out;

    const int qkv_smem = QKV_SMEM_BF16 * 2;     // 92160 B
    const int op_smem  = OP_SMEM_BF16 * 2;      // 55296 B
    static bool attr_done = false;
    if (!attr_done) {
        cudaFuncSetAttribute(qkv_mma, cudaFuncAttributeMaxDynamicSharedMemorySize, qkv_smem);
        cudaFuncSetAttribute(out_proj_mma, cudaFuncAttributeMaxDynamicSharedMemorySize, op_smem);
        attr_done = true;
    }

    prep_w<<<dim3(4, 4, 4), 256>>>(Wq, Wk, Wv, Wo);
    qkv_mma<<<dim3(8192 / 128, NH), 256, qkv_smem>>>(his, bq, bk, bv);
    attn_mma<<<dim3(NS / 128, NH, NB), 256>>>(mask, explore, exploit);
    out_proj_mma<<<dim3(8192 / 128, 4), 256, op_smem>>>(bo, mask, out);
}

// round 9
// speedup vs baseline: 9.6276x; 1.5529x over previous
#include <cuda_runtime.h>
#include <cuda_bf16.h>
#include <cuda_fp16.h>
#include <cstdint>
#include <math.h>

#define NB 4
#define NS 2048
#define NE 256
#define NH 4
#define ND 64

// Scratch (allocation-free). Q/K/V live in COMPACTED per-batch coordinates
// (rows 0..cnt_b-1 valid); AO is in ORIGINAL coordinates (masked rows stay 0).
__device__ float g_Q[NB*NH*NS*ND];                                  // [b,h,i,d] fp32
__device__ __align__(16) __half g_Kf[NB*NH*NS*ND];                  // [b,h,i,d] fp16
__device__ __align__(16) __half g_Vf[NB*NH*ND*NS];                  // [b,h,d,i] fp16
__device__ __align__(16) __nv_bfloat16 g_AOh[NB*NH*NS*ND];          // [b,h,s,d]
__device__ __align__(16) __nv_bfloat16 g_AOl[NB*NH*NS*ND];
__device__ __align__(16) __nv_bfloat16 g_Wth[4*NE*NE];              // [mat][n][k]
__device__ __align__(16) __nv_bfloat16 g_Wtl[4*NE*NE];
__device__ int g_idx[NB*NS];                                        // compacted -> orig s
__device__ int g_cnt[NB];

__device__ __forceinline__ uint32_t pack_bf16x2(float a, float b) {
    __nv_bfloat162 t = __floats2bfloat162_rn(a, b);   // a -> low half
    return *(uint32_t*)&t;
}
__device__ __forceinline__ uint32_t pack_h2(float a, float b) {
    __half2 t = __floats2half2_rn(a, b);              // a -> low half
    return *(uint32_t*)&t;
}
__device__ __forceinline__ void split_hi_lo(float x, float& hi, float& lo) {
    __nv_bfloat16 h = __float2bfloat16_rn(x);
    hi = __bfloat162float(h);
    lo = x - hi;
}

// mma.sync m16n8k16 row.col (sm_80+ PTX, no arch suffix)
__device__ __forceinline__ void mma16816(float c[4], const uint32_t a[4],
                                         uint32_t b0, uint32_t b1) {
    asm volatile(
        "mma.sync.aligned.m16n8k16.row.col.f32.bf16.bf16.f32 "
        "{%0,%1,%2,%3}, {%4,%5,%6,%7}, {%8,%9}, {%0,%1,%2,%3};"
        : "+f"(c[0]), "+f"(c[1]), "+f"(c[2]), "+f"(c[3])
        : "r"(a[0]), "r"(a[1]), "r"(a[2]), "r"(a[3]), "r"(b0), "r"(b1));
}
__device__ __forceinline__ void mma16816h(float c[4], const uint32_t a[4],
                                          uint32_t b0, uint32_t b1) {
    asm volatile(
        "mma.sync.aligned.m16n8k16.row.col.f32.f16.f16.f32 "
        "{%0,%1,%2,%3}, {%4,%5,%6,%7}, {%8,%9}, {%0,%1,%2,%3};"
        : "+f"(c[0]), "+f"(c[1]), "+f"(c[2]), "+f"(c[3])
        : "r"(a[0]), "r"(a[1]), "r"(a[2]), "r"(a[3]), "r"(b0), "r"(b1));
}

#define KPAD 72   // 16-bit row stride; word stride 36 -> conflict-free frag LDS

__device__ __forceinline__ void store_split4(__nv_bfloat16* bh, __nv_bfloat16* bl,
                                             int off, float4 v) {
    float h0,l0,h1,l1,h2,l2,h3,l3;
    split_hi_lo(v.x,h0,l0); split_hi_lo(v.y,h1,l1);
    split_hi_lo(v.z,h2,l2); split_hi_lo(v.w,h3,l3);
    *(uint32_t*)(bh + off)     = pack_bf16x2(h0, h1);
    *(uint32_t*)(bh + off + 2) = pack_bf16x2(h2, h3);
    *(uint32_t*)(bl + off)     = pack_bf16x2(l0, l1);
    *(uint32_t*)(bl + off + 2) = pack_bf16x2(l2, l3);
}

// ---------------------------------------------------------------------------
// Kernel A: per-batch compaction index (Hillis-Steele scan over 2048 mask bits)
// ---------------------------------------------------------------------------
__global__ __launch_bounds__(1024) void build_idx(const int* __restrict__ mask)
{
    __shared__ int scan[1024];
    const int b = blockIdx.x;
    const int tid = threadIdx.x;
    const int s0 = 2 * tid, s1 = 2 * tid + 1;
    const int m0 = (mask[b * NS + s0] == 0) ? 1 : 0;
    const int m1 = (mask[b * NS + s1] == 0) ? 1 : 0;
    scan[tid] = m0 + m1;
    __syncthreads();
    #pragma unroll
    for (int off = 1; off < 1024; off <<= 1) {
        int v = (tid >= off) ? scan[tid - off] : 0;
        __syncthreads();
        scan[tid] += v;
        __syncthreads();
    }
    const int excl = scan[tid] - m0 - m1;
    if (m0) g_idx[b * NS + excl] = s0;
    if (m1) g_idx[b * NS + excl + m0] = s1;
    const int total = scan[1023];
    for (int i = tid; i < NS; i += 1024)
        if (i >= total) g_idx[b * NS + i] = 0;     // pad with a valid index
    if (tid == 0) g_cnt[b] = total;
}

// ---------------------------------------------------------------------------
// Kernel 0: pre-split weights -> transposed hi/lo bf16 [mat][n][k].
// ---------------------------------------------------------------------------
__global__ __launch_bounds__(256) void prep_w(
    const float* __restrict__ Wq, const float* __restrict__ Wk,
    const float* __restrict__ Wv, const float* __restrict__ Wo)
{
    __shared__ float t[64][65];
    const float* Ws[4] = { Wq, Wk, Wv, Wo };
    const int mt = blockIdx.z;
    const int k0 = blockIdx.x * 64, n0 = blockIdx.y * 64;
    const int tid = threadIdx.x;
    const float* W = Ws[mt];

    #pragma unroll
    for (int it = 0; it < 16; it++) {
        int idx = tid + it * 256;
        int kk = idx >> 6, nn = idx & 63;
        t[kk][nn] = W[(k0 + kk) * NE + n0 + nn];
    }
    __syncthreads();

    #pragma unroll
    for (int it = 0; it < 2; it++) {
        int idx = tid + it * 256;
        int n = idx >> 3, c8 = (idx & 7) * 8;
        uint32_t hw[4], lw[4];
        #pragma unroll
        for (int p = 0; p < 4; p++) {
            float hi0, lo0, hi1, lo1;
            split_hi_lo(t[c8 + 2*p][n],     hi0, lo0);
            split_hi_lo(t[c8 + 2*p + 1][n], hi1, lo1);
            hw[p] = pack_bf16x2(hi0, hi1);
            lw[p] = pack_bf16x2(lo0, lo1);
        }
        size_t o = (size_t)mt * NE * NE + (size_t)(n0 + n) * NE + k0 + c8;
        *(uint4*)(g_Wth + o) = *(uint4*)hw;
        *(uint4*)(g_Wtl + o) = *(uint4*)lw;
    }
}

// ---------------------------------------------------------------------------
// Kernel 1: fused QKV projection on COMPACTED rows (gathered X).
// ---------------------------------------------------------------------------
#define XH_OFF   0
#define XL_OFF   (128*KPAD)
#define WTH_OFF  (2*128*KPAD)
#define WTL_OFF  (2*128*KPAD + 3*64*KPAD)
#define QKV_SMEM_BF16 (2*128*KPAD + 6*64*KPAD)   // 92160 B

__global__ __launch_bounds__(256, 1) void qkv_mma(
    const float* __restrict__ X,
    const float* __restrict__ bq, const float* __restrict__ bk,
    const float* __restrict__ bv)
{
    extern __shared__ __nv_bfloat16 smb[];
    __nv_bfloat16* Xh = smb + XH_OFF;
    __nv_bfloat16* Xl = smb + XL_OFF;

    const int tid  = threadIdx.x;
    const int w    = tid >> 5;
    const int lane = tid & 31;
    const int g    = lane >> 2;
    const int l4   = lane & 3;
    const int m0   = blockIdx.x * 128;          // compacted global row
    const int h    = blockIdx.y;
    const int n0   = h * 64;

    const int bb   = m0 >> 11;
    const int loc0 = m0 & (NS - 1);
    const int cnt  = g_cnt[bb];
    if (loc0 >= cnt) return;
    const int* idxp = g_idx + bb * NS;

    float acc[3][8][4];
    #pragma unroll
    for (int mt = 0; mt < 3; mt++)
        #pragma unroll
        for (int j = 0; j < 8; j++)
            #pragma unroll
            for (int c = 0; c < 4; c++) acc[mt][j][c] = 0.f;

    for (int k0 = 0; k0 < NE; k0 += 64) {
        #pragma unroll
        for (int it = 0; it < 8; it++) {
            int idx = tid + it * 256;
            int r = idx >> 4, c = (idx & 15) * 4;
            int src = idxp[loc0 + r];           // padded beyond cnt
            float4 v = *(const float4*)(X + ((size_t)bb * NS + src) * NE + k0 + c);
            store_split4(Xh, Xl, r * KPAD + c, v);
        }
        #pragma unroll
        for (int mt = 0; mt < 3; mt++) {
            __nv_bfloat16* Wth = smb + WTH_OFF + mt * 64 * KPAD;
            __nv_bfloat16* Wtl = smb + WTL_OFF + mt * 64 * KPAD;
            const size_t wb = (size_t)mt * NE * NE;
            #pragma unroll
            for (int it = 0; it < 2; it++) {
                int idx = tid + it * 256;
                int r = idx >> 3, c8 = (idx & 7) * 8;
                size_t o = wb + (size_t)(n0 + r) * NE + k0 + c8;
                *(uint4*)(Wth + r * KPAD + c8) = *(const uint4*)(g_Wth + o);
                *(uint4*)(Wtl + r * KPAD + c8) = *(const uint4*)(g_Wtl + o);
            }
        }
        __syncthreads();

        #pragma unroll
        for (int kc = 0; kc < 4; kc++) {
            int aoff = (w * 16 + g) * KPAD + kc * 16 + l4 * 2;
            uint32_t ah[4], al[4];
            ah[0] = *(const uint32_t*)(Xh + aoff);
            ah[1] = *(const uint32_t*)(Xh + aoff + 8 * KPAD);
            ah[2] = *(const uint32_t*)(Xh + aoff + 8);
            ah[3] = *(const uint32_t*)(Xh + aoff + 8 * KPAD + 8);
            al[0] = *(const uint32_t*)(Xl + aoff);
            al[1] = *(const uint32_t*)(Xl + aoff + 8 * KPAD);
            al[2] = *(const uint32_t*)(Xl + aoff + 8);
            al[3] = *(const uint32_t*)(Xl + aoff + 8 * KPAD + 8);

            #pragma unroll
            for (int mt = 0; mt < 3; mt++) {
                const __nv_bfloat16* Wth = smb + WTH_OFF + mt * 64 * KPAD;
                const __nv_bfloat16* Wtl = smb + WTL_OFF + mt * 64 * KPAD;
                #pragma unroll
                for (int j = 0; j < 8; j++) {
                    int boff = (j * 8 + g) * KPAD + kc * 16 + l4 * 2;
                    uint32_t bh0 = *(const uint32_t*)(Wth + boff);
                    uint32_t bh1 = *(const uint32_t*)(Wth + boff + 8);
                    uint32_t bl0 = *(const uint32_t*)(Wtl + boff);
                    uint32_t bl1 = *(const uint32_t*)(Wtl + boff + 8);
                    mma16816(acc[mt][j], ah, bh0, bh1);
                    mma16816(acc[mt][j], al, bh0, bh1);
                    mma16816(acc[mt][j], ah, bl0, bl1);
                }
            }
        }
        __syncthreads();
    }

    // Epilogue in compacted coordinates (b = bb, rows loc0+...).
    const int row0 = m0 + w * 16 + g;
    const int row1 = row0 + 8;
    const int s0 = row0 & (NS - 1);
    const int s1 = row1 & (NS - 1);

    // ---- Q: fp32 ----
    {
        float* O0 = g_Q + (((size_t)bb * NH + h) * NS + s0) * ND;
        float* O1 = g_Q + (((size_t)bb * NH + h) * NS + s1) * ND;
        #pragma unroll
        for (int j = 0; j < 8; j++) {
            int d = j * 8 + 2 * l4;
            float bx = bq[n0 + d], by = bq[n0 + d + 1];
            float2 v0 = { acc[0][j][0] + bx, acc[0][j][1] + by };
            float2 v1 = { acc[0][j][2] + bx, acc[0][j][3] + by };
            *(float2*)(O0 + d) = v0;
            *(float2*)(O1 + d) = v1;
        }
    }
    // ---- K: fp16 ----
    {
        size_t o0 = (((size_t)bb * NH + h) * NS + s0) * ND;
        size_t o1 = (((size_t)bb * NH + h) * NS + s1) * ND;
        #pragma unroll
        for (int j = 0; j < 8; j++) {
            int d = j * 8 + 2 * l4;
            float bx = bk[n0 + d], by = bk[n0 + d + 1];
            *(uint32_t*)(g_Kf + o0 + d) = pack_h2(acc[1][j][0] + bx, acc[1][j][1] + by);
            *(uint32_t*)(g_Kf + o1 + d) = pack_h2(acc[1][j][2] + bx, acc[1][j][3] + by);
        }
    }
    // ---- V: stage [d][i] fp32 in smem, write fp16 [b,h,d,i] ----
    #define VPAD 132
    __syncthreads();
    float* Vb = (float*)smb;
    #pragma unroll
    for (int j = 0; j < 8; j++) {
        int d = j * 8 + 2 * l4;
        float bx = bv[n0 + d], by = bv[n0 + d + 1];
        int sr0 = w * 16 + g, sr1 = sr0 + 8;
        Vb[(d    ) * VPAD + sr0] = acc[2][j][0] + bx;
        Vb[(d + 1) * VPAD + sr0] = acc[2][j][1] + by;
        Vb[(d    ) * VPAD + sr1] = acc[2][j][2] + bx;
        Vb[(d + 1) * VPAD + sr1] = acc[2][j][3] + by;
    }
    __syncthreads();
    #pragma unroll
    for (int it = 0; it < 8; it++) {
        int idx = tid + it * 256;
        int d = idx >> 5, c4 = (idx & 31) * 4;
        int s = loc0 + c4;
        size_t o = (((size_t)bb * NH + h) * ND + d) * NS + s;
        uint32_t hw[2] = { pack_h2(Vb[d * VPAD + c4],     Vb[d * VPAD + c4 + 1]),
                           pack_h2(Vb[d * VPAD + c4 + 2], Vb[d * VPAD + c4 + 3]) };
        *(uint2*)(g_Vf + o) = *(uint2*)hw;
    }
}

// ---------------------------------------------------------------------------
// Kernel 2: flash attention on compacted q/k (fp16 single-term mma).
// AO scattered back to original positions; unwritten rows stay 0.
// ---------------------------------------------------------------------------
__global__ __launch_bounds__(256, 2) void attn_mma(
    const float* __restrict__ explore,
    const float* __restrict__ exploit)
{
    __shared__ __align__(16) __half Ks[64*KPAD], Vs[64*KPAD];
    __shared__ float pens[64];

    const int tid  = threadIdx.x;
    const int w    = tid >> 5;
    const int lane = tid & 31;
    const int g    = lane >> 2;
    const int l4   = lane & 3;
    const int q0   = blockIdx.x * 128;
    const int h    = blockIdx.y, b = blockIdx.z;

    const int cnt = g_cnt[b];
    if (q0 >= cnt) return;
    const int* idxp = g_idx + b * NS;
    const int NT = (cnt + 63) >> 6;

    const size_t base = ((size_t)b * NH + h) * NS * ND;
    const float* Qp = g_Q + base;
    const __half* Kp = g_Kf + base;
    const __half* Vp = g_Vf + base;   // [d][i]

    const int row0 = w * 16 + g;
    const int row1 = row0 + 8;
    const int cq0 = q0 + row0, cq1 = q0 + row1;
    const int so0 = idxp[cq0], so1 = idxp[cq1];   // orig s (padded -> 0, discarded)
    float rs0, rs1;
    {
        float t0 = 1.0f + 0.5f * explore[b * NS + so0] - 0.5f * exploit[b * NS + so0];
        t0 = fminf(fmaxf(t0, 0.5f), 2.0f);
        rs0 = 0.125f / t0;
        float t1 = 1.0f + 0.5f * explore[b * NS + so1] - 0.5f * exploit[b * NS + so1];
        t1 = fminf(fmaxf(t1, 0.5f), 2.0f);
        rs1 = 0.125f / t1;
    }

    uint32_t qf[4][4];
    #pragma unroll
    for (int kc = 0; kc < 4; kc++) {
        int d0 = kc * 16 + l4 * 2;
        const float2 a00 = *(const float2*)(Qp + (size_t)cq0 * ND + d0);
        const float2 a10 = *(const float2*)(Qp + (size_t)cq1 * ND + d0);
        const float2 a01 = *(const float2*)(Qp + (size_t)cq0 * ND + d0 + 8);
        const float2 a11 = *(const float2*)(Qp + (size_t)cq1 * ND + d0 + 8);
        qf[kc][0] = pack_h2(a00.x * rs0, a00.y * rs0);
        qf[kc][1] = pack_h2(a10.x * rs1, a10.y * rs1);
        qf[kc][2] = pack_h2(a01.x * rs0, a01.y * rs0);
        qf[kc][3] = pack_h2(a11.x * rs1, a11.y * rs1);
    }

    float oacc[8][4];
    #pragma unroll
    for (int j = 0; j < 8; j++)
        #pragma unroll
        for (int c = 0; c < 4; c++) oacc[j][c] = 0.f;
    float lsum0 = 0.f, lsum1 = 0.f;

    for (int kt = 0; kt < NT; kt++) {
        const int kk0 = kt * 64;

        #pragma unroll
        for (int it = 0; it < 2; it++) {
            int idx = tid + it * 256;
            int r = idx >> 3, c8 = (idx & 7) * 8;
            *(uint4*)(Ks + r * KPAD + c8) = *(const uint4*)(Kp + (size_t)(kk0 + r) * ND + c8);
            *(uint4*)(Vs + r * KPAD + c8) = *(const uint4*)(Vp + (size_t)r * NS + kk0 + c8);
        }
        // tile-tail guard + fixed softmax shift (-11, cancels in normalize)
        if (tid < 64) pens[tid] = (kk0 + tid < cnt) ? -11.0f : -1e30f;
        __syncthreads();

        float sacc[8][4];
        #pragma unroll
        for (int j = 0; j < 8; j++)
            #pragma unroll
            for (int c = 0; c < 4; c++) sacc[j][c] = 0.f;

        #pragma unroll
        for (int kc = 0; kc < 4; kc++) {
            #pragma unroll
            for (int j = 0; j < 8; j++) {
                int boff = (j * 8 + g) * KPAD + kc * 16 + l4 * 2;
                uint32_t b0 = *(const uint32_t*)(Ks + boff);
                uint32_t b1 = *(const uint32_t*)(Ks + boff + 8);
                mma16816h(sacc[j], qf[kc], b0, b1);
            }
        }

        uint32_t ps[8][2];
        #pragma unroll
        for (int j = 0; j < 8; j++) {
            float2 pen2 = *(const float2*)(pens + j * 8 + l4 * 2);
            float p0 = __expf(sacc[j][0] + pen2.x);
            float p1 = __expf(sacc[j][1] + pen2.y);
            float p2 = __expf(sacc[j][2] + pen2.x);
            float p3 = __expf(sacc[j][3] + pen2.y);
            lsum0 += p0 + p1;
            lsum1 += p2 + p3;
            ps[j][0] = pack_h2(p0, p1);
            ps[j][1] = pack_h2(p2, p3);
        }

        #pragma unroll
        for (int kc = 0; kc < 4; kc++) {
            uint32_t Af[4] = { ps[2*kc][0], ps[2*kc][1], ps[2*kc+1][0], ps[2*kc+1][1] };
            #pragma unroll
            for (int j = 0; j < 8; j++) {
                int boff = (j * 8 + g) * KPAD + kc * 16 + l4 * 2;
                uint32_t b0 = *(const uint32_t*)(Vs + boff);
                uint32_t b1 = *(const uint32_t*)(Vs + boff + 8);
                mma16816h(oacc[j], Af, b0, b1);
            }
        }
        __syncthreads();
    }

    lsum0 += __shfl_xor_sync(0xffffffffu, lsum0, 1);
    lsum0 += __shfl_xor_sync(0xffffffffu, lsum0, 2);
    lsum1 += __shfl_xor_sync(0xffffffffu, lsum1, 1);
    lsum1 += __shfl_xor_sync(0xffffffffu, lsum1, 2);
    float inv0 = (lsum0 > 0.f) ? 1.f / lsum0 : 0.f;
    float inv1 = (lsum1 > 0.f) ? 1.f / lsum1 : 0.f;

    // ---- scatter AO (hi/lo bf16) to ORIGINAL positions, guarded ----
    if (cq0 < cnt) {
        size_t o0 = base + (size_t)so0 * ND;
        #pragma unroll
        for (int j = 0; j < 8; j++) {
            int d = j * 8 + l4 * 2;
            float h0,l0,h1,l1;
            split_hi_lo(oacc[j][0] * inv0, h0, l0);
            split_hi_lo(oacc[j][1] * inv0, h1, l1);
            *(uint32_t*)(g_AOh + o0 + d) = pack_bf16x2(h0, h1);
            *(uint32_t*)(g_AOl + o0 + d) = pack_bf16x2(l0, l1);
        }
    }
    if (cq1 < cnt) {
        size_t o1 = base + (size_t)so1 * ND;
        #pragma unroll
        for (int j = 0; j < 8; j++) {
            int d = j * 8 + l4 * 2;
            float h0,l0,h1,l1;
            split_hi_lo(oacc[j][2] * inv1, h0, l0);
            split_hi_lo(oacc[j][3] * inv1, h1, l1);
            *(uint32_t*)(g_AOh + o1 + d) = pack_bf16x2(h0, h1);
            *(uint32_t*)(g_AOl + o1 + d) = pack_bf16x2(l0, l1);
        }
    }
}

// ---------------------------------------------------------------------------
// Kernel 3: output projection via mma.sync (pre-split A and W) + mask zero.
// Original coordinates; masked rows read AO == 0 and are zeroed anyway.
// ---------------------------------------------------------------------------
#define OP_WTH_OFF (2*128*KPAD)
#define OP_WTL_OFF (2*128*KPAD + 64*KPAD)
#define OP_SMEM_BF16 (2*128*KPAD + 2*64*KPAD)   // 55296 B

__global__ __launch_bounds__(256, 2) void out_proj_mma(
    const float* __restrict__ bo,
    const int* __restrict__ mask,
    float* __restrict__ out)
{
    extern __shared__ __nv_bfloat16 smb[];
    __nv_bfloat16* Xh  = smb + XH_OFF;
    __nv_bfloat16* Xl  = smb + XL_OFF;
    __nv_bfloat16* Wth = smb + OP_WTH_OFF;
    __nv_bfloat16* Wtl = smb + OP_WTL_OFF;

    const int tid  = threadIdx.x;
    const int w    = tid >> 5;
    const int lane = tid & 31;
    const int g    = lane >> 2;
    const int l4   = lane & 3;
    const int m0   = blockIdx.x * 128;
    const int n0   = blockIdx.y * 64;

    float acc[8][4];
    #pragma unroll
    for (int j = 0; j < 8; j++)
        #pragma unroll
        for (int c = 0; c < 4; c++) acc[j][c] = 0.f;

    for (int k0 = 0; k0 < NE; k0 += 64) {
        const int hh = k0 >> 6;
        #pragma unroll
        for (int it = 0; it < 4; it++) {
            int idx = tid + it * 256;
            int r = idx >> 3, c8 = (idx & 7) * 8;
            int m = m0 + r;
            int bb_ = m >> 11, s = m & (NS - 1);
            size_t o = (((size_t)bb_ * NH + hh) * NS + s) * ND + c8;
            *(uint4*)(Xh + r * KPAD + c8) = *(const uint4*)(g_AOh + o);
            *(uint4*)(Xl + r * KPAD + c8) = *(const uint4*)(g_AOl + o);
        }
        #pragma unroll
        for (int it = 0; it < 2; it++) {
            int idx = tid + it * 256;
            int r = idx >> 3, c8 = (idx & 7) * 8;
            size_t o = (size_t)3 * NE * NE + (size_t)(n0 + r) * NE + k0 + c8;
            *(uint4*)(Wth + r * KPAD + c8) = *(const uint4*)(g_Wth + o);
            *(uint4*)(Wtl + r * KPAD + c8) = *(const uint4*)(g_Wtl + o);
        }
        __syncthreads();

        #pragma unroll
        for (int kc = 0; kc < 4; kc++) {
            int aoff = (w * 16 + g) * KPAD + kc * 16 + l4 * 2;
            uint32_t ah[4], al[4];
            ah[0] = *(const uint32_t*)(Xh + aoff);
            ah[1] = *(const uint32_t*)(Xh + aoff + 8 * KPAD);
            ah[2] = *(const uint32_t*)(Xh + aoff + 8);
            ah[3] = *(const uint32_t*)(Xh + aoff + 8 * KPAD + 8);
            al[0] = *(const uint32_t*)(Xl + aoff);
            al[1] = *(const uint32_t*)(Xl + aoff + 8 * KPAD);
            al[2] = *(const uint32_t*)(Xl + aoff + 8);
            al[3] = *(const uint32_t*)(Xl + aoff + 8 * KPAD + 8);
            #pragma unroll
            for (int j = 0; j < 8; j++) {
                int boff = (j * 8 + g) * KPAD + kc * 16 + l4 * 2;
                uint32_t bh0 = *(const uint32_t*)(Wth + boff);
                uint32_t bh1 = *(const uint32_t*)(Wth + boff + 8);
                uint32_t bl0 = *(const uint32_t*)(Wtl + boff);
                uint32_t bl1 = *(const uint32_t*)(Wtl + boff + 8);
                mma16816(acc[j], ah, bh0, bh1);
                mma16816(acc[j], al, bh0, bh1);
                mma16816(acc[j], ah, bl0, bl1);
            }
        }
        __syncthreads();
    }

    const int row0 = m0 + w * 16 + g;
    const int row1 = row0 + 8;
    const int b0_ = row0 >> 11, s0 = row0 & (NS - 1);
    const int b1_ = row1 >> 11, s1 = row1 & (NS - 1);
    const bool mq0 = mask[b0_ * NS + s0] != 0;
    const bool mq1 = mask[b1_ * NS + s1] != 0;
    #pragma unroll
    for (int j = 0; j < 8; j++) {
        int d = j * 8 + 2 * l4;
        float bx = bo[n0 + d], by = bo[n0 + d + 1];
        float2 v0 = { mq0 ? 0.f : acc[j][0] + bx, mq0 ? 0.f : acc[j][1] + by };
        float2 v1 = { mq1 ? 0.f : acc[j][2] + bx, mq1 ? 0.f : acc[j][3] + by };
        *(float2*)(out + (size_t)row0 * NE + n0 + d) = v0;
        *(float2*)(out + (size_t)row1 * NE + n0 + d) = v1;
    }
}

// ---------------------------------------------------------------------------
extern "C" void kernel_launch(void* const* d_in, const int* in_sizes, int n_in,
                              void* d_out, int out_size)
{
    const float* his     = (const float*)d_in[0];
    const int*   mask    = (const int*)d_in[1];
    const float* explore = (const float*)d_in[2];
    const float* exploit = (const float*)d_in[3];
    const float* Wq = (const float*)d_in[4];
    const float* bq = (const float*)d_in[5];
    const float* Wk = (const float*)d_in[6];
    const float* bk = (const float*)d_in[7];
    const float* Wv = (const float*)d_in[8];
    const float* bv = (const float*)d_in[9];
    const float* Wo = (const float*)d_in[10];
    const float* bo = (const float*)d_in[11];
    float* out = (float*)d_out;

    const int qkv_smem = QKV_SMEM_BF16 * 2;     // 92160 B
    const int op_smem  = OP_SMEM_BF16 * 2;      // 55296 B
    static bool attr_done = false;
    if (!attr_done) {
        cudaFuncSetAttribute(qkv_mma, cudaFuncAttributeMaxDynamicSharedMemorySize, qkv_smem);
        cudaFuncSetAttribute(out_proj_mma, cudaFuncAttributeMaxDynamicSharedMemorySize, op_smem);
        attr_done = true;
    }

    build_idx<<<NB, 1024>>>(mask);
    prep_w<<<dim3(4, 4, 4), 256>>>(Wq, Wk, Wv, Wo);
    qkv_mma<<<dim3(8192 / 128, NH), 256, qkv_smem>>>(his, bq, bk, bv);
    attn_mma<<<dim3(NS / 128, NH, NB), 256>>>(explore, exploit);
    out_proj_mma<<<dim3(8192 / 128, 4), 256, op_smem>>>(bo, mask, out);
}

// round 10
// speedup vs baseline: 11.3762x; 1.1816x over previous
#include <cuda_runtime.h>
#include <cuda_bf16.h>
#include <cuda_fp16.h>
#include <cstdint>
#include <math.h>

#define NB 4
#define NS 2048
#define NE 256
#define NH 4
#define ND 64

// Scratch (allocation-free). Q/K/V/AO all in COMPACTED per-batch coordinates.
__device__ float g_Q[NB*NH*NS*ND];                                  // [b,h,i,d] fp32
__device__ __align__(16) __half g_Kf[NB*NH*NS*ND];                  // [b,h,i,d] fp16
__device__ __align__(16) __half g_Vf[NB*NH*ND*NS];                  // [b,h,d,i] fp16
__device__ __align__(16) __nv_bfloat16 g_AOh[NB*NH*NS*ND];          // [b,h,i,d]
__device__ __align__(16) __nv_bfloat16 g_AOl[NB*NH*NS*ND];
__device__ __align__(16) __nv_bfloat16 g_Wth[4*NE*NE];              // [mat][n][k]
__device__ __align__(16) __nv_bfloat16 g_Wtl[4*NE*NE];
__device__ int g_idx[NB*NS];                                        // compacted -> orig s
__device__ int g_cnt[NB];

__device__ __forceinline__ uint32_t pack_bf16x2(float a, float b) {
    __nv_bfloat162 t = __floats2bfloat162_rn(a, b);   // a -> low half
    return *(uint32_t*)&t;
}
__device__ __forceinline__ uint32_t pack_h2(float a, float b) {
    __half2 t = __floats2half2_rn(a, b);              // a -> low half
    return *(uint32_t*)&t;
}
__device__ __forceinline__ void split_hi_lo(float x, float& hi, float& lo) {
    __nv_bfloat16 h = __float2bfloat16_rn(x);
    hi = __bfloat162float(h);
    lo = x - hi;
}

// mma.sync m16n8k16 row.col (sm_80+ PTX, no arch suffix)
__device__ __forceinline__ void mma16816(float c[4], const uint32_t a[4],
                                         uint32_t b0, uint32_t b1) {
    asm volatile(
        "mma.sync.aligned.m16n8k16.row.col.f32.bf16.bf16.f32 "
        "{%0,%1,%2,%3}, {%4,%5,%6,%7}, {%8,%9}, {%0,%1,%2,%3};"
        : "+f"(c[0]), "+f"(c[1]), "+f"(c[2]), "+f"(c[3])
        : "r"(a[0]), "r"(a[1]), "r"(a[2]), "r"(a[3]), "r"(b0), "r"(b1));
}
__device__ __forceinline__ void mma16816h(float c[4], const uint32_t a[4],
                                          uint32_t b0, uint32_t b1) {
    asm volatile(
        "mma.sync.aligned.m16n8k16.row.col.f32.f16.f16.f32 "
        "{%0,%1,%2,%3}, {%4,%5,%6,%7}, {%8,%9}, {%0,%1,%2,%3};"
        : "+f"(c[0]), "+f"(c[1]), "+f"(c[2]), "+f"(c[3])
        : "r"(a[0]), "r"(a[1]), "r"(a[2]), "r"(a[3]), "r"(b0), "r"(b1));
}

#define KPAD 72   // 16-bit row stride; word stride 36 -> conflict-free frag LDS

__device__ __forceinline__ void store_split4(__nv_bfloat16* bh, __nv_bfloat16* bl,
                                             int off, float4 v) {
    float h0,l0,h1,l1,h2,l2,h3,l3;
    split_hi_lo(v.x,h0,l0); split_hi_lo(v.y,h1,l1);
    split_hi_lo(v.z,h2,l2); split_hi_lo(v.w,h3,l3);
    *(uint32_t*)(bh + off)     = pack_bf16x2(h0, h1);
    *(uint32_t*)(bh + off + 2) = pack_bf16x2(h2, h3);
    *(uint32_t*)(bl + off)     = pack_bf16x2(l0, l1);
    *(uint32_t*)(bl + off + 2) = pack_bf16x2(l2, l3);
}

// ---------------------------------------------------------------------------
// Kernel A: per-batch compaction index (Hillis-Steele scan over 2048 mask bits)
// ---------------------------------------------------------------------------
__global__ __launch_bounds__(1024) void build_idx(const int* __restrict__ mask)
{
    __shared__ int scan[1024];
    const int b = blockIdx.x;
    const int tid = threadIdx.x;
    const int s0 = 2 * tid, s1 = 2 * tid + 1;
    const int m0 = (mask[b * NS + s0] == 0) ? 1 : 0;
    const int m1 = (mask[b * NS + s1] == 0) ? 1 : 0;
    scan[tid] = m0 + m1;
    __syncthreads();
    #pragma unroll
    for (int off = 1; off < 1024; off <<= 1) {
        int v = (tid >= off) ? scan[tid - off] : 0;
        __syncthreads();
        scan[tid] += v;
        __syncthreads();
    }
    const int excl = scan[tid] - m0 - m1;
    if (m0) g_idx[b * NS + excl] = s0;
    if (m1) g_idx[b * NS + excl + m0] = s1;
    const int total = scan[1023];
    for (int i = tid; i < NS; i += 1024)
        if (i >= total) g_idx[b * NS + i] = 0;     // pad with a valid index
    if (tid == 0) g_cnt[b] = total;
}

// ---------------------------------------------------------------------------
// Kernel B: zero all masked output rows (d_out is poisoned).
// ---------------------------------------------------------------------------
__global__ __launch_bounds__(256) void zero_masked(
    const int* __restrict__ mask, float* __restrict__ out)
{
    const int row = blockIdx.x * 4 + (threadIdx.x >> 6);
    const int c4 = threadIdx.x & 63;
    if (mask[row] != 0) {
        float4 z = {0.f, 0.f, 0.f, 0.f};
        *(float4*)(out + (size_t)row * NE + c4 * 4) = z;
    }
}

// ---------------------------------------------------------------------------
// Kernel 0: pre-split weights -> transposed hi/lo bf16 [mat][n][k].
// ---------------------------------------------------------------------------
__global__ __launch_bounds__(256) void prep_w(
    const float* __restrict__ Wq, const float* __restrict__ Wk,
    const float* __restrict__ Wv, const float* __restrict__ Wo)
{
    __shared__ float t[64][65];
    const float* Ws[4] = { Wq, Wk, Wv, Wo };
    const int mt = blockIdx.z;
    const int k0 = blockIdx.x * 64, n0 = blockIdx.y * 64;
    const int tid = threadIdx.x;
    const float* W = Ws[mt];

    #pragma unroll
    for (int it = 0; it < 16; it++) {
        int idx = tid + it * 256;
        int kk = idx >> 6, nn = idx & 63;
        t[kk][nn] = W[(k0 + kk) * NE + n0 + nn];
    }
    __syncthreads();

    #pragma unroll
    for (int it = 0; it < 2; it++) {
        int idx = tid + it * 256;
        int n = idx >> 3, c8 = (idx & 7) * 8;
        uint32_t hw[4], lw[4];
        #pragma unroll
        for (int p = 0; p < 4; p++) {
            float hi0, lo0, hi1, lo1;
            split_hi_lo(t[c8 + 2*p][n],     hi0, lo0);
            split_hi_lo(t[c8 + 2*p + 1][n], hi1, lo1);
            hw[p] = pack_bf16x2(hi0, hi1);
            lw[p] = pack_bf16x2(lo0, lo1);
        }
        size_t o = (size_t)mt * NE * NE + (size_t)(n0 + n) * NE + k0 + c8;
        *(uint4*)(g_Wth + o) = *(uint4*)hw;
        *(uint4*)(g_Wtl + o) = *(uint4*)lw;
    }
}

// ---------------------------------------------------------------------------
// Kernel 1: fused QKV projection on COMPACTED rows (gathered X).
// ---------------------------------------------------------------------------
#define XH_OFF   0
#define XL_OFF   (128*KPAD)
#define WTH_OFF  (2*128*KPAD)
#define WTL_OFF  (2*128*KPAD + 3*64*KPAD)
#define QKV_SMEM_BF16 (2*128*KPAD + 6*64*KPAD)   // 92160 B

__global__ __launch_bounds__(256, 1) void qkv_mma(
    const float* __restrict__ X,
    const float* __restrict__ bq, const float* __restrict__ bk,
    const float* __restrict__ bv)
{
    extern __shared__ __nv_bfloat16 smb[];
    __nv_bfloat16* Xh = smb + XH_OFF;
    __nv_bfloat16* Xl = smb + XL_OFF;

    const int tid  = threadIdx.x;
    const int w    = tid >> 5;
    const int lane = tid & 31;
    const int g    = lane >> 2;
    const int l4   = lane & 3;
    const int m0   = blockIdx.x * 128;          // compacted global row
    const int h    = blockIdx.y;
    const int n0   = h * 64;

    const int bb   = m0 >> 11;
    const int loc0 = m0 & (NS - 1);
    const int cnt  = g_cnt[bb];
    if (loc0 >= cnt) return;
    const int* idxp = g_idx + bb * NS;

    float acc[3][8][4];
    #pragma unroll
    for (int mt = 0; mt < 3; mt++)
        #pragma unroll
        for (int j = 0; j < 8; j++)
            #pragma unroll
            for (int c = 0; c < 4; c++) acc[mt][j][c] = 0.f;

    for (int k0 = 0; k0 < NE; k0 += 64) {
        #pragma unroll
        for (int it = 0; it < 8; it++) {
            int idx = tid + it * 256;
            int r = idx >> 4, c = (idx & 15) * 4;
            int src = idxp[loc0 + r];           // padded beyond cnt
            float4 v = *(const float4*)(X + ((size_t)bb * NS + src) * NE + k0 + c);
            store_split4(Xh, Xl, r * KPAD + c, v);
        }
        #pragma unroll
        for (int mt = 0; mt < 3; mt++) {
            __nv_bfloat16* Wth = smb + WTH_OFF + mt * 64 * KPAD;
            __nv_bfloat16* Wtl = smb + WTL_OFF + mt * 64 * KPAD;
            const size_t wb = (size_t)mt * NE * NE;
            #pragma unroll
            for (int it = 0; it < 2; it++) {
                int idx = tid + it * 256;
                int r = idx >> 3, c8 = (idx & 7) * 8;
                size_t o = wb + (size_t)(n0 + r) * NE + k0 + c8;
                *(uint4*)(Wth + r * KPAD + c8) = *(const uint4*)(g_Wth + o);
                *(uint4*)(Wtl + r * KPAD + c8) = *(const uint4*)(g_Wtl + o);
            }
        }
        __syncthreads();

        #pragma unroll
        for (int kc = 0; kc < 4; kc++) {
            int aoff = (w * 16 + g) * KPAD + kc * 16 + l4 * 2;
            uint32_t ah[4], al[4];
            ah[0] = *(const uint32_t*)(Xh + aoff);
            ah[1] = *(const uint32_t*)(Xh + aoff + 8 * KPAD);
            ah[2] = *(const uint32_t*)(Xh + aoff + 8);
            ah[3] = *(const uint32_t*)(Xh + aoff + 8 * KPAD + 8);
            al[0] = *(const uint32_t*)(Xl + aoff);
            al[1] = *(const uint32_t*)(Xl + aoff + 8 * KPAD);
            al[2] = *(const uint32_t*)(Xl + aoff + 8);
            al[3] = *(const uint32_t*)(Xl + aoff + 8 * KPAD + 8);

            #pragma unroll
            for (int mt = 0; mt < 3; mt++) {
                const __nv_bfloat16* Wth = smb + WTH_OFF + mt * 64 * KPAD;
                const __nv_bfloat16* Wtl = smb + WTL_OFF + mt * 64 * KPAD;
                #pragma unroll
                for (int j = 0; j < 8; j++) {
                    int boff = (j * 8 + g) * KPAD + kc * 16 + l4 * 2;
                    uint32_t bh0 = *(const uint32_t*)(Wth + boff);
                    uint32_t bh1 = *(const uint32_t*)(Wth + boff + 8);
                    uint32_t bl0 = *(const uint32_t*)(Wtl + boff);
                    uint32_t bl1 = *(const uint32_t*)(Wtl + boff + 8);
                    mma16816(acc[mt][j], ah, bh0, bh1);
                    mma16816(acc[mt][j], al, bh0, bh1);
                    mma16816(acc[mt][j], ah, bl0, bl1);
                }
            }
        }
        __syncthreads();
    }

    const int row0 = m0 + w * 16 + g;
    const int row1 = row0 + 8;
    const int s0 = row0 & (NS - 1);
    const int s1 = row1 & (NS - 1);

    // ---- Q: fp32 ----
    {
        float* O0 = g_Q + (((size_t)bb * NH + h) * NS + s0) * ND;
        float* O1 = g_Q + (((size_t)bb * NH + h) * NS + s1) * ND;
        #pragma unroll
        for (int j = 0; j < 8; j++) {
            int d = j * 8 + 2 * l4;
            float bx = bq[n0 + d], by = bq[n0 + d + 1];
            float2 v0 = { acc[0][j][0] + bx, acc[0][j][1] + by };
            float2 v1 = { acc[0][j][2] + bx, acc[0][j][3] + by };
            *(float2*)(O0 + d) = v0;
            *(float2*)(O1 + d) = v1;
        }
    }
    // ---- K: fp16 ----
    {
        size_t o0 = (((size_t)bb * NH + h) * NS + s0) * ND;
        size_t o1 = (((size_t)bb * NH + h) * NS + s1) * ND;
        #pragma unroll
        for (int j = 0; j < 8; j++) {
            int d = j * 8 + 2 * l4;
            float bx = bk[n0 + d], by = bk[n0 + d + 1];
            *(uint32_t*)(g_Kf + o0 + d) = pack_h2(acc[1][j][0] + bx, acc[1][j][1] + by);
            *(uint32_t*)(g_Kf + o1 + d) = pack_h2(acc[1][j][2] + bx, acc[1][j][3] + by);
        }
    }
    // ---- V: stage [d][i] fp32 in smem, write fp16 [b,h,d,i] ----
    #define VPAD 132
    __syncthreads();
    float* Vb = (float*)smb;
    #pragma unroll
    for (int j = 0; j < 8; j++) {
        int d = j * 8 + 2 * l4;
        float bx = bv[n0 + d], by = bv[n0 + d + 1];
        int sr0 = w * 16 + g, sr1 = sr0 + 8;
        Vb[(d    ) * VPAD + sr0] = acc[2][j][0] + bx;
        Vb[(d + 1) * VPAD + sr0] = acc[2][j][1] + by;
        Vb[(d    ) * VPAD + sr1] = acc[2][j][2] + bx;
        Vb[(d + 1) * VPAD + sr1] = acc[2][j][3] + by;
    }
    __syncthreads();
    #pragma unroll
    for (int it = 0; it < 8; it++) {
        int idx = tid + it * 256;
        int d = idx >> 5, c4 = (idx & 31) * 4;
        int s = (m0 & (NS - 1)) + c4;
        size_t o = (((size_t)bb * NH + h) * ND + d) * NS + s;
        uint32_t hw[2] = { pack_h2(Vb[d * VPAD + c4],     Vb[d * VPAD + c4 + 1]),
                           pack_h2(Vb[d * VPAD + c4 + 2], Vb[d * VPAD + c4 + 3]) };
        *(uint2*)(g_Vf + o) = *(uint2*)hw;
    }
}

// ---------------------------------------------------------------------------
// Kernel 2: flash attention, q-tile 64, 2 warpgroups split over K-tiles.
// Each wg owns its K/V smem buffers; named barriers; partials merged via smem.
// AO written in COMPACTED coordinates.
// ---------------------------------------------------------------------------
__global__ __launch_bounds__(256, 2) void attn_mma(
    const float* __restrict__ explore,
    const float* __restrict__ exploit)
{
    __shared__ __align__(16) __half Ks[2][64*KPAD];
    __shared__ __align__(16) __half Vs[2][64*KPAD];
    __shared__ float pens[2][64];

    const int tid  = threadIdx.x;
    const int w    = tid >> 5;
    const int wg   = w >> 2;          // 0/1
    const int w4   = w & 3;
    const int wtid = tid & 127;
    const int lane = tid & 31;
    const int g    = lane >> 2;
    const int l4   = lane & 3;
    const int q0   = blockIdx.x * 64;
    const int h    = blockIdx.y, b = blockIdx.z;

    const int cnt = g_cnt[b];
    if (q0 >= cnt) return;
    const int* idxp = g_idx + b * NS;
    const int NT = (cnt + 63) >> 6;

    const size_t base = ((size_t)b * NH + h) * NS * ND;
    const float* Qp = g_Q + base;
    const __half* Kp = g_Kf + base;
    const __half* Vp = g_Vf + base;   // [d][i]

    const int r0 = w4 * 16 + g;
    const int r1 = r0 + 8;
    const int cq0 = q0 + r0, cq1 = q0 + r1;
    const int so0 = idxp[cq0], so1 = idxp[cq1];
    float rs0, rs1;
    {
        float t0 = 1.0f + 0.5f * explore[b * NS + so0] - 0.5f * exploit[b * NS + so0];
        t0 = fminf(fmaxf(t0, 0.5f), 2.0f);
        rs0 = 0.125f / t0;
        float t1 = 1.0f + 0.5f * explore[b * NS + so1] - 0.5f * exploit[b * NS + so1];
        t1 = fminf(fmaxf(t1, 0.5f), 2.0f);
        rs1 = 0.125f / t1;
    }

    uint32_t qf[4][4];
    #pragma unroll
    for (int kc = 0; kc < 4; kc++) {
        int d0 = kc * 16 + l4 * 2;
        const float2 a00 = *(const float2*)(Qp + (size_t)cq0 * ND + d0);
        const float2 a10 = *(const float2*)(Qp + (size_t)cq1 * ND + d0);
        const float2 a01 = *(const float2*)(Qp + (size_t)cq0 * ND + d0 + 8);
        const float2 a11 = *(const float2*)(Qp + (size_t)cq1 * ND + d0 + 8);
        qf[kc][0] = pack_h2(a00.x * rs0, a00.y * rs0);
        qf[kc][1] = pack_h2(a10.x * rs1, a10.y * rs1);
        qf[kc][2] = pack_h2(a01.x * rs0, a01.y * rs0);
        qf[kc][3] = pack_h2(a11.x * rs1, a11.y * rs1);
    }

    float oacc[8][4];
    #pragma unroll
    for (int j = 0; j < 8; j++)
        #pragma unroll
        for (int c = 0; c < 4; c++) oacc[j][c] = 0.f;
    float lsum0 = 0.f, lsum1 = 0.f;

    __half* Ksw = Ks[wg];
    __half* Vsw = Vs[wg];

    for (int kt = wg; kt < NT; kt += 2) {
        const int kk0 = kt * 64;

        #pragma unroll
        for (int it = 0; it < 4; it++) {
            int idx = wtid + it * 128;
            int r = idx >> 3, c8 = (idx & 7) * 8;
            *(uint4*)(Ksw + r * KPAD + c8) = *(const uint4*)(Kp + (size_t)(kk0 + r) * ND + c8);
            *(uint4*)(Vsw + r * KPAD + c8) = *(const uint4*)(Vp + (size_t)r * NS + kk0 + c8);
        }
        if (wtid < 64) pens[wg][wtid] = (kk0 + wtid < cnt) ? -11.0f : -1e30f;
        asm volatile("bar.sync %0, %1;" :: "r"(wg + 1), "r"(128) : "memory");

        float sacc[8][4];
        #pragma unroll
        for (int j = 0; j < 8; j++)
            #pragma unroll
            for (int c = 0; c < 4; c++) sacc[j][c] = 0.f;

        #pragma unroll
        for (int kc = 0; kc < 4; kc++) {
            #pragma unroll
            for (int j = 0; j < 8; j++) {
                int boff = (j * 8 + g) * KPAD + kc * 16 + l4 * 2;
                uint32_t b0 = *(const uint32_t*)(Ksw + boff);
                uint32_t b1 = *(const uint32_t*)(Ksw + boff + 8);
                mma16816h(sacc[j], qf[kc], b0, b1);
            }
        }

        uint32_t ps[8][2];
        #pragma unroll
        for (int j = 0; j < 8; j++) {
            float2 pen2 = *(const float2*)(&pens[wg][j * 8 + l4 * 2]);
            float p0 = __expf(sacc[j][0] + pen2.x);
            float p1 = __expf(sacc[j][1] + pen2.y);
            float p2 = __expf(sacc[j][2] + pen2.x);
            float p3 = __expf(sacc[j][3] + pen2.y);
            lsum0 += p0 + p1;
            lsum1 += p2 + p3;
            ps[j][0] = pack_h2(p0, p1);
            ps[j][1] = pack_h2(p2, p3);
        }

        #pragma unroll
        for (int kc = 0; kc < 4; kc++) {
            uint32_t Af[4] = { ps[2*kc][0], ps[2*kc][1], ps[2*kc+1][0], ps[2*kc+1][1] };
            #pragma unroll
            for (int j = 0; j < 8; j++) {
                int boff = (j * 8 + g) * KPAD + kc * 16 + l4 * 2;
                uint32_t b0 = *(const uint32_t*)(Vsw + boff);
                uint32_t b1 = *(const uint32_t*)(Vsw + boff + 8);
                mma16816h(oacc[j], Af, b0, b1);
            }
        }
        asm volatile("bar.sync %0, %1;" :: "r"(wg + 1), "r"(128) : "memory");
    }

    // quad-reduce partial row sums
    lsum0 += __shfl_xor_sync(0xffffffffu, lsum0, 1);
    lsum0 += __shfl_xor_sync(0xffffffffu, lsum0, 2);
    lsum1 += __shfl_xor_sync(0xffffffffu, lsum1, 1);
    lsum1 += __shfl_xor_sync(0xffffffffu, lsum1, 2);

    // ---- combine wg partials through smem (overlay on Ks) ----
    __syncthreads();
    float* Ob = (float*)&Ks[0][0];          // 64 x 66 floats
    float* Lb = Ob + 64 * 66;               // 64 floats
    if (wg == 1) {
        #pragma unroll
        for (int j = 0; j < 8; j++) {
            int col = j * 8 + 2 * l4;
            Ob[r0 * 66 + col]     = oacc[j][0];
            Ob[r0 * 66 + col + 1] = oacc[j][1];
            Ob[r1 * 66 + col]     = oacc[j][2];
            Ob[r1 * 66 + col + 1] = oacc[j][3];
        }
        if (l4 == 0) { Lb[r0] = lsum0; Lb[r1] = lsum1; }
    }
    __syncthreads();
    if (wg == 0) {
        lsum0 += Lb[r0];
        lsum1 += Lb[r1];
        float inv0 = (lsum0 > 0.f) ? 1.f / lsum0 : 0.f;
        float inv1 = (lsum1 > 0.f) ? 1.f / lsum1 : 0.f;
        if (cq0 < cnt) {
            size_t o0 = base + (size_t)cq0 * ND;
            #pragma unroll
            for (int j = 0; j < 8; j++) {
                int col = j * 8 + 2 * l4;
                float v0 = (oacc[j][0] + Ob[r0 * 66 + col])     * inv0;
                float v1 = (oacc[j][1] + Ob[r0 * 66 + col + 1]) * inv0;
                float h0,l0,h1,l1;
                split_hi_lo(v0, h0, l0); split_hi_lo(v1, h1, l1);
                *(uint32_t*)(g_AOh + o0 + col) = pack_bf16x2(h0, h1);
                *(uint32_t*)(g_AOl + o0 + col) = pack_bf16x2(l0, l1);
            }
        }
        if (cq1 < cnt) {
            size_t o1 = base + (size_t)cq1 * ND;
            #pragma unroll
            for (int j = 0; j < 8; j++) {
                int col = j * 8 + 2 * l4;
                float v0 = (oacc[j][2] + Ob[r1 * 66 + col])     * inv1;
                float v1 = (oacc[j][3] + Ob[r1 * 66 + col + 1]) * inv1;
                float h0,l0,h1,l1;
                split_hi_lo(v0, h0, l0); split_hi_lo(v1, h1, l1);
                *(uint32_t*)(g_AOh + o1 + col) = pack_bf16x2(h0, h1);
                *(uint32_t*)(g_AOl + o1 + col) = pack_bf16x2(l0, l1);
            }
        }
    }
}

// ---------------------------------------------------------------------------
// Kernel 3: output projection on COMPACTED rows, scatter to original rows.
// m-tile 64, 128 threads, split-bf16 3-term (precision-critical).
// ---------------------------------------------------------------------------
__global__ __launch_bounds__(128, 4) void out_proj_mma(
    const float* __restrict__ bo,
    float* __restrict__ out)
{
    __shared__ __align__(16) __nv_bfloat16 Xh[64*KPAD], Xl[64*KPAD];
    __shared__ __align__(16) __nv_bfloat16 Wth[64*KPAD], Wtl[64*KPAD];

    const int tid  = threadIdx.x;
    const int w4   = tid >> 5;
    const int lane = tid & 31;
    const int g    = lane >> 2;
    const int l4   = lane & 3;
    const int m0   = blockIdx.x * 64;           // compacted global row
    const int n0   = blockIdx.y * 64;

    const int bb   = m0 >> 11;
    const int loc0 = m0 & (NS - 1);
    const int cnt  = g_cnt[bb];
    if (loc0 >= cnt) return;
    const int* idxp = g_idx + bb * NS;

    float acc[8][4];
    #pragma unroll
    for (int j = 0; j < 8; j++)
        #pragma unroll
        for (int c = 0; c < 4; c++) acc[j][c] = 0.f;

    for (int k0 = 0; k0 < NE; k0 += 64) {
        const int hh = k0 >> 6;
        #pragma unroll
        for (int it = 0; it < 4; it++) {
            int idx = tid + it * 128;
            int r = idx >> 3, c8 = (idx & 7) * 8;
            size_t o = (((size_t)bb * NH + hh) * NS + loc0 + r) * ND + c8;
            *(uint4*)(Xh + r * KPAD + c8) = *(const uint4*)(g_AOh + o);
            *(uint4*)(Xl + r * KPAD + c8) = *(const uint4*)(g_AOl + o);
        }
        #pragma unroll
        for (int it = 0; it < 4; it++) {
            int idx = tid + it * 128;
            int r = idx >> 3, c8 = (idx & 7) * 8;
            size_t o = (size_t)3 * NE * NE + (size_t)(n0 + r) * NE + k0 + c8;
            *(uint4*)(Wth + r * KPAD + c8) = *(const uint4*)(g_Wth + o);
            *(uint4*)(Wtl + r * KPAD + c8) = *(const uint4*)(g_Wtl + o);
        }
        __syncthreads();

        #pragma unroll
        for (int kc = 0; kc < 4; kc++) {
            int aoff = (w4 * 16 + g) * KPAD + kc * 16 + l4 * 2;
            uint32_t ah[4], al[4];
            ah[0] = *(const uint32_t*)(Xh + aoff);
            ah[1] = *(const uint32_t*)(Xh + aoff + 8 * KPAD);
            ah[2] = *(const uint32_t*)(Xh + aoff + 8);
            ah[3] = *(const uint32_t*)(Xh + aoff + 8 * KPAD + 8);
            al[0] = *(const uint32_t*)(Xl + aoff);
            al[1] = *(const uint32_t*)(Xl + aoff + 8 * KPAD);
            al[2] = *(const uint32_t*)(Xl + aoff + 8);
            al[3] = *(const uint32_t*)(Xl + aoff + 8 * KPAD + 8);
            #pragma unroll
            for (int j = 0; j < 8; j++) {
                int boff = (j * 8 + g) * KPAD + kc * 16 + l4 * 2;
                uint32_t bh0 = *(const uint32_t*)(Wth + boff);
                uint32_t bh1 = *(const uint32_t*)(Wth + boff + 8);
                uint32_t bl0 = *(const uint32_t*)(Wtl + boff);
                uint32_t bl1 = *(const uint32_t*)(Wtl + boff + 8);
                mma16816(acc[j], ah, bh0, bh1);
                mma16816(acc[j], al, bh0, bh1);
                mma16816(acc[j], ah, bl0, bl1);
            }
        }
        __syncthreads();
    }

    const int lr0 = loc0 + w4 * 16 + g;
    const int lr1 = lr0 + 8;
    if (lr0 < cnt) {
        int row = bb * NS + idxp[lr0];
        #pragma unroll
        for (int j = 0; j < 8; j++) {
            int d = j * 8 + 2 * l4;
            float2 v = { acc[j][0] + bo[n0 + d], acc[j][1] + bo[n0 + d + 1] };
            *(float2*)(out + (size_t)row * NE + n0 + d) = v;
        }
    }
    if (lr1 < cnt) {
        int row = bb * NS + idxp[lr1];
        #pragma unroll
        for (int j = 0; j < 8; j++) {
            int d = j * 8 + 2 * l4;
            float2 v = { acc[j][2] + bo[n0 + d], acc[j][3] + bo[n0 + d + 1] };
            *(float2*)(out + (size_t)row * NE + n0 + d) = v;
        }
    }
}

// ---------------------------------------------------------------------------
extern "C" void kernel_launch(void* const* d_in, const int* in_sizes, int n_in,
                              void* d_out, int out_size)
{
    const float* his     = (const float*)d_in[0];
    const int*   mask    = (const int*)d_in[1];
    const float* explore = (const float*)d_in[2];
    const float* exploit = (const float*)d_in[3];
    const float* Wq = (const float*)d_in[4];
    const float* bq = (const float*)d_in[5];
    const float* Wk = (const float*)d_in[6];
    const float* bk = (const float*)d_in[7];
    const float* Wv = (const float*)d_in[8];
    const float* bv = (const float*)d_in[9];
    const float* Wo = (const float*)d_in[10];
    const float* bo = (const float*)d_in[11];
    float* out = (float*)d_out;

    const int qkv_smem = QKV_SMEM_BF16 * 2;     // 92160 B
    static bool attr_done = false;
    if (!attr_done) {
        cudaFuncSetAttribute(qkv_mma, cudaFuncAttributeMaxDynamicSharedMemorySize, qkv_smem);
        attr_done = true;
    }

    build_idx<<<NB, 1024>>>(mask);
    prep_w<<<dim3(4, 4, 4), 256>>>(Wq, Wk, Wv, Wo);
    zero_masked<<<NB * NS / 4, 256>>>(mask, out);
    qkv_mma<<<dim3(8192 / 128, NH), 256, qkv_smem>>>(his, bq, bk, bv);
    attn_mma<<<dim3(NS / 64, NH, NB), 256>>>(explore, exploit);
    out_proj_mma<<<dim3(NB * NS / 64, 4), 128>>>(bo, out);
}

// round 11
// speedup vs baseline: 11.3965x; 1.0018x over previous
#include <cuda_runtime.h>
#include <cuda_bf16.h>
#include <cuda_fp16.h>
#include <cstdint>
#include <math.h>

#define NB 4
#define NS 2048
#define NE 256
#define NH 4
#define ND 64

// Scratch (allocation-free). Q/K/V/AO all in COMPACTED per-batch coordinates.
__device__ float g_Q[NB*NH*NS*ND];                                  // [b,h,i,d] fp32
__device__ __align__(16) __half g_Kf[NB*NH*NS*ND];                  // [b,h,i,d] fp16
__device__ __align__(16) __half g_Vf[NB*NH*ND*NS];                  // [b,h,d,i] fp16
__device__ __align__(16) __nv_bfloat16 g_AOh[NB*NH*NS*ND];          // [b,h,i,d]
__device__ __align__(16) __nv_bfloat16 g_AOl[NB*NH*NS*ND];
__device__ __align__(16) __nv_bfloat16 g_Wth[4*NE*NE];              // [mat][n][k]
__device__ __align__(16) __nv_bfloat16 g_Wtl[4*NE*NE];
__device__ int g_idx[NB*NS];                                        // compacted -> orig s
__device__ int g_cnt[NB];

__device__ __forceinline__ uint32_t pack_bf16x2(float a, float b) {
    __nv_bfloat162 t = __floats2bfloat162_rn(a, b);   // a -> low half
    return *(uint32_t*)&t;
}
__device__ __forceinline__ uint32_t pack_h2(float a, float b) {
    __half2 t = __floats2half2_rn(a, b);              // a -> low half
    return *(uint32_t*)&t;
}
__device__ __forceinline__ void split_hi_lo(float x, float& hi, float& lo) {
    __nv_bfloat16 h = __float2bfloat16_rn(x);
    hi = __bfloat162float(h);
    lo = x - hi;
}

// mma.sync m16n8k16 row.col (sm_80+ PTX, no arch suffix)
__device__ __forceinline__ void mma16816(float c[4], const uint32_t a[4],
                                         uint32_t b0, uint32_t b1) {
    asm volatile(
        "mma.sync.aligned.m16n8k16.row.col.f32.bf16.bf16.f32 "
        "{%0,%1,%2,%3}, {%4,%5,%6,%7}, {%8,%9}, {%0,%1,%2,%3};"
        : "+f"(c[0]), "+f"(c[1]), "+f"(c[2]), "+f"(c[3])
        : "r"(a[0]), "r"(a[1]), "r"(a[2]), "r"(a[3]), "r"(b0), "r"(b1));
}
__device__ __forceinline__ void mma16816h(float c[4], const uint32_t a[4],
                                          uint32_t b0, uint32_t b1) {
    asm volatile(
        "mma.sync.aligned.m16n8k16.row.col.f32.f16.f16.f32 "
        "{%0,%1,%2,%3}, {%4,%5,%6,%7}, {%8,%9}, {%0,%1,%2,%3};"
        : "+f"(c[0]), "+f"(c[1]), "+f"(c[2]), "+f"(c[3])
        : "r"(a[0]), "r"(a[1]), "r"(a[2]), "r"(a[3]), "r"(b0), "r"(b1));
}

#define KPAD 72   // 16-bit row stride; word stride 36 -> conflict-free frag LDS

__device__ __forceinline__ void store_split4(__nv_bfloat16* bh, __nv_bfloat16* bl,
                                             int off, float4 v) {
    float h0,l0,h1,l1,h2,l2,h3,l3;
    split_hi_lo(v.x,h0,l0); split_hi_lo(v.y,h1,l1);
    split_hi_lo(v.z,h2,l2); split_hi_lo(v.w,h3,l3);
    *(uint32_t*)(bh + off)     = pack_bf16x2(h0, h1);
    *(uint32_t*)(bh + off + 2) = pack_bf16x2(h2, h3);
    *(uint32_t*)(bl + off)     = pack_bf16x2(l0, l1);
    *(uint32_t*)(bl + off + 2) = pack_bf16x2(l2, l3);
}

// ---------------------------------------------------------------------------
// Kernel A: per-batch compaction index (Hillis-Steele scan over 2048 mask bits)
// ---------------------------------------------------------------------------
__global__ __launch_bounds__(1024) void build_idx(const int* __restrict__ mask)
{
    __shared__ int scan[1024];
    const int b = blockIdx.x;
    const int tid = threadIdx.x;
    const int s0 = 2 * tid, s1 = 2 * tid + 1;
    const int m0 = (mask[b * NS + s0] == 0) ? 1 : 0;
    const int m1 = (mask[b * NS + s1] == 0) ? 1 : 0;
    scan[tid] = m0 + m1;
    __syncthreads();
    #pragma unroll
    for (int off = 1; off < 1024; off <<= 1) {
        int v = (tid >= off) ? scan[tid - off] : 0;
        __syncthreads();
        scan[tid] += v;
        __syncthreads();
    }
    const int excl = scan[tid] - m0 - m1;
    if (m0) g_idx[b * NS + excl] = s0;
    if (m1) g_idx[b * NS + excl + m0] = s1;
    const int total = scan[1023];
    for (int i = tid; i < NS; i += 1024)
        if (i >= total) g_idx[b * NS + i] = 0;     // pad with a valid index
    if (tid == 0) g_cnt[b] = total;
}

// ---------------------------------------------------------------------------
// Kernel B: zero all masked output rows (d_out is poisoned).
// ---------------------------------------------------------------------------
__global__ __launch_bounds__(256) void zero_masked(
    const int* __restrict__ mask, float* __restrict__ out)
{
    const int row = blockIdx.x * 4 + (threadIdx.x >> 6);
    const int c4 = threadIdx.x & 63;
    if (mask[row] != 0) {
        float4 z = {0.f, 0.f, 0.f, 0.f};
        *(float4*)(out + (size_t)row * NE + c4 * 4) = z;
    }
}

// ---------------------------------------------------------------------------
// Kernel 0: pre-split weights -> transposed hi/lo bf16 [mat][n][k].
// ---------------------------------------------------------------------------
__global__ __launch_bounds__(256) void prep_w(
    const float* __restrict__ Wq, const float* __restrict__ Wk,
    const float* __restrict__ Wv, const float* __restrict__ Wo)
{
    __shared__ float t[64][65];
    const float* Ws[4] = { Wq, Wk, Wv, Wo };
    const int mt = blockIdx.z;
    const int k0 = blockIdx.x * 64, n0 = blockIdx.y * 64;
    const int tid = threadIdx.x;
    const float* W = Ws[mt];

    #pragma unroll
    for (int it = 0; it < 16; it++) {
        int idx = tid + it * 256;
        int kk = idx >> 6, nn = idx & 63;
        t[kk][nn] = W[(k0 + kk) * NE + n0 + nn];
    }
    __syncthreads();

    #pragma unroll
    for (int it = 0; it < 2; it++) {
        int idx = tid + it * 256;
        int n = idx >> 3, c8 = (idx & 7) * 8;
        uint32_t hw[4], lw[4];
        #pragma unroll
        for (int p = 0; p < 4; p++) {
            float hi0, lo0, hi1, lo1;
            split_hi_lo(t[c8 + 2*p][n],     hi0, lo0);
            split_hi_lo(t[c8 + 2*p + 1][n], hi1, lo1);
            hw[p] = pack_bf16x2(hi0, hi1);
            lw[p] = pack_bf16x2(lo0, lo1);
        }
        size_t o = (size_t)mt * NE * NE + (size_t)(n0 + n) * NE + k0 + c8;
        *(uint4*)(g_Wth + o) = *(uint4*)hw;
        *(uint4*)(g_Wtl + o) = *(uint4*)lw;
    }
}

// ---------------------------------------------------------------------------
// Kernel 1: fused QKV projection on COMPACTED rows (gathered X).
// m-tile 64, 128 threads, 2 CTAs/SM (regfile: 247*128*2 < 64K).
// ---------------------------------------------------------------------------
#define QX_H    0
#define QX_L    (64*KPAD)
#define QW_TH   (2*64*KPAD)
#define QW_TL   (5*64*KPAD)
#define QKV_SMEM_BF16 (8*64*KPAD)    // 36864 elems = 73728 B

__global__ __launch_bounds__(128, 2) void qkv_mma(
    const float* __restrict__ X,
    const float* __restrict__ bq, const float* __restrict__ bk,
    const float* __restrict__ bv)
{
    extern __shared__ __nv_bfloat16 smb[];
    __nv_bfloat16* Xh = smb + QX_H;
    __nv_bfloat16* Xl = smb + QX_L;

    const int tid  = threadIdx.x;
    const int w4   = tid >> 5;
    const int lane = tid & 31;
    const int g    = lane >> 2;
    const int l4   = lane & 3;
    const int m0   = blockIdx.x * 64;           // compacted global row
    const int h    = blockIdx.y;
    const int n0   = h * 64;

    const int bb   = m0 >> 11;
    const int loc0 = m0 & (NS - 1);
    const int cnt  = g_cnt[bb];
    if (loc0 >= cnt) return;
    const int* idxp = g_idx + bb * NS;

    float acc[3][8][4];
    #pragma unroll
    for (int mt = 0; mt < 3; mt++)
        #pragma unroll
        for (int j = 0; j < 8; j++)
            #pragma unroll
            for (int c = 0; c < 4; c++) acc[mt][j][c] = 0.f;

    for (int k0 = 0; k0 < NE; k0 += 64) {
        // ---- X tile [64 m][64 k], gathered + split hi/lo ----
        #pragma unroll
        for (int it = 0; it < 8; it++) {
            int idx = tid + it * 128;
            int r = idx >> 4, c = (idx & 15) * 4;
            int src = idxp[loc0 + r];           // padded beyond cnt
            float4 v = *(const float4*)(X + ((size_t)bb * NS + src) * NE + k0 + c);
            store_split4(Xh, Xl, r * KPAD + c, v);
        }
        // ---- W tiles (pre-split, transposed) straight copy ----
        #pragma unroll
        for (int mt = 0; mt < 3; mt++) {
            __nv_bfloat16* Wth = smb + QW_TH + mt * 64 * KPAD;
            __nv_bfloat16* Wtl = smb + QW_TL + mt * 64 * KPAD;
            const size_t wb = (size_t)mt * NE * NE;
            #pragma unroll
            for (int it = 0; it < 4; it++) {
                int idx = tid + it * 128;
                int r = idx >> 3, c8 = (idx & 7) * 8;
                size_t o = wb + (size_t)(n0 + r) * NE + k0 + c8;
                *(uint4*)(Wth + r * KPAD + c8) = *(const uint4*)(g_Wth + o);
                *(uint4*)(Wtl + r * KPAD + c8) = *(const uint4*)(g_Wtl + o);
            }
        }
        __syncthreads();

        #pragma unroll
        for (int kc = 0; kc < 4; kc++) {
            int aoff = (w4 * 16 + g) * KPAD + kc * 16 + l4 * 2;
            uint32_t ah[4], al[4];
            ah[0] = *(const uint32_t*)(Xh + aoff);
            ah[1] = *(const uint32_t*)(Xh + aoff + 8 * KPAD);
            ah[2] = *(const uint32_t*)(Xh + aoff + 8);
            ah[3] = *(const uint32_t*)(Xh + aoff + 8 * KPAD + 8);
            al[0] = *(const uint32_t*)(Xl + aoff);
            al[1] = *(const uint32_t*)(Xl + aoff + 8 * KPAD);
            al[2] = *(const uint32_t*)(Xl + aoff + 8);
            al[3] = *(const uint32_t*)(Xl + aoff + 8 * KPAD + 8);

            #pragma unroll
            for (int mt = 0; mt < 3; mt++) {
                const __nv_bfloat16* Wth = smb + QW_TH + mt * 64 * KPAD;
                const __nv_bfloat16* Wtl = smb + QW_TL + mt * 64 * KPAD;
                #pragma unroll
                for (int j = 0; j < 8; j++) {
                    int boff = (j * 8 + g) * KPAD + kc * 16 + l4 * 2;
                    uint32_t bh0 = *(const uint32_t*)(Wth + boff);
                    uint32_t bh1 = *(const uint32_t*)(Wth + boff + 8);
                    uint32_t bl0 = *(const uint32_t*)(Wtl + boff);
                    uint32_t bl1 = *(const uint32_t*)(Wtl + boff + 8);
                    mma16816(acc[mt][j], ah, bh0, bh1);
                    mma16816(acc[mt][j], al, bh0, bh1);
                    mma16816(acc[mt][j], ah, bl0, bl1);
                }
            }
        }
        __syncthreads();
    }

    const int row0 = m0 + w4 * 16 + g;
    const int row1 = row0 + 8;
    const int s0 = row0 & (NS - 1);
    const int s1 = row1 & (NS - 1);

    // ---- Q: fp32 ----
    {
        float* O0 = g_Q + (((size_t)bb * NH + h) * NS + s0) * ND;
        float* O1 = g_Q + (((size_t)bb * NH + h) * NS + s1) * ND;
        #pragma unroll
        for (int j = 0; j < 8; j++) {
            int d = j * 8 + 2 * l4;
            float bx = bq[n0 + d], by = bq[n0 + d + 1];
            float2 v0 = { acc[0][j][0] + bx, acc[0][j][1] + by };
            float2 v1 = { acc[0][j][2] + bx, acc[0][j][3] + by };
            *(float2*)(O0 + d) = v0;
            *(float2*)(O1 + d) = v1;
        }
    }
    // ---- K: fp16 ----
    {
        size_t o0 = (((size_t)bb * NH + h) * NS + s0) * ND;
        size_t o1 = (((size_t)bb * NH + h) * NS + s1) * ND;
        #pragma unroll
        for (int j = 0; j < 8; j++) {
            int d = j * 8 + 2 * l4;
            float bx = bk[n0 + d], by = bk[n0 + d + 1];
            *(uint32_t*)(g_Kf + o0 + d) = pack_h2(acc[1][j][0] + bx, acc[1][j][1] + by);
            *(uint32_t*)(g_Kf + o1 + d) = pack_h2(acc[1][j][2] + bx, acc[1][j][3] + by);
        }
    }
    // ---- V: stage [d][s] fp32 in smem (64x64), write fp16 [b,h,d,i] ----
    #define VPAD 68
    __syncthreads();
    float* Vb = (float*)smb;   // 64*68*4 = 17408 B, overlays tiles
    #pragma unroll
    for (int j = 0; j < 8; j++) {
        int d = j * 8 + 2 * l4;
        float bx = bv[n0 + d], by = bv[n0 + d + 1];
        int sr0 = w4 * 16 + g, sr1 = sr0 + 8;
        Vb[(d    ) * VPAD + sr0] = acc[2][j][0] + bx;
        Vb[(d + 1) * VPAD + sr0] = acc[2][j][1] + by;
        Vb[(d    ) * VPAD + sr1] = acc[2][j][2] + bx;
        Vb[(d + 1) * VPAD + sr1] = acc[2][j][3] + by;
    }
    __syncthreads();
    #pragma unroll
    for (int it = 0; it < 8; it++) {
        int idx = tid + it * 128;
        int d = idx >> 4, c4 = (idx & 15) * 4;
        int s = loc0 + c4;
        size_t o = (((size_t)bb * NH + h) * ND + d) * NS + s;
        uint32_t hw[2] = { pack_h2(Vb[d * VPAD + c4],     Vb[d * VPAD + c4 + 1]),
                           pack_h2(Vb[d * VPAD + c4 + 2], Vb[d * VPAD + c4 + 3]) };
        *(uint2*)(g_Vf + o) = *(uint2*)hw;
    }
}

// ---------------------------------------------------------------------------
// Kernel 2: flash attention, q-tile 64, 2 warpgroups split over K-tiles.
// ---------------------------------------------------------------------------
__global__ __launch_bounds__(256, 2) void attn_mma(
    const float* __restrict__ explore,
    const float* __restrict__ exploit)
{
    __shared__ __align__(16) __half Ks[2][64*KPAD];
    __shared__ __align__(16) __half Vs[2][64*KPAD];
    __shared__ float pens[2][64];

    const int tid  = threadIdx.x;
    const int w    = tid >> 5;
    const int wg   = w >> 2;          // 0/1
    const int w4   = w & 3;
    const int wtid = tid & 127;
    const int lane = tid & 31;
    const int g    = lane >> 2;
    const int l4   = lane & 3;
    const int q0   = blockIdx.x * 64;
    const int h    = blockIdx.y, b = blockIdx.z;

    const int cnt = g_cnt[b];
    if (q0 >= cnt) return;
    const int* idxp = g_idx + b * NS;
    const int NT = (cnt + 63) >> 6;

    const size_t base = ((size_t)b * NH + h) * NS * ND;
    const float* Qp = g_Q + base;
    const __half* Kp = g_Kf + base;
    const __half* Vp = g_Vf + base;   // [d][i]

    const int r0 = w4 * 16 + g;
    const int r1 = r0 + 8;
    const int cq0 = q0 + r0, cq1 = q0 + r1;
    const int so0 = idxp[cq0], so1 = idxp[cq1];
    float rs0, rs1;
    {
        float t0 = 1.0f + 0.5f * explore[b * NS + so0] - 0.5f * exploit[b * NS + so0];
        t0 = fminf(fmaxf(t0, 0.5f), 2.0f);
        rs0 = 0.125f / t0;
        float t1 = 1.0f + 0.5f * explore[b * NS + so1] - 0.5f * exploit[b * NS + so1];
        t1 = fminf(fmaxf(t1, 0.5f), 2.0f);
        rs1 = 0.125f / t1;
    }

    uint32_t qf[4][4];
    #pragma unroll
    for (int kc = 0; kc < 4; kc++) {
        int d0 = kc * 16 + l4 * 2;
        const float2 a00 = *(const float2*)(Qp + (size_t)cq0 * ND + d0);
        const float2 a10 = *(const float2*)(Qp + (size_t)cq1 * ND + d0);
        const float2 a01 = *(const float2*)(Qp + (size_t)cq0 * ND + d0 + 8);
        const float2 a11 = *(const float2*)(Qp + (size_t)cq1 * ND + d0 + 8);
        qf[kc][0] = pack_h2(a00.x * rs0, a00.y * rs0);
        qf[kc][1] = pack_h2(a10.x * rs1, a10.y * rs1);
        qf[kc][2] = pack_h2(a01.x * rs0, a01.y * rs0);
        qf[kc][3] = pack_h2(a11.x * rs1, a11.y * rs1);
    }

    float oacc[8][4];
    #pragma unroll
    for (int j = 0; j < 8; j++)
        #pragma unroll
        for (int c = 0; c < 4; c++) oacc[j][c] = 0.f;
    float lsum0 = 0.f, lsum1 = 0.f;

    __half* Ksw = Ks[wg];
    __half* Vsw = Vs[wg];

    for (int kt = wg; kt < NT; kt += 2) {
        const int kk0 = kt * 64;

        #pragma unroll
        for (int it = 0; it < 4; it++) {
            int idx = wtid + it * 128;
            int r = idx >> 3, c8 = (idx & 7) * 8;
            *(uint4*)(Ksw + r * KPAD + c8) = *(const uint4*)(Kp + (size_t)(kk0 + r) * ND + c8);
            *(uint4*)(Vsw + r * KPAD + c8) = *(const uint4*)(Vp + (size_t)r * NS + kk0 + c8);
        }
        if (wtid < 64) pens[wg][wtid] = (kk0 + wtid < cnt) ? -11.0f : -1e30f;
        asm volatile("bar.sync %0, %1;" :: "r"(wg + 1), "r"(128) : "memory");

        float sacc[8][4];
        #pragma unroll
        for (int j = 0; j < 8; j++)
            #pragma unroll
            for (int c = 0; c < 4; c++) sacc[j][c] = 0.f;

        #pragma unroll
        for (int kc = 0; kc < 4; kc++) {
            #pragma unroll
            for (int j = 0; j < 8; j++) {
                int boff = (j * 8 + g) * KPAD + kc * 16 + l4 * 2;
                uint32_t b0 = *(const uint32_t*)(Ksw + boff);
                uint32_t b1 = *(const uint32_t*)(Ksw + boff + 8);
                mma16816h(sacc[j], qf[kc], b0, b1);
            }
        }

        uint32_t ps[8][2];
        #pragma unroll
        for (int j = 0; j < 8; j++) {
            float2 pen2 = *(const float2*)(&pens[wg][j * 8 + l4 * 2]);
            float p0 = __expf(sacc[j][0] + pen2.x);
            float p1 = __expf(sacc[j][1] + pen2.y);
            float p2 = __expf(sacc[j][2] + pen2.x);
            float p3 = __expf(sacc[j][3] + pen2.y);
            lsum0 += p0 + p1;
            lsum1 += p2 + p3;
            ps[j][0] = pack_h2(p0, p1);
            ps[j][1] = pack_h2(p2, p3);
        }

        #pragma unroll
        for (int kc = 0; kc < 4; kc++) {
            uint32_t Af[4] = { ps[2*kc][0], ps[2*kc][1], ps[2*kc+1][0], ps[2*kc+1][1] };
            #pragma unroll
            for (int j = 0; j < 8; j++) {
                int boff = (j * 8 + g) * KPAD + kc * 16 + l4 * 2;
                uint32_t b0 = *(const uint32_t*)(Vsw + boff);
                uint32_t b1 = *(const uint32_t*)(Vsw + boff + 8);
                mma16816h(oacc[j], Af, b0, b1);
            }
        }
        asm volatile("bar.sync %0, %1;" :: "r"(wg + 1), "r"(128) : "memory");
    }

    lsum0 += __shfl_xor_sync(0xffffffffu, lsum0, 1);
    lsum0 += __shfl_xor_sync(0xffffffffu, lsum0, 2);
    lsum1 += __shfl_xor_sync(0xffffffffu, lsum1, 1);
    lsum1 += __shfl_xor_sync(0xffffffffu, lsum1, 2);

    // ---- combine wg partials through smem (overlay on Ks) ----
    __syncthreads();
    float* Ob = (float*)&Ks[0][0];          // 64 x 66 floats
    float* Lb = Ob + 64 * 66;               // 64 floats
    if (wg == 1) {
        #pragma unroll
        for (int j = 0; j < 8; j++) {
            int col = j * 8 + 2 * l4;
            Ob[r0 * 66 + col]     = oacc[j][0];
            Ob[r0 * 66 + col + 1] = oacc[j][1];
            Ob[r1 * 66 + col]     = oacc[j][2];
            Ob[r1 * 66 + col + 1] = oacc[j][3];
        }
        if (l4 == 0) { Lb[r0] = lsum0; Lb[r1] = lsum1; }
    }
    __syncthreads();
    if (wg == 0) {
        lsum0 += Lb[r0];
        lsum1 += Lb[r1];
        float inv0 = (lsum0 > 0.f) ? 1.f / lsum0 : 0.f;
        float inv1 = (lsum1 > 0.f) ? 1.f / lsum1 : 0.f;
        if (cq0 < cnt) {
            size_t o0 = base + (size_t)cq0 * ND;
            #pragma unroll
            for (int j = 0; j < 8; j++) {
                int col = j * 8 + 2 * l4;
                float v0 = (oacc[j][0] + Ob[r0 * 66 + col])     * inv0;
                float v1 = (oacc[j][1] + Ob[r0 * 66 + col + 1]) * inv0;
                float h0,l0,h1,l1;
                split_hi_lo(v0, h0, l0); split_hi_lo(v1, h1, l1);
                *(uint32_t*)(g_AOh + o0 + col) = pack_bf16x2(h0, h1);
                *(uint32_t*)(g_AOl + o0 + col) = pack_bf16x2(l0, l1);
            }
        }
        if (cq1 < cnt) {
            size_t o1 = base + (size_t)cq1 * ND;
            #pragma unroll
            for (int j = 0; j < 8; j++) {
                int col = j * 8 + 2 * l4;
                float v0 = (oacc[j][2] + Ob[r1 * 66 + col])     * inv1;
                float v1 = (oacc[j][3] + Ob[r1 * 66 + col + 1]) * inv1;
                float h0,l0,h1,l1;
                split_hi_lo(v0, h0, l0); split_hi_lo(v1, h1, l1);
                *(uint32_t*)(g_AOh + o1 + col) = pack_bf16x2(h0, h1);
                *(uint32_t*)(g_AOl + o1 + col) = pack_bf16x2(l0, l1);
            }
        }
    }
}

// ---------------------------------------------------------------------------
// Kernel 3: output projection on COMPACTED rows, scatter to original rows.
// ---------------------------------------------------------------------------
__global__ __launch_bounds__(128, 4) void out_proj_mma(
    const float* __restrict__ bo,
    float* __restrict__ out)
{
    __shared__ __align__(16) __nv_bfloat16 Xh[64*KPAD], Xl[64*KPAD];
    __shared__ __align__(16) __nv_bfloat16 Wth[64*KPAD], Wtl[64*KPAD];

    const int tid  = threadIdx.x;
    const int w4   = tid >> 5;
    const int lane = tid & 31;
    const int g    = lane >> 2;
    const int l4   = lane & 3;
    const int m0   = blockIdx.x * 64;           // compacted global row
    const int n0   = blockIdx.y * 64;

    const int bb   = m0 >> 11;
    const int loc0 = m0 & (NS - 1);
    const int cnt  = g_cnt[bb];
    if (loc0 >= cnt) return;
    const int* idxp = g_idx + bb * NS;

    float acc[8][4];
    #pragma unroll
    for (int j = 0; j < 8; j++)
        #pragma unroll
        for (int c = 0; c < 4; c++) acc[j][c] = 0.f;

    for (int k0 = 0; k0 < NE; k0 += 64) {
        const int hh = k0 >> 6;
        #pragma unroll
        for (int it = 0; it < 4; it++) {
            int idx = tid + it * 128;
            int r = idx >> 3, c8 = (idx & 7) * 8;
            size_t o = (((size_t)bb * NH + hh) * NS + loc0 + r) * ND + c8;
            *(uint4*)(Xh + r * KPAD + c8) = *(const uint4*)(g_AOh + o);
            *(uint4*)(Xl + r * KPAD + c8) = *(const uint4*)(g_AOl + o);
        }
        #pragma unroll
        for (int it = 0; it < 4; it++) {
            int idx = tid + it * 128;
            int r = idx >> 3, c8 = (idx & 7) * 8;
            size_t o = (size_t)3 * NE * NE + (size_t)(n0 + r) * NE + k0 + c8;
            *(uint4*)(Wth + r * KPAD + c8) = *(const uint4*)(g_Wth + o);
            *(uint4*)(Wtl + r * KPAD + c8) = *(const uint4*)(g_Wtl + o);
        }
        __syncthreads();

        #pragma unroll
        for (int kc = 0; kc < 4; kc++) {
            int aoff = (w4 * 16 + g) * KPAD + kc * 16 + l4 * 2;
            uint32_t ah[4], al[4];
            ah[0] = *(const uint32_t*)(Xh + aoff);
            ah[1] = *(const uint32_t*)(Xh + aoff + 8 * KPAD);
            ah[2] = *(const uint32_t*)(Xh + aoff + 8);
            ah[3] = *(const uint32_t*)(Xh + aoff + 8 * KPAD + 8);
            al[0] = *(const uint32_t*)(Xl + aoff);
            al[1] = *(const uint32_t*)(Xl + aoff + 8 * KPAD);
            al[2] = *(const uint32_t*)(Xl + aoff + 8);
            al[3] = *(const uint32_t*)(Xl + aoff + 8 * KPAD + 8);
            #pragma unroll
            for (int j = 0; j < 8; j++) {
                int boff = (j * 8 + g) * KPAD + kc * 16 + l4 * 2;
                uint32_t bh0 = *(const uint32_t*)(Wth + boff);
                uint32_t bh1 = *(const uint32_t*)(Wth + boff + 8);
                uint32_t bl0 = *(const uint32_t*)(Wtl + boff);
                uint32_t bl1 = *(const uint32_t*)(Wtl + boff + 8);
                mma16816(acc[j], ah, bh0, bh1);
                mma16816(acc[j], al, bh0, bh1);
                mma16816(acc[j], ah, bl0, bl1);
            }
        }
        __syncthreads();
    }

    const int lr0 = loc0 + w4 * 16 + g;
    const int lr1 = lr0 + 8;
    if (lr0 < cnt) {
        int row = bb * NS + idxp[lr0];
        #pragma unroll
        for (int j = 0; j < 8; j++) {
            int d = j * 8 + 2 * l4;
            float2 v = { acc[j][0] + bo[n0 + d], acc[j][1] + bo[n0 + d + 1] };
            *(float2*)(out + (size_t)row * NE + n0 + d) = v;
        }
    }
    if (lr1 < cnt) {
        int row = bb * NS + idxp[lr1];
        #pragma unroll
        for (int j = 0; j < 8; j++) {
            int d = j * 8 + 2 * l4;
            float2 v = { acc[j][2] + bo[n0 + d], acc[j][3] + bo[n0 + d + 1] };
            *(float2*)(out + (size_t)row * NE + n0 + d) = v;
        }
    }
}

// ---------------------------------------------------------------------------
extern "C" void kernel_launch(void* const* d_in, const int* in_sizes, int n_in,
                              void* d_out, int out_size)
{
    const float* his     = (const float*)d_in[0];
    const int*   mask    = (const int*)d_in[1];
    const float* explore = (const float*)d_in[2];
    const float* exploit = (const float*)d_in[3];
    const float* Wq = (const float*)d_in[4];
    const float* bq = (const float*)d_in[5];
    const float* Wk = (const float*)d_in[6];
    const float* bk = (const float*)d_in[7];
    const float* Wv = (const float*)d_in[8];
    const float* bv = (const float*)d_in[9];
    const float* Wo = (const float*)d_in[10];
    const float* bo = (const float*)d_in[11];
    float* out = (float*)d_out;

    const int qkv_smem = QKV_SMEM_BF16 * 2;     // 73728 B
    static cudaStream_t s2 = nullptr, s3 = nullptr;
    static cudaEvent_t ev_root = nullptr, ev_w = nullptr, ev_z = nullptr;
    if (s2 == nullptr) {
        cudaFuncSetAttribute(qkv_mma, cudaFuncAttributeMaxDynamicSharedMemorySize, qkv_smem);
        cudaStreamCreateWithFlags(&s2, cudaStreamNonBlocking);
        cudaStreamCreateWithFlags(&s3, cudaStreamNonBlocking);
        cudaEventCreateWithFlags(&ev_root, cudaEventDisableTiming);
        cudaEventCreateWithFlags(&ev_w, cudaEventDisableTiming);
        cudaEventCreateWithFlags(&ev_z, cudaEventDisableTiming);
    }

    // fork: prep_w on s2, zero_masked on s3, build_idx on main
    cudaEventRecord(ev_root, 0);
    cudaStreamWaitEvent(s2, ev_root, 0);
    cudaStreamWaitEvent(s3, ev_root, 0);
    prep_w<<<dim3(4, 4, 4), 256, 0, s2>>>(Wq, Wk, Wv, Wo);
    zero_masked<<<NB * NS / 4, 256, 0, s3>>>(mask, out);
    build_idx<<<NB, 1024>>>(mask);

    // join prep_w before qkv (needs g_Wth/g_Wtl)
    cudaEventRecord(ev_w, s2);
    cudaStreamWaitEvent(0, ev_w, 0);
    qkv_mma<<<dim3(NB * NS / 64, NH), 128, qkv_smem>>>(his, bq, bk, bv);
    attn_mma<<<dim3(NS / 64, NH, NB), 256>>>(explore, exploit);

    // join zero_masked before out_proj (both write `out`, disjoint rows)
    cudaEventRecord(ev_z, s3);
    cudaStreamWaitEvent(0, ev_z, 0);
    out_proj_mma<<<dim3(NB * NS / 64, 4), 128>>>(bo, out);
}

// round 12
// speedup vs baseline: 12.0596x; 1.0582x over previous
#include <cuda_runtime.h>
#include <cuda_bf16.h>
#include <cuda_fp16.h>
#include <cstdint>
#include <math.h>

#define NB 4
#define NS 2048
#define NE 256
#define NH 4
#define ND 64

// Scratch (allocation-free). Q/K/V/AO all in COMPACTED per-batch coordinates.
__device__ float g_Q[NB*NH*NS*ND];                                  // [b,h,i,d] fp32
__device__ __align__(16) __half g_Kf[NB*NH*NS*ND];                  // [b,h,i,d] fp16
__device__ __align__(16) __half g_Vf[NB*NH*ND*NS];                  // [b,h,d,i] fp16
__device__ __align__(16) __nv_bfloat16 g_AOh[NB*NH*NS*ND];          // [b,h,i,d]
__device__ __align__(16) __nv_bfloat16 g_AOl[NB*NH*NS*ND];
__device__ __align__(16) __nv_bfloat16 g_Wth[4*NE*NE];              // [mat][n][k]
__device__ __align__(16) __nv_bfloat16 g_Wtl[4*NE*NE];
__device__ int g_idx[NB*NS];                                        // compacted -> orig s
__device__ int g_cnt[NB];

__device__ __forceinline__ uint32_t pack_bf16x2(float a, float b) {
    __nv_bfloat162 t = __floats2bfloat162_rn(a, b);   // a -> low half
    return *(uint32_t*)&t;
}
__device__ __forceinline__ uint32_t pack_h2(float a, float b) {
    __half2 t = __floats2half2_rn(a, b);              // a -> low half
    return *(uint32_t*)&t;
}
__device__ __forceinline__ void split_hi_lo(float x, float& hi, float& lo) {
    __nv_bfloat16 h = __float2bfloat16_rn(x);
    hi = __bfloat162float(h);
    lo = x - hi;
}

// mma.sync m16n8k16 row.col (sm_80+ PTX, no arch suffix)
__device__ __forceinline__ void mma16816(float c[4], const uint32_t a[4],
                                         uint32_t b0, uint32_t b1) {
    asm volatile(
        "mma.sync.aligned.m16n8k16.row.col.f32.bf16.bf16.f32 "
        "{%0,%1,%2,%3}, {%4,%5,%6,%7}, {%8,%9}, {%0,%1,%2,%3};"
        : "+f"(c[0]), "+f"(c[1]), "+f"(c[2]), "+f"(c[3])
        : "r"(a[0]), "r"(a[1]), "r"(a[2]), "r"(a[3]), "r"(b0), "r"(b1));
}
__device__ __forceinline__ void mma16816h(float c[4], const uint32_t a[4],
                                          uint32_t b0, uint32_t b1) {
    asm volatile(
        "mma.sync.aligned.m16n8k16.row.col.f32.f16.f16.f32 "
        "{%0,%1,%2,%3}, {%4,%5,%6,%7}, {%8,%9}, {%0,%1,%2,%3};"
        : "+f"(c[0]), "+f"(c[1]), "+f"(c[2]), "+f"(c[3])
        : "r"(a[0]), "r"(a[1]), "r"(a[2]), "r"(a[3]), "r"(b0), "r"(b1));
}

// ldmatrix x4: four 8x8 b16 fragments in one instruction (sm_75+, no suffix)
__device__ __forceinline__ void ldsm4(uint32_t r[4], const void* p) {
    uint32_t a = (uint32_t)__cvta_generic_to_shared(p);
    asm volatile("ldmatrix.sync.aligned.m8n8.x4.shared.b16 {%0,%1,%2,%3}, [%4];"
                 : "=r"(r[0]), "=r"(r[1]), "=r"(r[2]), "=r"(r[3]) : "r"(a));
}

#define KPAD 72   // 16-bit row stride; 36-word stride -> conflict-free ldmatrix rows

__device__ __forceinline__ void store_split4(__nv_bfloat16* bh, __nv_bfloat16* bl,
                                             int off, float4 v) {
    float h0,l0,h1,l1,h2,l2,h3,l3;
    split_hi_lo(v.x,h0,l0); split_hi_lo(v.y,h1,l1);
    split_hi_lo(v.z,h2,l2); split_hi_lo(v.w,h3,l3);
    *(uint32_t*)(bh + off)     = pack_bf16x2(h0, h1);
    *(uint32_t*)(bh + off + 2) = pack_bf16x2(h2, h3);
    *(uint32_t*)(bl + off)     = pack_bf16x2(l0, l1);
    *(uint32_t*)(bl + off + 2) = pack_bf16x2(l2, l3);
}

// ---------------------------------------------------------------------------
// Kernel A: per-batch compaction index (Hillis-Steele scan over 2048 mask bits)
// ---------------------------------------------------------------------------
__global__ __launch_bounds__(1024) void build_idx(const int* __restrict__ mask)
{
    __shared__ int scan[1024];
    const int b = blockIdx.x;
    const int tid = threadIdx.x;
    const int s0 = 2 * tid, s1 = 2 * tid + 1;
    const int m0 = (mask[b * NS + s0] == 0) ? 1 : 0;
    const int m1 = (mask[b * NS + s1] == 0) ? 1 : 0;
    scan[tid] = m0 + m1;
    __syncthreads();
    #pragma unroll
    for (int off = 1; off < 1024; off <<= 1) {
        int v = (tid >= off) ? scan[tid - off] : 0;
        __syncthreads();
        scan[tid] += v;
        __syncthreads();
    }
    const int excl = scan[tid] - m0 - m1;
    if (m0) g_idx[b * NS + excl] = s0;
    if (m1) g_idx[b * NS + excl + m0] = s1;
    const int total = scan[1023];
    for (int i = tid; i < NS; i += 1024)
        if (i >= total) g_idx[b * NS + i] = 0;     // pad with a valid index
    if (tid == 0) g_cnt[b] = total;
}

// ---------------------------------------------------------------------------
// Kernel B: zero all masked output rows (d_out is poisoned).
// ---------------------------------------------------------------------------
__global__ __launch_bounds__(256) void zero_masked(
    const int* __restrict__ mask, float* __restrict__ out)
{
    const int row = blockIdx.x * 4 + (threadIdx.x >> 6);
    const int c4 = threadIdx.x & 63;
    if (mask[row] != 0) {
        float4 z = {0.f, 0.f, 0.f, 0.f};
        *(float4*)(out + (size_t)row * NE + c4 * 4) = z;
    }
}

// ---------------------------------------------------------------------------
// Kernel 0: pre-split weights -> transposed hi/lo bf16 [mat][n][k].
// ---------------------------------------------------------------------------
__global__ __launch_bounds__(256) void prep_w(
    const float* __restrict__ Wq, const float* __restrict__ Wk,
    const float* __restrict__ Wv, const float* __restrict__ Wo)
{
    __shared__ float t[64][65];
    const float* Ws[4] = { Wq, Wk, Wv, Wo };
    const int mt = blockIdx.z;
    const int k0 = blockIdx.x * 64, n0 = blockIdx.y * 64;
    const int tid = threadIdx.x;
    const float* W = Ws[mt];

    #pragma unroll
    for (int it = 0; it < 16; it++) {
        int idx = tid + it * 256;
        int kk = idx >> 6, nn = idx & 63;
        t[kk][nn] = W[(k0 + kk) * NE + n0 + nn];
    }
    __syncthreads();

    #pragma unroll
    for (int it = 0; it < 2; it++) {
        int idx = tid + it * 256;
        int n = idx >> 3, c8 = (idx & 7) * 8;
        uint32_t hw[4], lw[4];
        #pragma unroll
        for (int p = 0; p < 4; p++) {
            float hi0, lo0, hi1, lo1;
            split_hi_lo(t[c8 + 2*p][n],     hi0, lo0);
            split_hi_lo(t[c8 + 2*p + 1][n], hi1, lo1);
            hw[p] = pack_bf16x2(hi0, hi1);
            lw[p] = pack_bf16x2(lo0, lo1);
        }
        size_t o = (size_t)mt * NE * NE + (size_t)(n0 + n) * NE + k0 + c8;
        *(uint4*)(g_Wth + o) = *(uint4*)hw;
        *(uint4*)(g_Wtl + o) = *(uint4*)lw;
    }
}

// ---------------------------------------------------------------------------
// Kernel 1: fused QKV projection on COMPACTED rows (gathered X). ldmatrix frags.
// ---------------------------------------------------------------------------
#define QX_H    0
#define QX_L    (64*KPAD)
#define QW_TH   (2*64*KPAD)
#define QW_TL   (5*64*KPAD)
#define QKV_SMEM_BF16 (8*64*KPAD)    // 36864 elems = 73728 B

__global__ __launch_bounds__(128, 2) void qkv_mma(
    const float* __restrict__ X,
    const float* __restrict__ bq, const float* __restrict__ bk,
    const float* __restrict__ bv)
{
    extern __shared__ __nv_bfloat16 smb[];
    __nv_bfloat16* Xh = smb + QX_H;
    __nv_bfloat16* Xl = smb + QX_L;

    const int tid  = threadIdx.x;
    const int w4   = tid >> 5;
    const int lane = tid & 31;
    const int l4   = lane & 3;
    const int matl = lane >> 3;       // ldmatrix sub-matrix index
    const int rowl = lane & 7;        // ldmatrix row within sub-matrix
    const int m0   = blockIdx.x * 64;
    const int h    = blockIdx.y;
    const int n0   = h * 64;

    const int bb   = m0 >> 11;
    const int loc0 = m0 & (NS - 1);
    const int cnt  = g_cnt[bb];
    if (loc0 >= cnt) return;
    const int* idxp = g_idx + bb * NS;

    float acc[3][8][4];
    #pragma unroll
    for (int mt = 0; mt < 3; mt++)
        #pragma unroll
        for (int j = 0; j < 8; j++)
            #pragma unroll
            for (int c = 0; c < 4; c++) acc[mt][j][c] = 0.f;

    // ldmatrix address offsets (element units)
    const int a_off = (w4 * 16 + (matl & 1) * 8 + rowl) * KPAD + (matl >> 1) * 8;
    const int b_row = (matl >> 1) * 8 + rowl;     // within a 2-j pair
    const int b_kh  = (matl & 1) * 8;

    for (int k0 = 0; k0 < NE; k0 += 64) {
        #pragma unroll
        for (int it = 0; it < 8; it++) {
            int idx = tid + it * 128;
            int r = idx >> 4, c = (idx & 15) * 4;
            int src = idxp[loc0 + r];
            float4 v = *(const float4*)(X + ((size_t)bb * NS + src) * NE + k0 + c);
            store_split4(Xh, Xl, r * KPAD + c, v);
        }
        #pragma unroll
        for (int mt = 0; mt < 3; mt++) {
            __nv_bfloat16* Wth = smb + QW_TH + mt * 64 * KPAD;
            __nv_bfloat16* Wtl = smb + QW_TL + mt * 64 * KPAD;
            const size_t wb = (size_t)mt * NE * NE;
            #pragma unroll
            for (int it = 0; it < 4; it++) {
                int idx = tid + it * 128;
                int r = idx >> 3, c8 = (idx & 7) * 8;
                size_t o = wb + (size_t)(n0 + r) * NE + k0 + c8;
                *(uint4*)(Wth + r * KPAD + c8) = *(const uint4*)(g_Wth + o);
                *(uint4*)(Wtl + r * KPAD + c8) = *(const uint4*)(g_Wtl + o);
            }
        }
        __syncthreads();

        #pragma unroll
        for (int kc = 0; kc < 4; kc++) {
            uint32_t ah[4], al[4];
            ldsm4(ah, Xh + a_off + kc * 16);
            ldsm4(al, Xl + a_off + kc * 16);

            #pragma unroll
            for (int mt = 0; mt < 3; mt++) {
                const __nv_bfloat16* Wth = smb + QW_TH + mt * 64 * KPAD;
                const __nv_bfloat16* Wtl = smb + QW_TL + mt * 64 * KPAD;
                #pragma unroll
                for (int jp = 0; jp < 4; jp++) {
                    int boff = (jp * 16 + b_row) * KPAD + kc * 16 + b_kh;
                    uint32_t bh[4], bl[4];
                    ldsm4(bh, Wth + boff);
                    ldsm4(bl, Wtl + boff);
                    mma16816(acc[mt][2*jp],   ah, bh[0], bh[1]);
                    mma16816(acc[mt][2*jp],   al, bh[0], bh[1]);
                    mma16816(acc[mt][2*jp],   ah, bl[0], bl[1]);
                    mma16816(acc[mt][2*jp+1], ah, bh[2], bh[3]);
                    mma16816(acc[mt][2*jp+1], al, bh[2], bh[3]);
                    mma16816(acc[mt][2*jp+1], ah, bl[2], bl[3]);
                }
            }
        }
        __syncthreads();
    }

    const int g = lane >> 2;
    const int row0 = m0 + w4 * 16 + g;
    const int row1 = row0 + 8;
    const int s0 = row0 & (NS - 1);
    const int s1 = row1 & (NS - 1);

    // ---- Q: fp32 ----
    {
        float* O0 = g_Q + (((size_t)bb * NH + h) * NS + s0) * ND;
        float* O1 = g_Q + (((size_t)bb * NH + h) * NS + s1) * ND;
        #pragma unroll
        for (int j = 0; j < 8; j++) {
            int d = j * 8 + 2 * l4;
            float bx = bq[n0 + d], by = bq[n0 + d + 1];
            float2 v0 = { acc[0][j][0] + bx, acc[0][j][1] + by };
            float2 v1 = { acc[0][j][2] + bx, acc[0][j][3] + by };
            *(float2*)(O0 + d) = v0;
            *(float2*)(O1 + d) = v1;
        }
    }
    // ---- K: fp16 ----
    {
        size_t o0 = (((size_t)bb * NH + h) * NS + s0) * ND;
        size_t o1 = (((size_t)bb * NH + h) * NS + s1) * ND;
        #pragma unroll
        for (int j = 0; j < 8; j++) {
            int d = j * 8 + 2 * l4;
            float bx = bk[n0 + d], by = bk[n0 + d + 1];
            *(uint32_t*)(g_Kf + o0 + d) = pack_h2(acc[1][j][0] + bx, acc[1][j][1] + by);
            *(uint32_t*)(g_Kf + o1 + d) = pack_h2(acc[1][j][2] + bx, acc[1][j][3] + by);
        }
    }
    // ---- V: stage [d][s] fp32 in smem (64x64), write fp16 [b,h,d,i] ----
    #define VPAD 68
    __syncthreads();
    float* Vb = (float*)smb;
    #pragma unroll
    for (int j = 0; j < 8; j++) {
        int d = j * 8 + 2 * l4;
        float bx = bv[n0 + d], by = bv[n0 + d + 1];
        int sr0 = w4 * 16 + g, sr1 = sr0 + 8;
        Vb[(d    ) * VPAD + sr0] = acc[2][j][0] + bx;
        Vb[(d + 1) * VPAD + sr0] = acc[2][j][1] + by;
        Vb[(d    ) * VPAD + sr1] = acc[2][j][2] + bx;
        Vb[(d + 1) * VPAD + sr1] = acc[2][j][3] + by;
    }
    __syncthreads();
    #pragma unroll
    for (int it = 0; it < 8; it++) {
        int idx = tid + it * 128;
        int d = idx >> 4, c4 = (idx & 15) * 4;
        int s = loc0 + c4;
        size_t o = (((size_t)bb * NH + h) * ND + d) * NS + s;
        uint32_t hw[2] = { pack_h2(Vb[d * VPAD + c4],     Vb[d * VPAD + c4 + 1]),
                           pack_h2(Vb[d * VPAD + c4 + 2], Vb[d * VPAD + c4 + 3]) };
        *(uint2*)(g_Vf + o) = *(uint2*)hw;
    }
}

// ---------------------------------------------------------------------------
// Kernel 2: flash attention, q-tile 64, 2 warpgroups split over K-tiles.
// ldmatrix for K/V fragments.
// ---------------------------------------------------------------------------
__global__ __launch_bounds__(256, 2) void attn_mma(
    const float* __restrict__ explore,
    const float* __restrict__ exploit)
{
    __shared__ __align__(16) __half Ks[2][64*KPAD];
    __shared__ __align__(16) __half Vs[2][64*KPAD];
    __shared__ float pens[2][64];

    const int tid  = threadIdx.x;
    const int w    = tid >> 5;
    const int wg   = w >> 2;          // 0/1
    const int w4   = w & 3;
    const int wtid = tid & 127;
    const int lane = tid & 31;
    const int g    = lane >> 2;
    const int l4   = lane & 3;
    const int matl = lane >> 3;
    const int rowl = lane & 7;
    const int q0   = blockIdx.x * 64;
    const int h    = blockIdx.y, b = blockIdx.z;

    const int cnt = g_cnt[b];
    if (q0 >= cnt) return;
    const int* idxp = g_idx + b * NS;
    const int NT = (cnt + 63) >> 6;

    const size_t base = ((size_t)b * NH + h) * NS * ND;
    const float* Qp = g_Q + base;
    const __half* Kp = g_Kf + base;
    const __half* Vp = g_Vf + base;   // [d][i]

    const int r0 = w4 * 16 + g;
    const int r1 = r0 + 8;
    const int cq0 = q0 + r0, cq1 = q0 + r1;
    const int so0 = idxp[cq0], so1 = idxp[cq1];
    float rs0, rs1;
    {
        float t0 = 1.0f + 0.5f * explore[b * NS + so0] - 0.5f * exploit[b * NS + so0];
        t0 = fminf(fmaxf(t0, 0.5f), 2.0f);
        rs0 = 0.125f / t0;
        float t1 = 1.0f + 0.5f * explore[b * NS + so1] - 0.5f * exploit[b * NS + so1];
        t1 = fminf(fmaxf(t1, 0.5f), 2.0f);
        rs1 = 0.125f / t1;
    }

    uint32_t qf[4][4];
    #pragma unroll
    for (int kc = 0; kc < 4; kc++) {
        int d0 = kc * 16 + l4 * 2;
        const float2 a00 = *(const float2*)(Qp + (size_t)cq0 * ND + d0);
        const float2 a10 = *(const float2*)(Qp + (size_t)cq1 * ND + d0);
        const float2 a01 = *(const float2*)(Qp + (size_t)cq0 * ND + d0 + 8);
        const float2 a11 = *(const float2*)(Qp + (size_t)cq1 * ND + d0 + 8);
        qf[kc][0] = pack_h2(a00.x * rs0, a00.y * rs0);
        qf[kc][1] = pack_h2(a10.x * rs1, a10.y * rs1);
        qf[kc][2] = pack_h2(a01.x * rs0, a01.y * rs0);
        qf[kc][3] = pack_h2(a11.x * rs1, a11.y * rs1);
    }

    float oacc[8][4];
    #pragma unroll
    for (int j = 0; j < 8; j++)
        #pragma unroll
        for (int c = 0; c < 4; c++) oacc[j][c] = 0.f;
    float lsum0 = 0.f, lsum1 = 0.f;

    __half* Ksw = Ks[wg];
    __half* Vsw = Vs[wg];
    const int b_row = (matl >> 1) * 8 + rowl;
    const int b_kh  = (matl & 1) * 8;

    for (int kt = wg; kt < NT; kt += 2) {
        const int kk0 = kt * 64;

        #pragma unroll
        for (int it = 0; it < 4; it++) {
            int idx = wtid + it * 128;
            int r = idx >> 3, c8 = (idx & 7) * 8;
            *(uint4*)(Ksw + r * KPAD + c8) = *(const uint4*)(Kp + (size_t)(kk0 + r) * ND + c8);
            *(uint4*)(Vsw + r * KPAD + c8) = *(const uint4*)(Vp + (size_t)r * NS + kk0 + c8);
        }
        if (wtid < 64) pens[wg][wtid] = (kk0 + wtid < cnt) ? -11.0f : -1e30f;
        asm volatile("bar.sync %0, %1;" :: "r"(wg + 1), "r"(128) : "memory");

        float sacc[8][4];
        #pragma unroll
        for (int j = 0; j < 8; j++)
            #pragma unroll
            for (int c = 0; c < 4; c++) sacc[j][c] = 0.f;

        #pragma unroll
        for (int kc = 0; kc < 4; kc++) {
            #pragma unroll
            for (int jp = 0; jp < 4; jp++) {
                uint32_t kb[4];
                ldsm4(kb, Ksw + (jp * 16 + b_row) * KPAD + kc * 16 + b_kh);
                mma16816h(sacc[2*jp],   qf[kc], kb[0], kb[1]);
                mma16816h(sacc[2*jp+1], qf[kc], kb[2], kb[3]);
            }
        }

        uint32_t ps[8][2];
        #pragma unroll
        for (int j = 0; j < 8; j++) {
            float2 pen2 = *(const float2*)(&pens[wg][j * 8 + l4 * 2]);
            float p0 = __expf(sacc[j][0] + pen2.x);
            float p1 = __expf(sacc[j][1] + pen2.y);
            float p2 = __expf(sacc[j][2] + pen2.x);
            float p3 = __expf(sacc[j][3] + pen2.y);
            lsum0 += p0 + p1;
            lsum1 += p2 + p3;
            ps[j][0] = pack_h2(p0, p1);
            ps[j][1] = pack_h2(p2, p3);
        }

        #pragma unroll
        for (int kc = 0; kc < 4; kc++) {
            uint32_t Af[4] = { ps[2*kc][0], ps[2*kc][1], ps[2*kc+1][0], ps[2*kc+1][1] };
            #pragma unroll
            for (int jp = 0; jp < 4; jp++) {
                uint32_t vb[4];
                ldsm4(vb, Vsw + (jp * 16 + b_row) * KPAD + kc * 16 + b_kh);
                mma16816h(oacc[2*jp],   Af, vb[0], vb[1]);
                mma16816h(oacc[2*jp+1], Af, vb[2], vb[3]);
            }
        }
        asm volatile("bar.sync %0, %1;" :: "r"(wg + 1), "r"(128) : "memory");
    }

    lsum0 += __shfl_xor_sync(0xffffffffu, lsum0, 1);
    lsum0 += __shfl_xor_sync(0xffffffffu, lsum0, 2);
    lsum1 += __shfl_xor_sync(0xffffffffu, lsum1, 1);
    lsum1 += __shfl_xor_sync(0xffffffffu, lsum1, 2);

    // ---- combine wg partials through smem (overlay on Ks) ----
    __syncthreads();
    float* Ob = (float*)&Ks[0][0];          // 64 x 66 floats
    float* Lb = Ob + 64 * 66;               // 64 floats
    if (wg == 1) {
        #pragma unroll
        for (int j = 0; j < 8; j++) {
            int col = j * 8 + 2 * l4;
            Ob[r0 * 66 + col]     = oacc[j][0];
            Ob[r0 * 66 + col + 1] = oacc[j][1];
            Ob[r1 * 66 + col]     = oacc[j][2];
            Ob[r1 * 66 + col + 1] = oacc[j][3];
        }
        if (l4 == 0) { Lb[r0] = lsum0; Lb[r1] = lsum1; }
    }
    __syncthreads();
    if (wg == 0) {
        lsum0 += Lb[r0];
        lsum1 += Lb[r1];
        float inv0 = (lsum0 > 0.f) ? 1.f / lsum0 : 0.f;
        float inv1 = (lsum1 > 0.f) ? 1.f / lsum1 : 0.f;
        if (cq0 < cnt) {
            size_t o0 = base + (size_t)cq0 * ND;
            #pragma unroll
            for (int j = 0; j < 8; j++) {
                int col = j * 8 + 2 * l4;
                float v0 = (oacc[j][0] + Ob[r0 * 66 + col])     * inv0;
                float v1 = (oacc[j][1] + Ob[r0 * 66 + col + 1]) * inv0;
                float h0,l0,h1,l1;
                split_hi_lo(v0, h0, l0); split_hi_lo(v1, h1, l1);
                *(uint32_t*)(g_AOh + o0 + col) = pack_bf16x2(h0, h1);
                *(uint32_t*)(g_AOl + o0 + col) = pack_bf16x2(l0, l1);
            }
        }
        if (cq1 < cnt) {
            size_t o1 = base + (size_t)cq1 * ND;
            #pragma unroll
            for (int j = 0; j < 8; j++) {
                int col = j * 8 + 2 * l4;
                float v0 = (oacc[j][2] + Ob[r1 * 66 + col])     * inv1;
                float v1 = (oacc[j][3] + Ob[r1 * 66 + col + 1]) * inv1;
                float h0,l0,h1,l1;
                split_hi_lo(v0, h0, l0); split_hi_lo(v1, h1, l1);
                *(uint32_t*)(g_AOh + o1 + col) = pack_bf16x2(h0, h1);
                *(uint32_t*)(g_AOl + o1 + col) = pack_bf16x2(l0, l1);
            }
        }
    }
}

// ---------------------------------------------------------------------------
// Kernel 3: output projection on COMPACTED rows, scatter to original rows.
// ldmatrix fragments.
// ---------------------------------------------------------------------------
__global__ __launch_bounds__(128, 4) void out_proj_mma(
    const float* __restrict__ bo,
    float* __restrict__ out)
{
    __shared__ __align__(16) __nv_bfloat16 Xh[64*KPAD], Xl[64*KPAD];
    __shared__ __align__(16) __nv_bfloat16 Wth[64*KPAD], Wtl[64*KPAD];

    const int tid  = threadIdx.x;
    const int w4   = tid >> 5;
    const int lane = tid & 31;
    const int l4   = lane & 3;
    const int matl = lane >> 3;
    const int rowl = lane & 7;
    const int m0   = blockIdx.x * 64;
    const int n0   = blockIdx.y * 64;

    const int bb   = m0 >> 11;
    const int loc0 = m0 & (NS - 1);
    const int cnt  = g_cnt[bb];
    if (loc0 >= cnt) return;
    const int* idxp = g_idx + bb * NS;

    float acc[8][4];
    #pragma unroll
    for (int j = 0; j < 8; j++)
        #pragma unroll
        for (int c = 0; c < 4; c++) acc[j][c] = 0.f;

    const int a_off = (w4 * 16 + (matl & 1) * 8 + rowl) * KPAD + (matl >> 1) * 8;
    const int b_row = (matl >> 1) * 8 + rowl;
    const int b_kh  = (matl & 1) * 8;

    for (int k0 = 0; k0 < NE; k0 += 64) {
        const int hh = k0 >> 6;
        #pragma unroll
        for (int it = 0; it < 4; it++) {
            int idx = tid + it * 128;
            int r = idx >> 3, c8 = (idx & 7) * 8;
            size_t o = (((size_t)bb * NH + hh) * NS + loc0 + r) * ND + c8;
            *(uint4*)(Xh + r * KPAD + c8) = *(const uint4*)(g_AOh + o);
            *(uint4*)(Xl + r * KPAD + c8) = *(const uint4*)(g_AOl + o);
        }
        #pragma unroll
        for (int it = 0; it < 4; it++) {
            int idx = tid + it * 128;
            int r = idx >> 3, c8 = (idx & 7) * 8;
            size_t o = (size_t)3 * NE * NE + (size_t)(n0 + r) * NE + k0 + c8;
            *(uint4*)(Wth + r * KPAD + c8) = *(const uint4*)(g_Wth + o);
            *(uint4*)(Wtl + r * KPAD + c8) = *(const uint4*)(g_Wtl + o);
        }
        __syncthreads();

        #pragma unroll
        for (int kc = 0; kc < 4; kc++) {
            uint32_t ah[4], al[4];
            ldsm4(ah, Xh + a_off + kc * 16);
            ldsm4(al, Xl + a_off + kc * 16);
            #pragma unroll
            for (int jp = 0; jp < 4; jp++) {
                int boff = (jp * 16 + b_row) * KPAD + kc * 16 + b_kh;
                uint32_t bh[4], bl[4];
                ldsm4(bh, Wth + boff);
                ldsm4(bl, Wtl + boff);
                mma16816(acc[2*jp],   ah, bh[0], bh[1]);
                mma16816(acc[2*jp],   al, bh[0], bh[1]);
                mma16816(acc[2*jp],   ah, bl[0], bl[1]);
                mma16816(acc[2*jp+1], ah, bh[2], bh[3]);
                mma16816(acc[2*jp+1], al, bh[2], bh[3]);
                mma16816(acc[2*jp+1], ah, bl[2], bl[3]);
            }
        }
        __syncthreads();
    }

    const int g = lane >> 2;
    const int lr0 = loc0 + w4 * 16 + g;
    const int lr1 = lr0 + 8;
    if (lr0 < cnt) {
        int row = bb * NS + idxp[lr0];
        #pragma unroll
        for (int j = 0; j < 8; j++) {
            int d = j * 8 + 2 * l4;
            float2 v = { acc[j][0] + bo[n0 + d], acc[j][1] + bo[n0 + d + 1] };
            *(float2*)(out + (size_t)row * NE + n0 + d) = v;
        }
    }
    if (lr1 < cnt) {
        int row = bb * NS + idxp[lr1];
        #pragma unroll
        for (int j = 0; j < 8; j++) {
            int d = j * 8 + 2 * l4;
            float2 v = { acc[j][2] + bo[n0 + d], acc[j][3] + bo[n0 + d + 1] };
            *(float2*)(out + (size_t)row * NE + n0 + d) = v;
        }
    }
}

// ---------------------------------------------------------------------------
extern "C" void kernel_launch(void* const* d_in, const int* in_sizes, int n_in,
                              void* d_out, int out_size)
{
    const float* his     = (const float*)d_in[0];
    const int*   mask    = (const int*)d_in[1];
    const float* explore = (const float*)d_in[2];
    const float* exploit = (const float*)d_in[3];
    const float* Wq = (const float*)d_in[4];
    const float* bq = (const float*)d_in[5];
    const float* Wk = (const float*)d_in[6];
    const float* bk = (const float*)d_in[7];
    const float* Wv = (const float*)d_in[8];
    const float* bv = (const float*)d_in[9];
    const float* Wo = (const float*)d_in[10];
    const float* bo = (const float*)d_in[11];
    float* out = (float*)d_out;

    const int qkv_smem = QKV_SMEM_BF16 * 2;     // 73728 B
    static cudaStream_t s2 = nullptr, s3 = nullptr;
    static cudaEvent_t ev_root = nullptr, ev_w = nullptr, ev_z = nullptr;
    if (s2 == nullptr) {
        cudaFuncSetAttribute(qkv_mma, cudaFuncAttributeMaxDynamicSharedMemorySize, qkv_smem);
        cudaStreamCreateWithFlags(&s2, cudaStreamNonBlocking);
        cudaStreamCreateWithFlags(&s3, cudaStreamNonBlocking);
        cudaEventCreateWithFlags(&ev_root, cudaEventDisableTiming);
        cudaEventCreateWithFlags(&ev_w, cudaEventDisableTiming);
        cudaEventCreateWithFlags(&ev_z, cudaEventDisableTiming);
    }

    // fork: prep_w on s2, zero_masked on s3, build_idx on main
    cudaEventRecord(ev_root, 0);
    cudaStreamWaitEvent(s2, ev_root, 0);
    cudaStreamWaitEvent(s3, ev_root, 0);
    prep_w<<<dim3(4, 4, 4), 256, 0, s2>>>(Wq, Wk, Wv, Wo);
    zero_masked<<<NB * NS / 4, 256, 0, s3>>>(mask, out);
    build_idx<<<NB, 1024>>>(mask);

    // join prep_w before qkv (needs g_Wth/g_Wtl)
    cudaEventRecord(ev_w, s2);
    cudaStreamWaitEvent(0, ev_w, 0);
    qkv_mma<<<dim3(NB * NS / 64, NH), 128, qkv_smem>>>(his, bq, bk, bv);
    attn_mma<<<dim3(NS / 64, NH, NB), 256>>>(explore, exploit);

    // join zero_masked before out_proj (both write `out`, disjoint rows)
    cudaEventRecord(ev_z, s3);
    cudaStreamWaitEvent(0, ev_z, 0);
    out_proj_mma<<<dim3(NB * NS / 64, 4), 128>>>(bo, out);
}